// round 10
// baseline (speedup 1.0000x reference)
#include <cuda_runtime.h>
#include <cuda_bf16.h>
#include <math.h>
#include <stdint.h>

#define T   2048
#define Dm  512
#define Np  32
#define Hd  2048
#define Kk  4
#define NHd 8
#define HDd 64
#define Sd  1024
#define Bd  2
#define D3  1536

#define AT_PAD 68
#define AT_REG (64 * AT_PAD)
#define SMEM_ATTN (3 * AT_REG * 4)

// HMMA tile constants: pitch 72 bf16 per row, 128 rows per tile
#define FP 72
#define FTILE (128 * FP)               // bf16 units per tile
#define SMEM_FFN (4 * FTILE * 2)       // bytes: 2 bufs x (A + B)

__device__ int   g_idx[T * Kk];
__device__ int   g_cnt[Np];
__device__ int   g_list[Np * T];
__device__ float g_pairs[T * Kk * Dm];
__device__ float g_nout[T * Dm];
__device__ float g_qkv[T * D3];
__device__ float g_attnout[T * Dm];
__device__ __nv_bfloat16 g_x3[T * 2 * Dm];                 // [t][hi(512)|lo(512)]
__device__ __nv_bfloat16 g_nout3[T * 2 * Dm];
__device__ __nv_bfloat16 g_attno3[T * 2 * Dm];
__device__ __nv_bfloat16 g_W13[(size_t)Np * Hd * 2 * Dm];  // [n][h][Wh|Wl]
__device__ __nv_bfloat16 g_W23[(size_t)Np * Dm * 2 * Hd];  // [n][d][Wh|Wl]
__device__ __nv_bfloat16 g_Wqkv3[(size_t)D3 * 2 * Dm];
__device__ __nv_bfloat16 g_Wo3[(size_t)Dm * 2 * Dm];
__device__ __nv_bfloat16 g_h3[(size_t)T * Kk * 2 * Hd];    // [pair][hh|hl]

__device__ __forceinline__ float gelu_f(float v) {
    float u = 0.7978845608028654f * (v + 0.044715f * v * v * v);
    return 0.5f * v * (1.0f + tanhf(u));
}

__device__ __forceinline__ uint32_t cvta_smem(const void* p) {
    uint32_t a;
    asm("{ .reg .u64 t; cvta.to.shared.u64 t, %1; cvt.u32.u64 %0, t; }" : "=r"(a) : "l"(p));
    return a;
}

__device__ __forceinline__ void mma_bf16(float c[4], uint32_t a0, uint32_t a1,
                                         uint32_t a2, uint32_t a3,
                                         uint32_t b0, uint32_t b1) {
    asm volatile(
        "mma.sync.aligned.m16n8k16.row.col.f32.bf16.bf16.f32 "
        "{%0,%1,%2,%3}, {%4,%5,%6,%7}, {%8,%9}, {%0,%1,%2,%3};"
        : "+f"(c[0]), "+f"(c[1]), "+f"(c[2]), "+f"(c[3])
        : "r"(a0), "r"(a1), "r"(a2), "r"(a3), "r"(b0), "r"(b1));
}

__device__ __forceinline__ void ldsm4(uint32_t r[4], uint32_t a) {
    asm volatile("ldmatrix.sync.aligned.m8n8.x4.shared.b16 {%0,%1,%2,%3}, [%4];"
        : "=r"(r[0]), "=r"(r[1]), "=r"(r[2]), "=r"(r[3]) : "r"(a));
}

// ---------------- router / list ----------------
__global__ void router_k(const float* __restrict__ x, const float* __restrict__ Wr,
                         const float* __restrict__ br) {
    int warp = threadIdx.x >> 5, lane = threadIdx.x & 31;
    int t = blockIdx.x * 8 + warp;
    const float* xp = x + (size_t)t * Dm + lane * 16;
    float4 xv[4];
#pragma unroll
    for (int i = 0; i < 4; i++) xv[i] = *(const float4*)(xp + i * 4);
    float lg[32];
#pragma unroll 1
    for (int n = 0; n < 32; n++) {
        const float* wp = Wr + n * Dm + lane * 16;
        float acc = 0.f;
#pragma unroll
        for (int i = 0; i < 4; i++) {
            float4 w = *(const float4*)(wp + i * 4);
            acc += xv[i].x * w.x + xv[i].y * w.y + xv[i].z * w.z + xv[i].w * w.w;
        }
#pragma unroll
        for (int o = 16; o; o >>= 1) acc += __shfl_xor_sync(0xffffffffu, acc, o);
        lg[n] = acc + br[n];
    }
    if (lane == 0) {
        unsigned used = 0;
        for (int k2 = 0; k2 < 4; k2++) {
            float best = -1e30f; int bi = 0;
            for (int n = 0; n < 32; n++)
                if (!((used >> n) & 1u) && lg[n] > best) { best = lg[n]; bi = n; }
            used |= 1u << bi;
            g_idx[t * 4 + k2] = bi;
        }
    }
}
__global__ void zero_k() { if (threadIdx.x < Np) g_cnt[threadIdx.x] = 0; }
__global__ void build_k() {
    int e = blockIdx.x * 256 + threadIdx.x;
    if (e >= T * Kk) return;
    int n = g_idx[e];
    int pos = atomicAdd(&g_cnt[n], 1);
    g_list[n * T + pos] = e;
}

// ---------------- bf16 split conversions ----------------
__global__ void conv3_k(const float* __restrict__ src, __nv_bfloat16* __restrict__ dst) {
    int i = blockIdx.x * 256 + threadIdx.x;
    int t = i >> 9, d = i & 511;
    float v = src[i];
    __nv_bfloat16 hi = __float2bfloat16(v);
    __nv_bfloat16 lo = __float2bfloat16(v - __bfloat162float(hi));
    dst[(size_t)t * 1024 + d] = hi;
    dst[(size_t)t * 1024 + 512 + d] = lo;
}
__global__ void convw_k(const float* __restrict__ W, __nv_bfloat16* __restrict__ W3,
                        int Kd, int Nd) {
    __shared__ float tile[32][33];
    int n = blockIdx.z, k0 = blockIdx.y * 32, c0 = blockIdx.x * 32;
    const float* Wn = W + (size_t)n * Kd * Nd;
#pragma unroll
    for (int i = 0; i < 32; i += 8)
        tile[threadIdx.y + i][threadIdx.x] = Wn[(size_t)(k0 + threadIdx.y + i) * Nd + c0 + threadIdx.x];
    __syncthreads();
    __nv_bfloat16* Wo = W3 + (size_t)n * Nd * 2 * Kd;
#pragma unroll
    for (int i = 0; i < 32; i += 8) {
        float v = tile[threadIdx.x][threadIdx.y + i];
        __nv_bfloat16 hi = __float2bfloat16(v);
        __nv_bfloat16 lo = __float2bfloat16(v - __bfloat162float(hi));
        size_t ro = (size_t)(c0 + threadIdx.y + i) * 2 * Kd + k0 + threadIdx.x;
        Wo[ro] = hi;
        Wo[ro + Kd] = lo;
    }
}
__global__ void convwd_k(const float* __restrict__ W, __nv_bfloat16* __restrict__ W3, int K) {
    int i = blockIdx.x * 256 + threadIdx.x;
    int n = i / K, k = i - n * K;
    float v = W[i];
    __nv_bfloat16 hi = __float2bfloat16(v);
    __nv_bfloat16 lo = __float2bfloat16(v - __bfloat162float(hi));
    W3[(size_t)n * 2 * K + k] = hi;
    W3[(size_t)n * 2 * K + K + k] = lo;
}

// ---------------- shared HMMA mainloop (warp tile 32x32, 16 warps) ----------------
__device__ __forceinline__ void hmma_chunk16(uint32_t smb_A, uint32_t smb_B,
                                             int warpM, int warpN, int rA, int kA,
                                             int rB, int kB, float acc[2][4][4]) {
#pragma unroll
    for (int kk = 0; kk < 4; kk++) {
        uint32_t af[2][4], bf[4][2];
#pragma unroll
        for (int mt = 0; mt < 2; mt++)
            ldsm4(af[mt], smb_A + (uint32_t)(((warpM + mt * 16 + rA) * FP + kk * 16 + kA) * 2));
#pragma unroll
        for (int nt2 = 0; nt2 < 2; nt2++) {
            uint32_t treg[4];
            ldsm4(treg, smb_B + (uint32_t)(((warpN + nt2 * 16 + rB) * FP + kk * 16 + kB) * 2));
            bf[2 * nt2][0] = treg[0]; bf[2 * nt2][1] = treg[1];
            bf[2 * nt2 + 1][0] = treg[2]; bf[2 * nt2 + 1][1] = treg[3];
        }
#pragma unroll
        for (int mt = 0; mt < 2; mt++)
#pragma unroll
            for (int nt = 0; nt < 4; nt++)
                mma_bf16(acc[mt][nt], af[mt][0], af[mt][1], af[mt][2], af[mt][3],
                         bf[nt][0], bf[nt][1]);
    }
}

// ---------------- FFN pass 1: h = gelu(x @ W1 + b1) ----------------
__global__ __launch_bounds__(512)
void ffn1_mma_k(const float* __restrict__ b1) {
    int n = blockIdx.z, mt0 = blockIdx.y, nb = blockIdx.x * 128;
    int cnt = g_cnt[n];
    int base = mt0 * 128;
    if (base >= cnt) return;

    extern __shared__ __align__(16) __nv_bfloat16 sm[];
    __shared__ int es[128];
    int tid = threadIdx.x, wid = tid >> 5, lane = tid & 31;
    if (tid < 128) es[tid] = (base + tid < cnt) ? g_list[n * T + base + tid] : -1;
    __syncthreads();

    int hr = tid >> 2, q16 = (tid & 3) * 16;
    int e_row = es[hr];
    const __nv_bfloat16* arow = (e_row >= 0) ? (g_x3 + (size_t)(e_row >> 2) * 1024) : 0;
    const __nv_bfloat16* brow = g_W13 + ((size_t)n * Hd + nb + hr) * 1024;
    int sto = hr * FP + q16;

    float acc[2][4][4];
#pragma unroll
    for (int i = 0; i < 2; i++)
#pragma unroll
        for (int j = 0; j < 4; j++)
#pragma unroll
            for (int k = 0; k < 4; k++) acc[i][j][k] = 0.f;

    int g = lane >> 2, t2 = (lane & 3) * 2;
    int warpM = (wid >> 2) * 32, warpN = (wid & 3) * 32;
    int rA = ((lane >> 3) & 1) * 8 + (lane & 7);
    int kA = (lane >> 4) * 8;
    int rB = (lane & 7) + (lane >> 4) * 8;
    int kB = ((lane >> 3) & 1) * 8;
    uint32_t smb = cvta_smem(sm);

    const int NCH = 24;
    uint4 ra[2], rb[2];
    if (arow) {
        ra[0] = *(const uint4*)(arow + q16);
        ra[1] = *(const uint4*)(arow + q16 + 8);
    } else {
        ra[0] = make_uint4(0, 0, 0, 0); ra[1] = make_uint4(0, 0, 0, 0);
    }
    rb[0] = *(const uint4*)(brow + q16);
    rb[1] = *(const uint4*)(brow + q16 + 8);
    *(uint4*)(sm + sto) = ra[0]; *(uint4*)(sm + sto + 8) = ra[1];
    *(uint4*)(sm + FTILE + sto) = rb[0]; *(uint4*)(sm + FTILE + sto + 8) = rb[1];
    __syncthreads();

#pragma unroll 1
    for (int c = 0; c < NCH; c++) {
        int buf = c & 1;
        if (c + 1 < NCH) {
            int c1 = c + 1;
            int kc = c1 & 7;
            int sA = (c1 < 16) ? 0 : 512;
            int sB = (c1 >= 8 && c1 < 16) ? 512 : 0;
            if (arow) {
                const __nv_bfloat16* ap = arow + sA + kc * 64 + q16;
                ra[0] = *(const uint4*)(ap); ra[1] = *(const uint4*)(ap + 8);
            }
            const __nv_bfloat16* bp = brow + sB + kc * 64 + q16;
            rb[0] = *(const uint4*)(bp); rb[1] = *(const uint4*)(bp + 8);
        }
        uint32_t baseA = smb + (uint32_t)(buf * 2 * FTILE * 2);
        hmma_chunk16(baseA, baseA + FTILE * 2, warpM, warpN, rA, kA, rB, kB, acc);
        if (c + 1 < NCH) {
            __nv_bfloat16* d = sm + ((c + 1) & 1) * 2 * FTILE;
            *(uint4*)(d + sto) = ra[0]; *(uint4*)(d + sto + 8) = ra[1];
            *(uint4*)(d + FTILE + sto) = rb[0]; *(uint4*)(d + FTILE + sto + 8) = rb[1];
        }
        __syncthreads();
    }

#pragma unroll
    for (int mt = 0; mt < 2; mt++) {
#pragma unroll
        for (int rr = 0; rr < 2; rr++) {
            int row = warpM + mt * 16 + g + rr * 8;
            int er = es[row];
            if (er < 0) continue;
            __nv_bfloat16* hp = g_h3 + (size_t)er * 4096;
#pragma unroll
            for (int nt = 0; nt < 4; nt++) {
                int col = nb + warpN + nt * 8 + t2;
                float v0 = gelu_f(acc[mt][nt][rr * 2 + 0] + b1[(size_t)n * Hd + col]);
                float v1 = gelu_f(acc[mt][nt][rr * 2 + 1] + b1[(size_t)n * Hd + col + 1]);
                __nv_bfloat16 h0 = __float2bfloat16(v0), h1 = __float2bfloat16(v1);
                __nv_bfloat16 l0 = __float2bfloat16(v0 - __bfloat162float(h0));
                __nv_bfloat16 l1 = __float2bfloat16(v1 - __bfloat162float(h1));
                uint32_t hp2 = (uint32_t)__bfloat16_as_ushort(h0) | ((uint32_t)__bfloat16_as_ushort(h1) << 16);
                uint32_t lp2 = (uint32_t)__bfloat16_as_ushort(l0) | ((uint32_t)__bfloat16_as_ushort(l1) << 16);
                *(uint32_t*)(hp + col) = hp2;
                *(uint32_t*)(hp + 2048 + col) = lp2;
            }
        }
    }
}

// ---------------- FFN pass 2: out = h @ W2 + b2 ----------------
__global__ __launch_bounds__(512)
void ffn2_mma_k(const float* __restrict__ b2) {
    int n = blockIdx.z, mt0 = blockIdx.y, nb = blockIdx.x * 128;
    int cnt = g_cnt[n];
    int base = mt0 * 128;
    if (base >= cnt) return;

    extern __shared__ __align__(16) __nv_bfloat16 sm[];
    __shared__ int es[128];
    int tid = threadIdx.x, wid = tid >> 5, lane = tid & 31;
    if (tid < 128) es[tid] = (base + tid < cnt) ? g_list[n * T + base + tid] : -1;
    __syncthreads();

    int hr = tid >> 2, q16 = (tid & 3) * 16;
    int e_row = es[hr];
    const __nv_bfloat16* arow = (e_row >= 0) ? (g_h3 + (size_t)e_row * 4096) : 0;
    const __nv_bfloat16* brow = g_W23 + ((size_t)n * Dm + nb + hr) * 4096;
    int sto = hr * FP + q16;

    float acc[2][4][4];
#pragma unroll
    for (int i = 0; i < 2; i++)
#pragma unroll
        for (int j = 0; j < 4; j++)
#pragma unroll
            for (int k = 0; k < 4; k++) acc[i][j][k] = 0.f;

    int g = lane >> 2, t2 = (lane & 3) * 2;
    int warpM = (wid >> 2) * 32, warpN = (wid & 3) * 32;
    int rA = ((lane >> 3) & 1) * 8 + (lane & 7);
    int kA = (lane >> 4) * 8;
    int rB = (lane & 7) + (lane >> 4) * 8;
    int kB = ((lane >> 3) & 1) * 8;
    uint32_t smb = cvta_smem(sm);

    const int NCH = 96;
    uint4 ra[2], rb[2];
    if (arow) {
        ra[0] = *(const uint4*)(arow + q16);
        ra[1] = *(const uint4*)(arow + q16 + 8);
    } else {
        ra[0] = make_uint4(0, 0, 0, 0); ra[1] = make_uint4(0, 0, 0, 0);
    }
    rb[0] = *(const uint4*)(brow + q16);
    rb[1] = *(const uint4*)(brow + q16 + 8);
    *(uint4*)(sm + sto) = ra[0]; *(uint4*)(sm + sto + 8) = ra[1];
    *(uint4*)(sm + FTILE + sto) = rb[0]; *(uint4*)(sm + FTILE + sto + 8) = rb[1];
    __syncthreads();

#pragma unroll 1
    for (int c = 0; c < NCH; c++) {
        int buf = c & 1;
        if (c + 1 < NCH) {
            int c1 = c + 1;
            int kc = c1 & 31;
            int sA = (c1 < 64) ? 0 : 2048;
            int sB = (c1 >= 32 && c1 < 64) ? 2048 : 0;
            if (arow) {
                const __nv_bfloat16* ap = arow + sA + kc * 64 + q16;
                ra[0] = *(const uint4*)(ap); ra[1] = *(const uint4*)(ap + 8);
            }
            const __nv_bfloat16* bp = brow + sB + kc * 64 + q16;
            rb[0] = *(const uint4*)(bp); rb[1] = *(const uint4*)(bp + 8);
        }
        uint32_t baseA = smb + (uint32_t)(buf * 2 * FTILE * 2);
        hmma_chunk16(baseA, baseA + FTILE * 2, warpM, warpN, rA, kA, rB, kB, acc);
        if (c + 1 < NCH) {
            __nv_bfloat16* d = sm + ((c + 1) & 1) * 2 * FTILE;
            *(uint4*)(d + sto) = ra[0]; *(uint4*)(d + sto + 8) = ra[1];
            *(uint4*)(d + FTILE + sto) = rb[0]; *(uint4*)(d + FTILE + sto + 8) = rb[1];
        }
        __syncthreads();
    }

#pragma unroll
    for (int mt = 0; mt < 2; mt++) {
#pragma unroll
        for (int rr = 0; rr < 2; rr++) {
            int row = warpM + mt * 16 + g + rr * 8;
            int er = es[row];
            if (er < 0) continue;
            float* op = g_pairs + (size_t)er * Dm;
#pragma unroll
            for (int nt = 0; nt < 4; nt++) {
                int col = nb + warpN + nt * 8 + t2;
                float2 o;
                o.x = acc[mt][nt][rr * 2 + 0] + b2[(size_t)n * Dm + col];
                o.y = acc[mt][nt][rr * 2 + 1] + b2[(size_t)n * Dm + col + 1];
                *(float2*)(op + col) = o;
            }
        }
    }
}

// ---------------- dense HMMA GEMM: C[M,Nc] = A @ W^T + bias ----------------
__global__ __launch_bounds__(512)
void gemm_mma_k(const __nv_bfloat16* __restrict__ A3, const __nv_bfloat16* __restrict__ W3,
                const float* __restrict__ bias, float* __restrict__ C, int Nc, int Kd) {
    int nb = blockIdx.x * 128, mg = blockIdx.y * 128;
    extern __shared__ __align__(16) __nv_bfloat16 sm[];
    int tid = threadIdx.x, wid = tid >> 5, lane = tid & 31;

    int hr = tid >> 2, q16 = (tid & 3) * 16;
    const __nv_bfloat16* arow = A3 + (size_t)(mg + hr) * 2 * Kd;
    const __nv_bfloat16* brow = W3 + (size_t)(nb + hr) * 2 * Kd;
    int sto = hr * FP + q16;

    float acc[2][4][4];
#pragma unroll
    for (int i = 0; i < 2; i++)
#pragma unroll
        for (int j = 0; j < 4; j++)
#pragma unroll
            for (int k = 0; k < 4; k++) acc[i][j][k] = 0.f;

    int g = lane >> 2, t2 = (lane & 3) * 2;
    int warpM = (wid >> 2) * 32, warpN = (wid & 3) * 32;
    int rA = ((lane >> 3) & 1) * 8 + (lane & 7);
    int kA = (lane >> 4) * 8;
    int rB = (lane & 7) + (lane >> 4) * 8;
    int kB = ((lane >> 3) & 1) * 8;
    uint32_t smb = cvta_smem(sm);

    int cpseg = Kd >> 6;
    int NCH = 3 * cpseg;
    uint4 ra[2], rb[2];
    ra[0] = *(const uint4*)(arow + q16); ra[1] = *(const uint4*)(arow + q16 + 8);
    rb[0] = *(const uint4*)(brow + q16); rb[1] = *(const uint4*)(brow + q16 + 8);
    *(uint4*)(sm + sto) = ra[0]; *(uint4*)(sm + sto + 8) = ra[1];
    *(uint4*)(sm + FTILE + sto) = rb[0]; *(uint4*)(sm + FTILE + sto + 8) = rb[1];
    __syncthreads();

#pragma unroll 1
    for (int c = 0; c < NCH; c++) {
        int buf = c & 1;
        if (c + 1 < NCH) {
            int c1 = c + 1;
            int seg = c1 / cpseg;
            int kc = c1 - seg * cpseg;
            int sA = (seg == 2) ? Kd : 0;
            int sB = (seg == 1) ? Kd : 0;
            const __nv_bfloat16* ap = arow + sA + kc * 64 + q16;
            const __nv_bfloat16* bp = brow + sB + kc * 64 + q16;
            ra[0] = *(const uint4*)(ap); ra[1] = *(const uint4*)(ap + 8);
            rb[0] = *(const uint4*)(bp); rb[1] = *(const uint4*)(bp + 8);
        }
        uint32_t baseA = smb + (uint32_t)(buf * 2 * FTILE * 2);
        hmma_chunk16(baseA, baseA + FTILE * 2, warpM, warpN, rA, kA, rB, kB, acc);
        if (c + 1 < NCH) {
            __nv_bfloat16* d = sm + ((c + 1) & 1) * 2 * FTILE;
            *(uint4*)(d + sto) = ra[0]; *(uint4*)(d + sto + 8) = ra[1];
            *(uint4*)(d + FTILE + sto) = rb[0]; *(uint4*)(d + FTILE + sto + 8) = rb[1];
        }
        __syncthreads();
    }

#pragma unroll
    for (int mt = 0; mt < 2; mt++) {
#pragma unroll
        for (int rr = 0; rr < 2; rr++) {
            int row = mg + warpM + mt * 16 + g + rr * 8;
            float* op = C + (size_t)row * Nc;
#pragma unroll
            for (int nt = 0; nt < 4; nt++) {
                int col = nb + warpN + nt * 8 + t2;
                float2 o;
                o.x = acc[mt][nt][rr * 2 + 0] + bias[col];
                o.y = acc[mt][nt][rr * 2 + 1] + bias[col + 1];
                *(float2*)(op + col) = o;
            }
        }
    }
}

// ---------------- mean over k, fused bf16 split ----------------
__global__ void reduce3_k() {
    int id = blockIdx.x * 256 + threadIdx.x;
    if (id >= T * Dm / 4) return;
    int t = id >> 7, c4 = (id & 127) << 2;
    float4 s = make_float4(0.f, 0.f, 0.f, 0.f);
#pragma unroll
    for (int k2 = 0; k2 < 4; k2++) {
        float4 v = *(const float4*)&g_pairs[(size_t)(t * 4 + k2) * Dm + c4];
        s.x += v.x; s.y += v.y; s.z += v.z; s.w += v.w;
    }
    s.x *= 0.25f; s.y *= 0.25f; s.z *= 0.25f; s.w *= 0.25f;
    *(float4*)&g_nout[(size_t)t * Dm + c4] = s;
    float vv[4] = {s.x, s.y, s.z, s.w};
    ushort hi4[4], lo4[4];
#pragma unroll
    for (int i = 0; i < 4; i++) {
        __nv_bfloat16 hi = __float2bfloat16(vv[i]);
        __nv_bfloat16 lo = __float2bfloat16(vv[i] - __bfloat162float(hi));
        hi4[i] = __bfloat16_as_ushort(hi);
        lo4[i] = __bfloat16_as_ushort(lo);
    }
    *(uint2*)&g_nout3[(size_t)t * 1024 + c4] = *(uint2*)hi4;
    *(uint2*)&g_nout3[(size_t)t * 1024 + 512 + c4] = *(uint2*)lo4;
}

// ---------------- attention (flash, q-tile 64), bf16-split epilogue ----------------
__global__ __launch_bounds__(256)
void attn2_k() {
    extern __shared__ float smf[];
    float* Qs  = smf;
    float* KPs = smf + AT_REG;
    float* Vs  = smf + 2 * AT_REG;
    int q0 = blockIdx.x * 64, h = blockIdx.y, b = blockIdx.z;
    int tid = threadIdx.x, lane = tid & 31, w = tid >> 5;
    int qr = w * 8;
    {
        int r = tid >> 2, c0 = (tid & 3) * 16;
        const float* qp = g_qkv + (size_t)(b * Sd + q0 + r) * D3 + h * HDd + c0;
#pragma unroll
        for (int i = 0; i < 4; i++) {
            float4 v = *(const float4*)(qp + i * 4);
            Qs[(c0 + i * 4 + 0) * AT_PAD + r] = v.x * 0.125f;
            Qs[(c0 + i * 4 + 1) * AT_PAD + r] = v.y * 0.125f;
            Qs[(c0 + i * 4 + 2) * AT_PAD + r] = v.z * 0.125f;
            Qs[(c0 + i * 4 + 3) * AT_PAD + r] = v.w * 0.125f;
        }
    }
    float m[8], l[8], o0[8], o1[8];
#pragma unroll
    for (int r = 0; r < 8; r++) { m[r] = -1e30f; l[r] = 0.f; o0[r] = 0.f; o1[r] = 0.f; }
#pragma unroll 1
    for (int j0 = 0; j0 < Sd; j0 += 64) {
        __syncthreads();
        {
            int r = tid >> 2, c0 = (tid & 3) * 16;
            const float* kp = g_qkv + (size_t)(b * Sd + j0 + r) * D3 + Dm + h * HDd + c0;
            const float* vp = kp + Dm;
#pragma unroll
            for (int i = 0; i < 4; i++) {
                float4 kv = *(const float4*)(kp + i * 4);
                KPs[(c0 + i * 4 + 0) * AT_PAD + r] = kv.x;
                KPs[(c0 + i * 4 + 1) * AT_PAD + r] = kv.y;
                KPs[(c0 + i * 4 + 2) * AT_PAD + r] = kv.z;
                KPs[(c0 + i * 4 + 3) * AT_PAD + r] = kv.w;
                float4 vv = *(const float4*)(vp + i * 4);
                Vs[(c0 + i * 4 + 0) * AT_PAD + r] = vv.x;
                Vs[(c0 + i * 4 + 1) * AT_PAD + r] = vv.y;
                Vs[(c0 + i * 4 + 2) * AT_PAD + r] = vv.z;
                Vs[(c0 + i * 4 + 3) * AT_PAD + r] = vv.w;
            }
        }
        __syncthreads();
        float s[8][2];
#pragma unroll
        for (int r = 0; r < 8; r++) { s[r][0] = 0.f; s[r][1] = 0.f; }
#pragma unroll 8
        for (int d = 0; d < 64; d++) {
            float4 qa = *(const float4*)&Qs[d * AT_PAD + qr];
            float4 qb = *(const float4*)&Qs[d * AT_PAD + qr + 4];
            float2 kk = *(const float2*)&KPs[d * AT_PAD + 2 * lane];
            s[0][0] += qa.x * kk.x; s[0][1] += qa.x * kk.y;
            s[1][0] += qa.y * kk.x; s[1][1] += qa.y * kk.y;
            s[2][0] += qa.z * kk.x; s[2][1] += qa.z * kk.y;
            s[3][0] += qa.w * kk.x; s[3][1] += qa.w * kk.y;
            s[4][0] += qb.x * kk.x; s[4][1] += qb.x * kk.y;
            s[5][0] += qb.y * kk.x; s[5][1] += qb.y * kk.y;
            s[6][0] += qb.z * kk.x; s[6][1] += qb.z * kk.y;
            s[7][0] += qb.w * kk.x; s[7][1] += qb.w * kk.y;
        }
#pragma unroll
        for (int r = 0; r < 8; r++) {
            float tmax = fmaxf(s[r][0], s[r][1]);
#pragma unroll
            for (int o = 16; o; o >>= 1) tmax = fmaxf(tmax, __shfl_xor_sync(0xffffffffu, tmax, o));
            float mn = fmaxf(m[r], tmax);
            float corr = __expf(m[r] - mn);
            float p0 = __expf(s[r][0] - mn);
            float p1 = __expf(s[r][1] - mn);
            float rs = p0 + p1;
#pragma unroll
            for (int o = 16; o; o >>= 1) rs += __shfl_xor_sync(0xffffffffu, rs, o);
            l[r] = l[r] * corr + rs;
            m[r] = mn;
            o0[r] *= corr; o1[r] *= corr;
            s[r][0] = p0; s[r][1] = p1;
        }
        __syncthreads();
#pragma unroll
        for (int r = 0; r < 8; r++)
            *(float2*)&KPs[(qr + r) * AT_PAD + 2 * lane] = make_float2(s[r][0], s[r][1]);
        __syncthreads();
        const float* vr0 = &Vs[lane * AT_PAD];
        const float* vr1 = &Vs[(lane + 32) * AT_PAD];
#pragma unroll 4
        for (int k4 = 0; k4 < 16; k4++) {
            float4 v0 = *(const float4*)(vr0 + 4 * k4);
            float4 v1 = *(const float4*)(vr1 + 4 * k4);
#pragma unroll
            for (int r = 0; r < 8; r++) {
                float4 p = *(const float4*)&KPs[(qr + r) * AT_PAD + 4 * k4];
                o0[r] += p.x * v0.x + p.y * v0.y + p.z * v0.z + p.w * v0.w;
                o1[r] += p.x * v1.x + p.y * v1.y + p.z * v1.z + p.w * v1.w;
            }
        }
    }
#pragma unroll
    for (int r = 0; r < 8; r++) {
        float inv = 1.0f / l[r];
        int t = b * Sd + q0 + qr + r;
        float va = o0[r] * inv, vb = o1[r] * inv;
        __nv_bfloat16 ha = __float2bfloat16(va);
        __nv_bfloat16 la = __float2bfloat16(va - __bfloat162float(ha));
        __nv_bfloat16 hb = __float2bfloat16(vb);
        __nv_bfloat16 lb = __float2bfloat16(vb - __bfloat162float(hb));
        __nv_bfloat16* dp = g_attno3 + (size_t)t * 1024 + h * HDd + lane;
        dp[0] = ha; dp[32] = hb;
        dp[512] = la; dp[544] = lb;
    }
}

// ---------------- fused dual LN ----------------
__global__ void ln_k(const float* __restrict__ x,
                     const float* __restrict__ ln1w, const float* __restrict__ ln1b,
                     const float* __restrict__ ln2w, const float* __restrict__ ln2b,
                     float* __restrict__ out) {
    int t = blockIdx.x, tid = threadIdx.x;
    __shared__ float r1[8], r2[8];
    __shared__ float mu_s, rs_s;
    size_t off = (size_t)t * Dm;
    float a0 = x[off + tid] + g_attnout[off + tid];
    float a1 = x[off + 256 + tid] + g_attnout[off + 256 + tid];
    float s = a0 + a1, ss = a0 * a0 + a1 * a1;
#pragma unroll
    for (int o = 16; o; o >>= 1) {
        s += __shfl_xor_sync(0xffffffffu, s, o);
        ss += __shfl_xor_sync(0xffffffffu, ss, o);
    }
    if ((tid & 31) == 0) { r1[tid >> 5] = s; r2[tid >> 5] = ss; }
    __syncthreads();
    if (tid == 0) {
        float S = 0.f, SS = 0.f;
#pragma unroll
        for (int i = 0; i < 8; i++) { S += r1[i]; SS += r2[i]; }
        float mu = S * (1.0f / 512.0f);
        mu_s = mu;
        rs_s = rsqrtf(SS * (1.0f / 512.0f) - mu * mu + 1e-5f);
    }
    __syncthreads();
    float mu = mu_s, rs = rs_s;
    float z0 = (a0 - mu) * rs * ln1w[tid] + ln1b[tid] + g_nout[off + tid];
    float z1 = (a1 - mu) * rs * ln1w[256 + tid] + ln1b[256 + tid] + g_nout[off + 256 + tid];
    s = z0 + z1; ss = z0 * z0 + z1 * z1;
#pragma unroll
    for (int o = 16; o; o >>= 1) {
        s += __shfl_xor_sync(0xffffffffu, s, o);
        ss += __shfl_xor_sync(0xffffffffu, ss, o);
    }
    __syncthreads();
    if ((tid & 31) == 0) { r1[tid >> 5] = s; r2[tid >> 5] = ss; }
    __syncthreads();
    if (tid == 0) {
        float S = 0.f, SS = 0.f;
#pragma unroll
        for (int i = 0; i < 8; i++) { S += r1[i]; SS += r2[i]; }
        float mu2 = S * (1.0f / 512.0f);
        mu_s = mu2;
        rs_s = rsqrtf(SS * (1.0f / 512.0f) - mu2 * mu2 + 1e-5f);
    }
    __syncthreads();
    mu = mu_s; rs = rs_s;
    out[off + tid] = (z0 - mu) * rs * ln2w[tid] + ln2b[tid];
    out[off + 256 + tid] = (z1 - mu) * rs * ln2w[256 + tid] + ln2b[256 + tid];
}

// ---------------- launcher ----------------
extern "C" void kernel_launch(void* const* d_in, const int* in_sizes, int n_in,
                              void* d_out, int out_size) {
    const float* x    = (const float*)d_in[0];
    const float* Wr   = (const float*)d_in[1];
    const float* br   = (const float*)d_in[2];
    const float* W1   = (const float*)d_in[3];
    const float* b1   = (const float*)d_in[4];
    const float* W2   = (const float*)d_in[5];
    const float* b2   = (const float*)d_in[6];
    const float* Wqkv = (const float*)d_in[7];
    const float* bqkv = (const float*)d_in[8];
    const float* Wo   = (const float*)d_in[9];
    const float* bo   = (const float*)d_in[10];
    const float* ln1w = (const float*)d_in[11];
    const float* ln1b = (const float*)d_in[12];
    const float* ln2w = (const float*)d_in[13];
    const float* ln2b = (const float*)d_in[14];
    float* out = (float*)d_out;

    float *p_qkv, *p_attnout;
    __nv_bfloat16 *p_x3, *p_w13, *p_w23, *p_wqkv3, *p_wo3, *p_nout3, *p_attno3;
    cudaGetSymbolAddress((void**)&p_qkv, g_qkv);
    cudaGetSymbolAddress((void**)&p_attnout, g_attnout);
    cudaGetSymbolAddress((void**)&p_x3, g_x3);
    cudaGetSymbolAddress((void**)&p_w13, g_W13);
    cudaGetSymbolAddress((void**)&p_w23, g_W23);
    cudaGetSymbolAddress((void**)&p_wqkv3, g_Wqkv3);
    cudaGetSymbolAddress((void**)&p_wo3, g_Wo3);
    cudaGetSymbolAddress((void**)&p_nout3, g_nout3);
    cudaGetSymbolAddress((void**)&p_attno3, g_attno3);

    static int init_done = 0;
    static cudaStream_t sA, sB;
    static cudaEvent_t evRoot, evA, evB, evQ, evO;
    if (!init_done) {
        cudaFuncSetAttribute(attn2_k, cudaFuncAttributeMaxDynamicSharedMemorySize, SMEM_ATTN);
        cudaFuncSetAttribute(ffn1_mma_k, cudaFuncAttributeMaxDynamicSharedMemorySize, SMEM_FFN);
        cudaFuncSetAttribute(ffn2_mma_k, cudaFuncAttributeMaxDynamicSharedMemorySize, SMEM_FFN);
        cudaFuncSetAttribute(gemm_mma_k, cudaFuncAttributeMaxDynamicSharedMemorySize, SMEM_FFN);
        cudaStreamCreateWithFlags(&sA, cudaStreamNonBlocking);
        cudaStreamCreateWithFlags(&sB, cudaStreamNonBlocking);
        cudaEventCreateWithFlags(&evRoot, cudaEventDisableTiming);
        cudaEventCreateWithFlags(&evA, cudaEventDisableTiming);
        cudaEventCreateWithFlags(&evB, cudaEventDisableTiming);
        cudaEventCreateWithFlags(&evQ, cudaEventDisableTiming);
        cudaEventCreateWithFlags(&evO, cudaEventDisableTiming);
        init_done = 1;
    }

    // fork point
    cudaEventRecord(evRoot, 0);
    cudaStreamWaitEvent(sA, evRoot, 0);
    cudaStreamWaitEvent(sB, evRoot, 0);

    // stream A: inputs needed by ffn1
    conv3_k<<<T * Dm / 256, 256, 0, sA>>>(x, p_x3);
    convw_k<<<dim3(Hd / 32, Dm / 32, Np), dim3(32, 8), 0, sA>>>(W1, p_w13, Dm, Hd);
    cudaEventRecord(evA, sA);

    // stream B: inputs needed by ffn2 / projections
    convw_k<<<dim3(Dm / 32, Hd / 32, Np), dim3(32, 8), 0, sB>>>(W2, p_w23, Hd, Dm);
    cudaEventRecord(evB, sB);
    convwd_k<<<D3 * Dm / 256, 256, 0, sB>>>(Wqkv, p_wqkv3, Dm);
    cudaEventRecord(evQ, sB);
    convwd_k<<<Dm * Dm / 256, 256, 0, sB>>>(Wo, p_wo3, Dm);
    cudaEventRecord(evO, sB);

    // main stream: router + list build (overlaps conversions)
    router_k<<<T / 8, 256>>>(x, Wr, br);
    zero_k<<<1, 32>>>();
    build_k<<<(T * Kk + 255) / 256, 256>>>();

    // sparse FFN on tensor cores
    cudaStreamWaitEvent(0, evA, 0);
    ffn1_mma_k<<<dim3(16, 16, 32), 512, SMEM_FFN>>>(b1);
    cudaStreamWaitEvent(0, evB, 0);
    ffn2_mma_k<<<dim3(4, 16, 32), 512, SMEM_FFN>>>(b2);
    reduce3_k<<<(T * Dm / 4 + 255) / 256, 256>>>();

    // attention (HMMA projections + fp32 flash core)
    cudaStreamWaitEvent(0, evQ, 0);
    gemm_mma_k<<<dim3(D3 / 128, T / 128), 512, SMEM_FFN>>>(p_nout3, p_wqkv3, bqkv, p_qkv, D3, Dm);
    attn2_k<<<dim3(Sd / 64, NHd, Bd), 256, SMEM_ATTN>>>();
    cudaStreamWaitEvent(0, evO, 0);
    gemm_mma_k<<<dim3(Dm / 128, T / 128), 512, SMEM_FFN>>>(p_attno3, p_wo3, bo, p_attnout, Dm, Dm);

    // epilogue
    ln_k<<<T, 256>>>(x, ln1w, ln1b, ln2w, ln2b, out);
}

// round 11
// speedup vs baseline: 1.0265x; 1.0265x over previous
#include <cuda_runtime.h>
#include <cuda_bf16.h>
#include <math.h>
#include <stdint.h>

#define T   2048
#define Dm  512
#define Np  32
#define Hd  2048
#define Kk  4
#define NHd 8
#define HDd 64
#define Sd  1024
#define Bd  2
#define D3  1536

#define AT_PAD 68
#define AT_REG (64 * AT_PAD)
#define SMEM_ATTN (3 * AT_REG * 4)

// HMMA tile constants: pitch 72 bf16 per row
#define FP 72
#define FTILE (128 * FP)                 // bf16 units per 128-row tile (dense gemm)
#define SMEM_GEMM (4 * FTILE * 2)        // dense gemm: 2 bufs x (A128 + B128)
#define FSTAGE (192 * FP)                // ffn stage: A(64 rows) + B(128 rows), bf16 units
#define SMEM_FFN (2 * FSTAGE * 2)        // 2 stages, bytes = 55296

__device__ int   g_idx[T * Kk];
__device__ int   g_cnt[Np];
__device__ int   g_list[Np * T];
__device__ float g_pairs[T * Kk * Dm];
__device__ float g_nout[T * Dm];
__device__ float g_qkv[T * D3];
__device__ float g_attnout[T * Dm];
__device__ __nv_bfloat16 g_x3[T * 2 * Dm];                 // [t][hi(512)|lo(512)]
__device__ __nv_bfloat16 g_nout3[T * 2 * Dm];
__device__ __nv_bfloat16 g_attno3[T * 2 * Dm];
__device__ __nv_bfloat16 g_W13[(size_t)Np * Hd * 2 * Dm];  // [n][h][Wh|Wl]
__device__ __nv_bfloat16 g_W23[(size_t)Np * Dm * 2 * Hd];  // [n][d][Wh|Wl]
__device__ __nv_bfloat16 g_Wqkv3[(size_t)D3 * 2 * Dm];
__device__ __nv_bfloat16 g_Wo3[(size_t)Dm * 2 * Dm];
__device__ __nv_bfloat16 g_h3[(size_t)T * Kk * 2 * Hd];    // [pair][hh|hl]

__device__ __forceinline__ float gelu_f(float v) {
    float u = 0.7978845608028654f * (v + 0.044715f * v * v * v);
    return 0.5f * v * (1.0f + tanhf(u));
}

__device__ __forceinline__ uint32_t cvta_smem(const void* p) {
    uint32_t a;
    asm("{ .reg .u64 t; cvta.to.shared.u64 t, %1; cvt.u32.u64 %0, t; }" : "=r"(a) : "l"(p));
    return a;
}

__device__ __forceinline__ void mma_bf16(float c[4], uint32_t a0, uint32_t a1,
                                         uint32_t a2, uint32_t a3,
                                         uint32_t b0, uint32_t b1) {
    asm volatile(
        "mma.sync.aligned.m16n8k16.row.col.f32.bf16.bf16.f32 "
        "{%0,%1,%2,%3}, {%4,%5,%6,%7}, {%8,%9}, {%0,%1,%2,%3};"
        : "+f"(c[0]), "+f"(c[1]), "+f"(c[2]), "+f"(c[3])
        : "r"(a0), "r"(a1), "r"(a2), "r"(a3), "r"(b0), "r"(b1));
}

__device__ __forceinline__ void ldsm4(uint32_t r[4], uint32_t a) {
    asm volatile("ldmatrix.sync.aligned.m8n8.x4.shared.b16 {%0,%1,%2,%3}, [%4];"
        : "=r"(r[0]), "=r"(r[1]), "=r"(r[2]), "=r"(r[3]) : "r"(a));
}

// ---------------- router / list ----------------
__global__ void router_k(const float* __restrict__ x, const float* __restrict__ Wr,
                         const float* __restrict__ br) {
    int warp = threadIdx.x >> 5, lane = threadIdx.x & 31;
    int t = blockIdx.x * 8 + warp;
    const float* xp = x + (size_t)t * Dm + lane * 16;
    float4 xv[4];
#pragma unroll
    for (int i = 0; i < 4; i++) xv[i] = *(const float4*)(xp + i * 4);
    float lg[32];
#pragma unroll 1
    for (int n = 0; n < 32; n++) {
        const float* wp = Wr + n * Dm + lane * 16;
        float acc = 0.f;
#pragma unroll
        for (int i = 0; i < 4; i++) {
            float4 w = *(const float4*)(wp + i * 4);
            acc += xv[i].x * w.x + xv[i].y * w.y + xv[i].z * w.z + xv[i].w * w.w;
        }
#pragma unroll
        for (int o = 16; o; o >>= 1) acc += __shfl_xor_sync(0xffffffffu, acc, o);
        lg[n] = acc + br[n];
    }
    if (lane == 0) {
        unsigned used = 0;
        for (int k2 = 0; k2 < 4; k2++) {
            float best = -1e30f; int bi = 0;
            for (int n = 0; n < 32; n++)
                if (!((used >> n) & 1u) && lg[n] > best) { best = lg[n]; bi = n; }
            used |= 1u << bi;
            g_idx[t * 4 + k2] = bi;
        }
    }
}
__global__ void zero_k() { if (threadIdx.x < Np) g_cnt[threadIdx.x] = 0; }
__global__ void build_k() {
    int e = blockIdx.x * 256 + threadIdx.x;
    if (e >= T * Kk) return;
    int n = g_idx[e];
    int pos = atomicAdd(&g_cnt[n], 1);
    g_list[n * T + pos] = e;
}

// ---------------- bf16 split conversions ----------------
__global__ void conv3_k(const float* __restrict__ src, __nv_bfloat16* __restrict__ dst) {
    int i = blockIdx.x * 256 + threadIdx.x;
    int t = i >> 9, d = i & 511;
    float v = src[i];
    __nv_bfloat16 hi = __float2bfloat16(v);
    __nv_bfloat16 lo = __float2bfloat16(v - __bfloat162float(hi));
    dst[(size_t)t * 1024 + d] = hi;
    dst[(size_t)t * 1024 + 512 + d] = lo;
}
__global__ void convw_k(const float* __restrict__ W, __nv_bfloat16* __restrict__ W3,
                        int Kd, int Nd) {
    __shared__ float tile[32][33];
    int n = blockIdx.z, k0 = blockIdx.y * 32, c0 = blockIdx.x * 32;
    const float* Wn = W + (size_t)n * Kd * Nd;
#pragma unroll
    for (int i = 0; i < 32; i += 8)
        tile[threadIdx.y + i][threadIdx.x] = Wn[(size_t)(k0 + threadIdx.y + i) * Nd + c0 + threadIdx.x];
    __syncthreads();
    __nv_bfloat16* Wo = W3 + (size_t)n * Nd * 2 * Kd;
#pragma unroll
    for (int i = 0; i < 32; i += 8) {
        float v = tile[threadIdx.x][threadIdx.y + i];
        __nv_bfloat16 hi = __float2bfloat16(v);
        __nv_bfloat16 lo = __float2bfloat16(v - __bfloat162float(hi));
        size_t ro = (size_t)(c0 + threadIdx.y + i) * 2 * Kd + k0 + threadIdx.x;
        Wo[ro] = hi;
        Wo[ro + Kd] = lo;
    }
}
__global__ void convwd_k(const float* __restrict__ W, __nv_bfloat16* __restrict__ W3, int K) {
    int i = blockIdx.x * 256 + threadIdx.x;
    int n = i / K, k = i - n * K;
    float v = W[i];
    __nv_bfloat16 hi = __float2bfloat16(v);
    __nv_bfloat16 lo = __float2bfloat16(v - __bfloat162float(hi));
    W3[(size_t)n * 2 * K + k] = hi;
    W3[(size_t)n * 2 * K + K + k] = lo;
}

// ---------------- HMMA chunk: warp tile 64x32 (dense gemm) ----------------
__device__ __forceinline__ void hmma_chunk(uint32_t smb_A, uint32_t smb_B,
                                           int warpM, int warpN, int rA, int kA,
                                           int rB, int kB, float acc[4][4][4]) {
#pragma unroll
    for (int kk = 0; kk < 4; kk++) {
        uint32_t af[4][4], bf[4][2];
#pragma unroll
        for (int mt = 0; mt < 4; mt++)
            ldsm4(af[mt], smb_A + (uint32_t)(((warpM + mt * 16 + rA) * FP + kk * 16 + kA) * 2));
#pragma unroll
        for (int nt2 = 0; nt2 < 2; nt2++) {
            uint32_t treg[4];
            ldsm4(treg, smb_B + (uint32_t)(((warpN + nt2 * 16 + rB) * FP + kk * 16 + kB) * 2));
            bf[2 * nt2][0] = treg[0]; bf[2 * nt2][1] = treg[1];
            bf[2 * nt2 + 1][0] = treg[2]; bf[2 * nt2 + 1][1] = treg[3];
        }
#pragma unroll
        for (int mt = 0; mt < 4; mt++)
#pragma unroll
            for (int nt = 0; nt < 4; nt++)
                mma_bf16(acc[mt][nt], af[mt][0], af[mt][1], af[mt][2], af[mt][3],
                         bf[nt][0], bf[nt][1]);
    }
}

// ---------------- HMMA chunk: warp tile 32x32 (ffn, M=64 tiles) ----------------
__device__ __forceinline__ void hmma_chunk16(uint32_t smb_A, uint32_t smb_B,
                                             int warpM, int warpN, int rA, int kA,
                                             int rB, int kB, float acc[2][4][4]) {
#pragma unroll
    for (int kk = 0; kk < 4; kk++) {
        uint32_t af[2][4], bf[4][2];
#pragma unroll
        for (int mt = 0; mt < 2; mt++)
            ldsm4(af[mt], smb_A + (uint32_t)(((warpM + mt * 16 + rA) * FP + kk * 16 + kA) * 2));
#pragma unroll
        for (int nt2 = 0; nt2 < 2; nt2++) {
            uint32_t treg[4];
            ldsm4(treg, smb_B + (uint32_t)(((warpN + nt2 * 16 + rB) * FP + kk * 16 + kB) * 2));
            bf[2 * nt2][0] = treg[0]; bf[2 * nt2][1] = treg[1];
            bf[2 * nt2 + 1][0] = treg[2]; bf[2 * nt2 + 1][1] = treg[3];
        }
#pragma unroll
        for (int mt = 0; mt < 2; mt++)
#pragma unroll
            for (int nt = 0; nt < 4; nt++)
                mma_bf16(acc[mt][nt], af[mt][0], af[mt][1], af[mt][2], af[mt][3],
                         bf[nt][0], bf[nt][1]);
    }
}

// ---------------- FFN pass 1: h = gelu(x @ W1 + b1), M=64 tiles ----------------
__global__ __launch_bounds__(256, 2)
void ffn1_mma_k(const float* __restrict__ b1) {
    int n = blockIdx.z, mt0 = blockIdx.y, nb = blockIdx.x * 128;
    int cnt = g_cnt[n];
    int base = mt0 * 64;
    if (base >= cnt) return;

    extern __shared__ __align__(16) __nv_bfloat16 sm[];
    __shared__ int es[64];
    int tid = threadIdx.x, wid = tid >> 5, lane = tid & 31;
    if (tid < 64) es[tid] = (base + tid < cnt) ? g_list[n * T + base + tid] : -1;
    __syncthreads();

    // A loader: 64 rows, 16 k per thread
    int arw = tid >> 2, aq = (tid & 3) * 16;
    int e_row = es[arw];
    const __nv_bfloat16* arow = (e_row >= 0) ? (g_x3 + (size_t)(e_row >> 2) * 1024) : 0;
    int stoA = arw * FP + aq;
    // B loader: 128 rows, 32 k per thread
    int brw = tid >> 1, bh = (tid & 1) * 32;
    const __nv_bfloat16* brow = g_W13 + ((size_t)n * Hd + nb + brw) * 1024;
    int stoB = 64 * FP + brw * FP + bh;

    float acc[2][4][4];
#pragma unroll
    for (int i = 0; i < 2; i++)
#pragma unroll
        for (int j = 0; j < 4; j++)
#pragma unroll
            for (int k = 0; k < 4; k++) acc[i][j][k] = 0.f;

    int g = lane >> 2, t2 = (lane & 3) * 2;
    int warpM = (wid >> 2) * 32, warpN = (wid & 3) * 32;
    int rA = ((lane >> 3) & 1) * 8 + (lane & 7);
    int kA = (lane >> 4) * 8;
    int rB = (lane & 7) + (lane >> 4) * 8;
    int kB = ((lane >> 3) & 1) * 8;
    uint32_t smb = cvta_smem(sm);

    const int NCH = 24;
    uint4 ra[2], rb[4];
    if (arow) {
        ra[0] = *(const uint4*)(arow + aq);
        ra[1] = *(const uint4*)(arow + aq + 8);
    } else { ra[0] = make_uint4(0, 0, 0, 0); ra[1] = make_uint4(0, 0, 0, 0); }
#pragma unroll
    for (int i = 0; i < 4; i++) rb[i] = *(const uint4*)(brow + bh + i * 8);
    *(uint4*)(sm + stoA) = ra[0]; *(uint4*)(sm + stoA + 8) = ra[1];
#pragma unroll
    for (int i = 0; i < 4; i++) *(uint4*)(sm + stoB + i * 8) = rb[i];
    __syncthreads();

#pragma unroll 1
    for (int c = 0; c < NCH; c++) {
        int buf = c & 1;
        if (c + 1 < NCH) {
            int c1 = c + 1;
            int kc = c1 & 7;
            int sA = (c1 < 16) ? 0 : 512;
            int sB = (c1 >= 8 && c1 < 16) ? 512 : 0;
            if (arow) {
                const __nv_bfloat16* ap = arow + sA + kc * 64 + aq;
                ra[0] = *(const uint4*)(ap); ra[1] = *(const uint4*)(ap + 8);
            }
            const __nv_bfloat16* bp = brow + sB + kc * 64 + bh;
#pragma unroll
            for (int i = 0; i < 4; i++) rb[i] = *(const uint4*)(bp + i * 8);
        }
        uint32_t baseA = smb + (uint32_t)(buf * FSTAGE * 2);
        hmma_chunk16(baseA, baseA + 64 * FP * 2, warpM, warpN, rA, kA, rB, kB, acc);
        if (c + 1 < NCH) {
            __nv_bfloat16* d = sm + ((c + 1) & 1) * FSTAGE;
            *(uint4*)(d + stoA) = ra[0]; *(uint4*)(d + stoA + 8) = ra[1];
#pragma unroll
            for (int i = 0; i < 4; i++) *(uint4*)(d + stoB + i * 8) = rb[i];
        }
        __syncthreads();
    }

#pragma unroll
    for (int mt = 0; mt < 2; mt++) {
#pragma unroll
        for (int rr = 0; rr < 2; rr++) {
            int row = warpM + mt * 16 + g + rr * 8;
            int er = es[row];
            if (er < 0) continue;
            __nv_bfloat16* hp = g_h3 + (size_t)er * 4096;
#pragma unroll
            for (int nt = 0; nt < 4; nt++) {
                int col = nb + warpN + nt * 8 + t2;
                float v0 = gelu_f(acc[mt][nt][rr * 2 + 0] + b1[(size_t)n * Hd + col]);
                float v1 = gelu_f(acc[mt][nt][rr * 2 + 1] + b1[(size_t)n * Hd + col + 1]);
                __nv_bfloat16 h0 = __float2bfloat16(v0), h1 = __float2bfloat16(v1);
                __nv_bfloat16 l0 = __float2bfloat16(v0 - __bfloat162float(h0));
                __nv_bfloat16 l1 = __float2bfloat16(v1 - __bfloat162float(h1));
                uint32_t hp2 = (uint32_t)__bfloat16_as_ushort(h0) | ((uint32_t)__bfloat16_as_ushort(h1) << 16);
                uint32_t lp2 = (uint32_t)__bfloat16_as_ushort(l0) | ((uint32_t)__bfloat16_as_ushort(l1) << 16);
                *(uint32_t*)(hp + col) = hp2;
                *(uint32_t*)(hp + 2048 + col) = lp2;
            }
        }
    }
}

// ---------------- FFN pass 2: out = h @ W2 + b2, M=64 tiles ----------------
__global__ __launch_bounds__(256, 2)
void ffn2_mma_k(const float* __restrict__ b2) {
    int n = blockIdx.z, mt0 = blockIdx.y, nb = blockIdx.x * 128;
    int cnt = g_cnt[n];
    int base = mt0 * 64;
    if (base >= cnt) return;

    extern __shared__ __align__(16) __nv_bfloat16 sm[];
    __shared__ int es[64];
    int tid = threadIdx.x, wid = tid >> 5, lane = tid & 31;
    if (tid < 64) es[tid] = (base + tid < cnt) ? g_list[n * T + base + tid] : -1;
    __syncthreads();

    int arw = tid >> 2, aq = (tid & 3) * 16;
    int e_row = es[arw];
    const __nv_bfloat16* arow = (e_row >= 0) ? (g_h3 + (size_t)e_row * 4096) : 0;
    int stoA = arw * FP + aq;
    int brw = tid >> 1, bh = (tid & 1) * 32;
    const __nv_bfloat16* brow = g_W23 + ((size_t)n * Dm + nb + brw) * 4096;
    int stoB = 64 * FP + brw * FP + bh;

    float acc[2][4][4];
#pragma unroll
    for (int i = 0; i < 2; i++)
#pragma unroll
        for (int j = 0; j < 4; j++)
#pragma unroll
            for (int k = 0; k < 4; k++) acc[i][j][k] = 0.f;

    int g = lane >> 2, t2 = (lane & 3) * 2;
    int warpM = (wid >> 2) * 32, warpN = (wid & 3) * 32;
    int rA = ((lane >> 3) & 1) * 8 + (lane & 7);
    int kA = (lane >> 4) * 8;
    int rB = (lane & 7) + (lane >> 4) * 8;
    int kB = ((lane >> 3) & 1) * 8;
    uint32_t smb = cvta_smem(sm);

    const int NCH = 96;
    uint4 ra[2], rb[4];
    if (arow) {
        ra[0] = *(const uint4*)(arow + aq);
        ra[1] = *(const uint4*)(arow + aq + 8);
    } else { ra[0] = make_uint4(0, 0, 0, 0); ra[1] = make_uint4(0, 0, 0, 0); }
#pragma unroll
    for (int i = 0; i < 4; i++) rb[i] = *(const uint4*)(brow + bh + i * 8);
    *(uint4*)(sm + stoA) = ra[0]; *(uint4*)(sm + stoA + 8) = ra[1];
#pragma unroll
    for (int i = 0; i < 4; i++) *(uint4*)(sm + stoB + i * 8) = rb[i];
    __syncthreads();

#pragma unroll 1
    for (int c = 0; c < NCH; c++) {
        int buf = c & 1;
        if (c + 1 < NCH) {
            int c1 = c + 1;
            int kc = c1 & 31;
            int sA = (c1 < 64) ? 0 : 2048;
            int sB = (c1 >= 32 && c1 < 64) ? 2048 : 0;
            if (arow) {
                const __nv_bfloat16* ap = arow + sA + kc * 64 + aq;
                ra[0] = *(const uint4*)(ap); ra[1] = *(const uint4*)(ap + 8);
            }
            const __nv_bfloat16* bp = brow + sB + kc * 64 + bh;
#pragma unroll
            for (int i = 0; i < 4; i++) rb[i] = *(const uint4*)(bp + i * 8);
        }
        uint32_t baseA = smb + (uint32_t)(buf * FSTAGE * 2);
        hmma_chunk16(baseA, baseA + 64 * FP * 2, warpM, warpN, rA, kA, rB, kB, acc);
        if (c + 1 < NCH) {
            __nv_bfloat16* d = sm + ((c + 1) & 1) * FSTAGE;
            *(uint4*)(d + stoA) = ra[0]; *(uint4*)(d + stoA + 8) = ra[1];
#pragma unroll
            for (int i = 0; i < 4; i++) *(uint4*)(d + stoB + i * 8) = rb[i];
        }
        __syncthreads();
    }

#pragma unroll
    for (int mt = 0; mt < 2; mt++) {
#pragma unroll
        for (int rr = 0; rr < 2; rr++) {
            int row = warpM + mt * 16 + g + rr * 8;
            int er = es[row];
            if (er < 0) continue;
            float* op = g_pairs + (size_t)er * Dm;
#pragma unroll
            for (int nt = 0; nt < 4; nt++) {
                int col = nb + warpN + nt * 8 + t2;
                float2 o;
                o.x = acc[mt][nt][rr * 2 + 0] + b2[(size_t)n * Dm + col];
                o.y = acc[mt][nt][rr * 2 + 1] + b2[(size_t)n * Dm + col + 1];
                *(float2*)(op + col) = o;
            }
        }
    }
}

// ---------------- dense HMMA GEMM: C[M,Nc] = A @ W^T + bias (M=128 tiles) ----------------
__global__ __launch_bounds__(256)
void gemm_mma_k(const __nv_bfloat16* __restrict__ A3, const __nv_bfloat16* __restrict__ W3,
                const float* __restrict__ bias, float* __restrict__ C, int Nc, int Kd) {
    int nb = blockIdx.x * 128, mg = blockIdx.y * 128;
    extern __shared__ __align__(16) __nv_bfloat16 sm[];
    int tid = threadIdx.x, wid = tid >> 5, lane = tid & 31;

    int hr = tid >> 1, half = tid & 1;
    const __nv_bfloat16* arow = A3 + (size_t)(mg + hr) * 2 * Kd;
    const __nv_bfloat16* brow = W3 + (size_t)(nb + hr) * 2 * Kd;
    int sto = hr * FP + half * 32;

    float acc[4][4][4];
#pragma unroll
    for (int i = 0; i < 4; i++)
#pragma unroll
        for (int j = 0; j < 4; j++)
#pragma unroll
            for (int k = 0; k < 4; k++) acc[i][j][k] = 0.f;

    int g = lane >> 2, t2 = (lane & 3) * 2;
    int warpM = (wid >> 2) * 64, warpN = (wid & 3) * 32;
    int rA = ((lane >> 3) & 1) * 8 + (lane & 7);
    int kA = (lane >> 4) * 8;
    int rB = (lane & 7) + (lane >> 4) * 8;
    int kB = ((lane >> 3) & 1) * 8;
    uint32_t smb = cvta_smem(sm);

    int cpseg = Kd >> 6;
    int NCH = 3 * cpseg;
    uint4 ra[4], rb[4];
#pragma unroll
    for (int i = 0; i < 4; i++) {
        ra[i] = *(const uint4*)(arow + half * 32 + i * 8);
        rb[i] = *(const uint4*)(brow + half * 32 + i * 8);
    }
#pragma unroll
    for (int i = 0; i < 4; i++) {
        *(uint4*)(sm + sto + i * 8) = ra[i];
        *(uint4*)(sm + FTILE + sto + i * 8) = rb[i];
    }
    __syncthreads();

#pragma unroll 1
    for (int c = 0; c < NCH; c++) {
        int buf = c & 1;
        if (c + 1 < NCH) {
            int c1 = c + 1;
            int seg = c1 / cpseg;
            int kc = c1 - seg * cpseg;
            int sA = (seg == 2) ? Kd : 0;
            int sB = (seg == 1) ? Kd : 0;
            const __nv_bfloat16* ap = arow + sA + kc * 64 + half * 32;
            const __nv_bfloat16* bp = brow + sB + kc * 64 + half * 32;
#pragma unroll
            for (int i = 0; i < 4; i++) {
                ra[i] = *(const uint4*)(ap + i * 8);
                rb[i] = *(const uint4*)(bp + i * 8);
            }
        }
        uint32_t baseA = smb + (uint32_t)(buf * 2 * FTILE * 2);
        hmma_chunk(baseA, baseA + FTILE * 2, warpM, warpN, rA, kA, rB, kB, acc);
        if (c + 1 < NCH) {
            __nv_bfloat16* d = sm + ((c + 1) & 1) * 2 * FTILE;
#pragma unroll
            for (int i = 0; i < 4; i++) {
                *(uint4*)(d + sto + i * 8) = ra[i];
                *(uint4*)(d + FTILE + sto + i * 8) = rb[i];
            }
        }
        __syncthreads();
    }

#pragma unroll
    for (int mt = 0; mt < 4; mt++) {
#pragma unroll
        for (int rr = 0; rr < 2; rr++) {
            int row = mg + warpM + mt * 16 + g + rr * 8;
            float* op = C + (size_t)row * Nc;
#pragma unroll
            for (int nt = 0; nt < 4; nt++) {
                int col = nb + warpN + nt * 8 + t2;
                float2 o;
                o.x = acc[mt][nt][rr * 2 + 0] + bias[col];
                o.y = acc[mt][nt][rr * 2 + 1] + bias[col + 1];
                *(float2*)(op + col) = o;
            }
        }
    }
}

// ---------------- mean over k, fused bf16 split ----------------
__global__ void reduce3_k() {
    int id = blockIdx.x * 256 + threadIdx.x;
    if (id >= T * Dm / 4) return;
    int t = id >> 7, c4 = (id & 127) << 2;
    float4 s = make_float4(0.f, 0.f, 0.f, 0.f);
#pragma unroll
    for (int k2 = 0; k2 < 4; k2++) {
        float4 v = *(const float4*)&g_pairs[(size_t)(t * 4 + k2) * Dm + c4];
        s.x += v.x; s.y += v.y; s.z += v.z; s.w += v.w;
    }
    s.x *= 0.25f; s.y *= 0.25f; s.z *= 0.25f; s.w *= 0.25f;
    *(float4*)&g_nout[(size_t)t * Dm + c4] = s;
    float vv[4] = {s.x, s.y, s.z, s.w};
    ushort hi4[4], lo4[4];
#pragma unroll
    for (int i = 0; i < 4; i++) {
        __nv_bfloat16 hi = __float2bfloat16(vv[i]);
        __nv_bfloat16 lo = __float2bfloat16(vv[i] - __bfloat162float(hi));
        hi4[i] = __bfloat16_as_ushort(hi);
        lo4[i] = __bfloat16_as_ushort(lo);
    }
    *(uint2*)&g_nout3[(size_t)t * 1024 + c4] = *(uint2*)hi4;
    *(uint2*)&g_nout3[(size_t)t * 1024 + 512 + c4] = *(uint2*)lo4;
}

// ---------------- attention (flash, q-tile 64), bf16-split epilogue ----------------
__global__ __launch_bounds__(256)
void attn2_k() {
    extern __shared__ float smf[];
    float* Qs  = smf;
    float* KPs = smf + AT_REG;
    float* Vs  = smf + 2 * AT_REG;
    int q0 = blockIdx.x * 64, h = blockIdx.y, b = blockIdx.z;
    int tid = threadIdx.x, lane = tid & 31, w = tid >> 5;
    int qr = w * 8;
    {
        int r = tid >> 2, c0 = (tid & 3) * 16;
        const float* qp = g_qkv + (size_t)(b * Sd + q0 + r) * D3 + h * HDd + c0;
#pragma unroll
        for (int i = 0; i < 4; i++) {
            float4 v = *(const float4*)(qp + i * 4);
            Qs[(c0 + i * 4 + 0) * AT_PAD + r] = v.x * 0.125f;
            Qs[(c0 + i * 4 + 1) * AT_PAD + r] = v.y * 0.125f;
            Qs[(c0 + i * 4 + 2) * AT_PAD + r] = v.z * 0.125f;
            Qs[(c0 + i * 4 + 3) * AT_PAD + r] = v.w * 0.125f;
        }
    }
    float m[8], l[8], o0[8], o1[8];
#pragma unroll
    for (int r = 0; r < 8; r++) { m[r] = -1e30f; l[r] = 0.f; o0[r] = 0.f; o1[r] = 0.f; }
#pragma unroll 1
    for (int j0 = 0; j0 < Sd; j0 += 64) {
        __syncthreads();
        {
            int r = tid >> 2, c0 = (tid & 3) * 16;
            const float* kp = g_qkv + (size_t)(b * Sd + j0 + r) * D3 + Dm + h * HDd + c0;
            const float* vp = kp + Dm;
#pragma unroll
            for (int i = 0; i < 4; i++) {
                float4 kv = *(const float4*)(kp + i * 4);
                KPs[(c0 + i * 4 + 0) * AT_PAD + r] = kv.x;
                KPs[(c0 + i * 4 + 1) * AT_PAD + r] = kv.y;
                KPs[(c0 + i * 4 + 2) * AT_PAD + r] = kv.z;
                KPs[(c0 + i * 4 + 3) * AT_PAD + r] = kv.w;
                float4 vv = *(const float4*)(vp + i * 4);
                Vs[(c0 + i * 4 + 0) * AT_PAD + r] = vv.x;
                Vs[(c0 + i * 4 + 1) * AT_PAD + r] = vv.y;
                Vs[(c0 + i * 4 + 2) * AT_PAD + r] = vv.z;
                Vs[(c0 + i * 4 + 3) * AT_PAD + r] = vv.w;
            }
        }
        __syncthreads();
        float s[8][2];
#pragma unroll
        for (int r = 0; r < 8; r++) { s[r][0] = 0.f; s[r][1] = 0.f; }
#pragma unroll 8
        for (int d = 0; d < 64; d++) {
            float4 qa = *(const float4*)&Qs[d * AT_PAD + qr];
            float4 qb = *(const float4*)&Qs[d * AT_PAD + qr + 4];
            float2 kk = *(const float2*)&KPs[d * AT_PAD + 2 * lane];
            s[0][0] += qa.x * kk.x; s[0][1] += qa.x * kk.y;
            s[1][0] += qa.y * kk.x; s[1][1] += qa.y * kk.y;
            s[2][0] += qa.z * kk.x; s[2][1] += qa.z * kk.y;
            s[3][0] += qa.w * kk.x; s[3][1] += qa.w * kk.y;
            s[4][0] += qb.x * kk.x; s[4][1] += qb.x * kk.y;
            s[5][0] += qb.y * kk.x; s[5][1] += qb.y * kk.y;
            s[6][0] += qb.z * kk.x; s[6][1] += qb.z * kk.y;
            s[7][0] += qb.w * kk.x; s[7][1] += qb.w * kk.y;
        }
#pragma unroll
        for (int r = 0; r < 8; r++) {
            float tmax = fmaxf(s[r][0], s[r][1]);
#pragma unroll
            for (int o = 16; o; o >>= 1) tmax = fmaxf(tmax, __shfl_xor_sync(0xffffffffu, tmax, o));
            float mn = fmaxf(m[r], tmax);
            float corr = __expf(m[r] - mn);
            float p0 = __expf(s[r][0] - mn);
            float p1 = __expf(s[r][1] - mn);
            float rs = p0 + p1;
#pragma unroll
            for (int o = 16; o; o >>= 1) rs += __shfl_xor_sync(0xffffffffu, rs, o);
            l[r] = l[r] * corr + rs;
            m[r] = mn;
            o0[r] *= corr; o1[r] *= corr;
            s[r][0] = p0; s[r][1] = p1;
        }
        __syncthreads();
#pragma unroll
        for (int r = 0; r < 8; r++)
            *(float2*)&KPs[(qr + r) * AT_PAD + 2 * lane] = make_float2(s[r][0], s[r][1]);
        __syncthreads();
        const float* vr0 = &Vs[lane * AT_PAD];
        const float* vr1 = &Vs[(lane + 32) * AT_PAD];
#pragma unroll 4
        for (int k4 = 0; k4 < 16; k4++) {
            float4 v0 = *(const float4*)(vr0 + 4 * k4);
            float4 v1 = *(const float4*)(vr1 + 4 * k4);
#pragma unroll
            for (int r = 0; r < 8; r++) {
                float4 p = *(const float4*)&KPs[(qr + r) * AT_PAD + 4 * k4];
                o0[r] += p.x * v0.x + p.y * v0.y + p.z * v0.z + p.w * v0.w;
                o1[r] += p.x * v1.x + p.y * v1.y + p.z * v1.z + p.w * v1.w;
            }
        }
    }
#pragma unroll
    for (int r = 0; r < 8; r++) {
        float inv = 1.0f / l[r];
        int t = b * Sd + q0 + qr + r;
        float va = o0[r] * inv, vb = o1[r] * inv;
        __nv_bfloat16 ha = __float2bfloat16(va);
        __nv_bfloat16 la = __float2bfloat16(va - __bfloat162float(ha));
        __nv_bfloat16 hb = __float2bfloat16(vb);
        __nv_bfloat16 lb = __float2bfloat16(vb - __bfloat162float(hb));
        __nv_bfloat16* dp = g_attno3 + (size_t)t * 1024 + h * HDd + lane;
        dp[0] = ha; dp[32] = hb;
        dp[512] = la; dp[544] = lb;
    }
}

// ---------------- fused dual LN ----------------
__global__ void ln_k(const float* __restrict__ x,
                     const float* __restrict__ ln1w, const float* __restrict__ ln1b,
                     const float* __restrict__ ln2w, const float* __restrict__ ln2b,
                     float* __restrict__ out) {
    int t = blockIdx.x, tid = threadIdx.x;
    __shared__ float r1[8], r2[8];
    __shared__ float mu_s, rs_s;
    size_t off = (size_t)t * Dm;
    float a0 = x[off + tid] + g_attnout[off + tid];
    float a1 = x[off + 256 + tid] + g_attnout[off + 256 + tid];
    float s = a0 + a1, ss = a0 * a0 + a1 * a1;
#pragma unroll
    for (int o = 16; o; o >>= 1) {
        s += __shfl_xor_sync(0xffffffffu, s, o);
        ss += __shfl_xor_sync(0xffffffffu, ss, o);
    }
    if ((tid & 31) == 0) { r1[tid >> 5] = s; r2[tid >> 5] = ss; }
    __syncthreads();
    if (tid == 0) {
        float S = 0.f, SS = 0.f;
#pragma unroll
        for (int i = 0; i < 8; i++) { S += r1[i]; SS += r2[i]; }
        float mu = S * (1.0f / 512.0f);
        mu_s = mu;
        rs_s = rsqrtf(SS * (1.0f / 512.0f) - mu * mu + 1e-5f);
    }
    __syncthreads();
    float mu = mu_s, rs = rs_s;
    float z0 = (a0 - mu) * rs * ln1w[tid] + ln1b[tid] + g_nout[off + tid];
    float z1 = (a1 - mu) * rs * ln1w[256 + tid] + ln1b[256 + tid] + g_nout[off + 256 + tid];
    s = z0 + z1; ss = z0 * z0 + z1 * z1;
#pragma unroll
    for (int o = 16; o; o >>= 1) {
        s += __shfl_xor_sync(0xffffffffu, s, o);
        ss += __shfl_xor_sync(0xffffffffu, ss, o);
    }
    __syncthreads();
    if ((tid & 31) == 0) { r1[tid >> 5] = s; r2[tid >> 5] = ss; }
    __syncthreads();
    if (tid == 0) {
        float S = 0.f, SS = 0.f;
#pragma unroll
        for (int i = 0; i < 8; i++) { S += r1[i]; SS += r2[i]; }
        float mu2 = S * (1.0f / 512.0f);
        mu_s = mu2;
        rs_s = rsqrtf(SS * (1.0f / 512.0f) - mu2 * mu2 + 1e-5f);
    }
    __syncthreads();
    mu = mu_s; rs = rs_s;
    out[off + tid] = (z0 - mu) * rs * ln2w[tid] + ln2b[tid];
    out[off + 256 + tid] = (z1 - mu) * rs * ln2w[256 + tid] + ln2b[256 + tid];
}

// ---------------- launcher ----------------
extern "C" void kernel_launch(void* const* d_in, const int* in_sizes, int n_in,
                              void* d_out, int out_size) {
    const float* x    = (const float*)d_in[0];
    const float* Wr   = (const float*)d_in[1];
    const float* br   = (const float*)d_in[2];
    const float* W1   = (const float*)d_in[3];
    const float* b1   = (const float*)d_in[4];
    const float* W2   = (const float*)d_in[5];
    const float* b2   = (const float*)d_in[6];
    const float* Wqkv = (const float*)d_in[7];
    const float* bqkv = (const float*)d_in[8];
    const float* Wo   = (const float*)d_in[9];
    const float* bo   = (const float*)d_in[10];
    const float* ln1w = (const float*)d_in[11];
    const float* ln1b = (const float*)d_in[12];
    const float* ln2w = (const float*)d_in[13];
    const float* ln2b = (const float*)d_in[14];
    float* out = (float*)d_out;

    float *p_qkv, *p_attnout;
    __nv_bfloat16 *p_x3, *p_w13, *p_w23, *p_wqkv3, *p_wo3, *p_nout3, *p_attno3;
    cudaGetSymbolAddress((void**)&p_qkv, g_qkv);
    cudaGetSymbolAddress((void**)&p_attnout, g_attnout);
    cudaGetSymbolAddress((void**)&p_x3, g_x3);
    cudaGetSymbolAddress((void**)&p_w13, g_W13);
    cudaGetSymbolAddress((void**)&p_w23, g_W23);
    cudaGetSymbolAddress((void**)&p_wqkv3, g_Wqkv3);
    cudaGetSymbolAddress((void**)&p_wo3, g_Wo3);
    cudaGetSymbolAddress((void**)&p_nout3, g_nout3);
    cudaGetSymbolAddress((void**)&p_attno3, g_attno3);

    static int init_done = 0;
    static cudaStream_t sA, sB;
    static cudaEvent_t evRoot, evA, evB, evQ, evO;
    if (!init_done) {
        cudaFuncSetAttribute(attn2_k, cudaFuncAttributeMaxDynamicSharedMemorySize, SMEM_ATTN);
        cudaFuncSetAttribute(ffn1_mma_k, cudaFuncAttributeMaxDynamicSharedMemorySize, SMEM_FFN);
        cudaFuncSetAttribute(ffn2_mma_k, cudaFuncAttributeMaxDynamicSharedMemorySize, SMEM_FFN);
        cudaFuncSetAttribute(gemm_mma_k, cudaFuncAttributeMaxDynamicSharedMemorySize, SMEM_GEMM);
        cudaStreamCreateWithFlags(&sA, cudaStreamNonBlocking);
        cudaStreamCreateWithFlags(&sB, cudaStreamNonBlocking);
        cudaEventCreateWithFlags(&evRoot, cudaEventDisableTiming);
        cudaEventCreateWithFlags(&evA, cudaEventDisableTiming);
        cudaEventCreateWithFlags(&evB, cudaEventDisableTiming);
        cudaEventCreateWithFlags(&evQ, cudaEventDisableTiming);
        cudaEventCreateWithFlags(&evO, cudaEventDisableTiming);
        init_done = 1;
    }

    // fork point
    cudaEventRecord(evRoot, 0);
    cudaStreamWaitEvent(sA, evRoot, 0);
    cudaStreamWaitEvent(sB, evRoot, 0);

    // stream A: inputs needed by ffn1
    conv3_k<<<T * Dm / 256, 256, 0, sA>>>(x, p_x3);
    convw_k<<<dim3(Hd / 32, Dm / 32, Np), dim3(32, 8), 0, sA>>>(W1, p_w13, Dm, Hd);
    cudaEventRecord(evA, sA);

    // stream B: inputs needed by ffn2 / projections
    convw_k<<<dim3(Dm / 32, Hd / 32, Np), dim3(32, 8), 0, sB>>>(W2, p_w23, Hd, Dm);
    cudaEventRecord(evB, sB);
    convwd_k<<<D3 * Dm / 256, 256, 0, sB>>>(Wqkv, p_wqkv3, Dm);
    cudaEventRecord(evQ, sB);
    convwd_k<<<Dm * Dm / 256, 256, 0, sB>>>(Wo, p_wo3, Dm);
    cudaEventRecord(evO, sB);

    // main stream: router + list build (overlaps conversions)
    router_k<<<T / 8, 256>>>(x, Wr, br);
    zero_k<<<1, 32>>>();
    build_k<<<(T * Kk + 255) / 256, 256>>>();

    // sparse FFN on tensor cores (M=64 tiles: minimal ragged-tile waste)
    cudaStreamWaitEvent(0, evA, 0);
    ffn1_mma_k<<<dim3(16, 32, 32), 256, SMEM_FFN>>>(b1);
    cudaStreamWaitEvent(0, evB, 0);
    ffn2_mma_k<<<dim3(4, 32, 32), 256, SMEM_FFN>>>(b2);
    reduce3_k<<<(T * Dm / 4 + 255) / 256, 256>>>();

    // attention (HMMA projections + fp32 flash core)
    cudaStreamWaitEvent(0, evQ, 0);
    gemm_mma_k<<<dim3(D3 / 128, T / 128), 256, SMEM_GEMM>>>(p_nout3, p_wqkv3, bqkv, p_qkv, D3, Dm);
    attn2_k<<<dim3(Sd / 64, NHd, Bd), 256, SMEM_ATTN>>>();
    cudaStreamWaitEvent(0, evO, 0);
    gemm_mma_k<<<dim3(Dm / 128, T / 128), 256, SMEM_GEMM>>>(p_attno3, p_wo3, bo, p_attnout, Dm, Dm);

    // epilogue
    ln_k<<<T, 256>>>(x, ln1w, ln1b, ln2w, ln2b, out);
}

// round 12
// speedup vs baseline: 1.2051x; 1.1740x over previous
#include <cuda_runtime.h>
#include <cuda_fp16.h>
#include <math.h>
#include <stdint.h>

#define T   2048
#define Dm  512
#define Np  32
#define Hd  2048
#define Kk  4
#define NHd 8
#define HDd 64
#define Sd  1024
#define Bd  2
#define D3  1536

#define AT_PAD 68
#define AT_REG (64 * AT_PAD)
#define SMEM_ATTN (3 * AT_REG * 4)

// HMMA tile constants: pitch 72 fp16 per row
#define FP 72
#define FTILE (128 * FP)                 // fp16 units per 128-row tile (dense gemm)
#define SMEM_GEMM (4 * FTILE * 2)        // dense gemm: 2 bufs x (A128 + B128)
#define FSTAGE (192 * FP)                // ffn stage: A(64 rows) + B(128 rows)
#define SMEM_FFN (2 * FSTAGE * 2)        // 2 stages

__device__ int   g_idx[T * Kk];
__device__ int   g_cnt[Np];
__device__ int   g_list[Np * T];
__device__ float g_pairs[T * Kk * Dm];
__device__ float g_nout[T * Dm];
__device__ float g_qkv[T * D3];
__device__ float g_attnout[T * Dm];
__device__ __half g_x2[T * Dm];
__device__ __half g_nout2[T * Dm];
__device__ __half g_attno2[T * Dm];
__device__ __half g_W12[(size_t)Np * Hd * Dm];   // [n][h][k]
__device__ __half g_W22[(size_t)Np * Dm * Hd];   // [n][d][k]
__device__ __half g_Wqkv2[(size_t)D3 * Dm];
__device__ __half g_Wo2[(size_t)Dm * Dm];
__device__ __half g_h2[(size_t)T * Kk * Hd];     // [pair][h]

__device__ __forceinline__ float gelu_f(float v) {
    float u = 0.7978845608028654f * (v + 0.044715f * v * v * v);
    return 0.5f * v * (1.0f + tanhf(u));
}

__device__ __forceinline__ uint32_t cvta_smem(const void* p) {
    uint32_t a;
    asm("{ .reg .u64 t; cvta.to.shared.u64 t, %1; cvt.u32.u64 %0, t; }" : "=r"(a) : "l"(p));
    return a;
}

__device__ __forceinline__ void mma_f16(float c[4], uint32_t a0, uint32_t a1,
                                        uint32_t a2, uint32_t a3,
                                        uint32_t b0, uint32_t b1) {
    asm volatile(
        "mma.sync.aligned.m16n8k16.row.col.f32.f16.f16.f32 "
        "{%0,%1,%2,%3}, {%4,%5,%6,%7}, {%8,%9}, {%0,%1,%2,%3};"
        : "+f"(c[0]), "+f"(c[1]), "+f"(c[2]), "+f"(c[3])
        : "r"(a0), "r"(a1), "r"(a2), "r"(a3), "r"(b0), "r"(b1));
}

__device__ __forceinline__ void ldsm4(uint32_t r[4], uint32_t a) {
    asm volatile("ldmatrix.sync.aligned.m8n8.x4.shared.b16 {%0,%1,%2,%3}, [%4];"
        : "=r"(r[0]), "=r"(r[1]), "=r"(r[2]), "=r"(r[3]) : "r"(a));
}

// ---------------- router / list ----------------
__global__ void router_k(const float* __restrict__ x, const float* __restrict__ Wr,
                         const float* __restrict__ br) {
    int warp = threadIdx.x >> 5, lane = threadIdx.x & 31;
    int t = blockIdx.x * 8 + warp;
    const float* xp = x + (size_t)t * Dm + lane * 16;
    float4 xv[4];
#pragma unroll
    for (int i = 0; i < 4; i++) xv[i] = *(const float4*)(xp + i * 4);
    float lg[32];
#pragma unroll 1
    for (int n = 0; n < 32; n++) {
        const float* wp = Wr + n * Dm + lane * 16;
        float acc = 0.f;
#pragma unroll
        for (int i = 0; i < 4; i++) {
            float4 w = *(const float4*)(wp + i * 4);
            acc += xv[i].x * w.x + xv[i].y * w.y + xv[i].z * w.z + xv[i].w * w.w;
        }
#pragma unroll
        for (int o = 16; o; o >>= 1) acc += __shfl_xor_sync(0xffffffffu, acc, o);
        lg[n] = acc + br[n];
    }
    if (lane == 0) {
        unsigned used = 0;
        for (int k2 = 0; k2 < 4; k2++) {
            float best = -1e30f; int bi = 0;
            for (int n = 0; n < 32; n++)
                if (!((used >> n) & 1u) && lg[n] > best) { best = lg[n]; bi = n; }
            used |= 1u << bi;
            g_idx[t * 4 + k2] = bi;
        }
    }
}
__global__ void zero_k() { if (threadIdx.x < Np) g_cnt[threadIdx.x] = 0; }
__global__ void build_k() {
    int e = blockIdx.x * 256 + threadIdx.x;
    if (e >= T * Kk) return;
    int n = g_idx[e];
    int pos = atomicAdd(&g_cnt[n], 1);
    g_list[n * T + pos] = e;
}

// ---------------- fp16 conversions ----------------
__global__ void conv2_k(const float* __restrict__ src, __half* __restrict__ dst, int total) {
    int i = blockIdx.x * 256 + threadIdx.x;
    if (i < total) dst[i] = __float2half(src[i]);
}
// W[n][Kd][Nd] fp32 -> W2[n][Nd][Kd] fp16 (transposing)
__global__ void convw2_k(const float* __restrict__ W, __half* __restrict__ W2h,
                         int Kd, int Nd) {
    __shared__ float tile[32][33];
    int n = blockIdx.z, k0 = blockIdx.y * 32, c0 = blockIdx.x * 32;
    const float* Wn = W + (size_t)n * Kd * Nd;
#pragma unroll
    for (int i = 0; i < 32; i += 8)
        tile[threadIdx.y + i][threadIdx.x] = Wn[(size_t)(k0 + threadIdx.y + i) * Nd + c0 + threadIdx.x];
    __syncthreads();
    __half* Wo = W2h + (size_t)n * Nd * Kd;
#pragma unroll
    for (int i = 0; i < 32; i += 8)
        Wo[(size_t)(c0 + threadIdx.y + i) * Kd + k0 + threadIdx.x] =
            __float2half(tile[threadIdx.x][threadIdx.y + i]);
}

// ---------------- HMMA chunk: warp tile 64x32 (dense gemm) ----------------
__device__ __forceinline__ void hmma_chunk(uint32_t smb_A, uint32_t smb_B,
                                           int warpM, int warpN, int rA, int kA,
                                           int rB, int kB, float acc[4][4][4]) {
#pragma unroll
    for (int kk = 0; kk < 4; kk++) {
        uint32_t af[4][4], bf[4][2];
#pragma unroll
        for (int mt = 0; mt < 4; mt++)
            ldsm4(af[mt], smb_A + (uint32_t)(((warpM + mt * 16 + rA) * FP + kk * 16 + kA) * 2));
#pragma unroll
        for (int nt2 = 0; nt2 < 2; nt2++) {
            uint32_t treg[4];
            ldsm4(treg, smb_B + (uint32_t)(((warpN + nt2 * 16 + rB) * FP + kk * 16 + kB) * 2));
            bf[2 * nt2][0] = treg[0]; bf[2 * nt2][1] = treg[1];
            bf[2 * nt2 + 1][0] = treg[2]; bf[2 * nt2 + 1][1] = treg[3];
        }
#pragma unroll
        for (int mt = 0; mt < 4; mt++)
#pragma unroll
            for (int nt = 0; nt < 4; nt++)
                mma_f16(acc[mt][nt], af[mt][0], af[mt][1], af[mt][2], af[mt][3],
                        bf[nt][0], bf[nt][1]);
    }
}

// ---------------- HMMA chunk: warp tile 32x32 (ffn, M=64 tiles) ----------------
__device__ __forceinline__ void hmma_chunk16(uint32_t smb_A, uint32_t smb_B,
                                             int warpM, int warpN, int rA, int kA,
                                             int rB, int kB, float acc[2][4][4]) {
#pragma unroll
    for (int kk = 0; kk < 4; kk++) {
        uint32_t af[2][4], bf[4][2];
#pragma unroll
        for (int mt = 0; mt < 2; mt++)
            ldsm4(af[mt], smb_A + (uint32_t)(((warpM + mt * 16 + rA) * FP + kk * 16 + kA) * 2));
#pragma unroll
        for (int nt2 = 0; nt2 < 2; nt2++) {
            uint32_t treg[4];
            ldsm4(treg, smb_B + (uint32_t)(((warpN + nt2 * 16 + rB) * FP + kk * 16 + kB) * 2));
            bf[2 * nt2][0] = treg[0]; bf[2 * nt2][1] = treg[1];
            bf[2 * nt2 + 1][0] = treg[2]; bf[2 * nt2 + 1][1] = treg[3];
        }
#pragma unroll
        for (int mt = 0; mt < 2; mt++)
#pragma unroll
            for (int nt = 0; nt < 4; nt++)
                mma_f16(acc[mt][nt], af[mt][0], af[mt][1], af[mt][2], af[mt][3],
                        bf[nt][0], bf[nt][1]);
    }
}

// ---------------- FFN pass 1: h = gelu(x @ W1 + b1), M=64 tiles, K=512 ----------------
__global__ __launch_bounds__(256, 2)
void ffn1_mma_k(const float* __restrict__ b1) {
    int n = blockIdx.z, mt0 = blockIdx.y, nb = blockIdx.x * 128;
    int cnt = g_cnt[n];
    int base = mt0 * 64;
    if (base >= cnt) return;

    extern __shared__ __align__(16) __half sm[];
    __shared__ int es[64];
    int tid = threadIdx.x, wid = tid >> 5, lane = tid & 31;
    if (tid < 64) es[tid] = (base + tid < cnt) ? g_list[n * T + base + tid] : -1;
    __syncthreads();

    int arw = tid >> 2, aq = (tid & 3) * 16;
    int e_row = es[arw];
    const __half* arow = (e_row >= 0) ? (g_x2 + (size_t)(e_row >> 2) * Dm) : 0;
    int stoA = arw * FP + aq;
    int brw = tid >> 1, bh = (tid & 1) * 32;
    const __half* brow = g_W12 + ((size_t)n * Hd + nb + brw) * Dm;
    int stoB = 64 * FP + brw * FP + bh;

    float acc[2][4][4];
#pragma unroll
    for (int i = 0; i < 2; i++)
#pragma unroll
        for (int j = 0; j < 4; j++)
#pragma unroll
            for (int k = 0; k < 4; k++) acc[i][j][k] = 0.f;

    int g = lane >> 2, t2 = (lane & 3) * 2;
    int warpM = (wid >> 2) * 32, warpN = (wid & 3) * 32;
    int rA = ((lane >> 3) & 1) * 8 + (lane & 7);
    int kA = (lane >> 4) * 8;
    int rB = (lane & 7) + (lane >> 4) * 8;
    int kB = ((lane >> 3) & 1) * 8;
    uint32_t smb = cvta_smem(sm);

    const int NCH = 8;
    uint4 ra[2], rb[4];
    if (arow) {
        ra[0] = *(const uint4*)(arow + aq);
        ra[1] = *(const uint4*)(arow + aq + 8);
    } else { ra[0] = make_uint4(0, 0, 0, 0); ra[1] = make_uint4(0, 0, 0, 0); }
#pragma unroll
    for (int i = 0; i < 4; i++) rb[i] = *(const uint4*)(brow + bh + i * 8);
    *(uint4*)(sm + stoA) = ra[0]; *(uint4*)(sm + stoA + 8) = ra[1];
#pragma unroll
    for (int i = 0; i < 4; i++) *(uint4*)(sm + stoB + i * 8) = rb[i];
    __syncthreads();

#pragma unroll 1
    for (int c = 0; c < NCH; c++) {
        int buf = c & 1;
        if (c + 1 < NCH) {
            int ko = (c + 1) * 64;
            if (arow) {
                const __half* ap = arow + ko + aq;
                ra[0] = *(const uint4*)(ap); ra[1] = *(const uint4*)(ap + 8);
            }
            const __half* bp = brow + ko + bh;
#pragma unroll
            for (int i = 0; i < 4; i++) rb[i] = *(const uint4*)(bp + i * 8);
        }
        uint32_t baseA = smb + (uint32_t)(buf * FSTAGE * 2);
        hmma_chunk16(baseA, baseA + 64 * FP * 2, warpM, warpN, rA, kA, rB, kB, acc);
        if (c + 1 < NCH) {
            __half* d = sm + ((c + 1) & 1) * FSTAGE;
            *(uint4*)(d + stoA) = ra[0]; *(uint4*)(d + stoA + 8) = ra[1];
#pragma unroll
            for (int i = 0; i < 4; i++) *(uint4*)(d + stoB + i * 8) = rb[i];
        }
        __syncthreads();
    }

#pragma unroll
    for (int mt = 0; mt < 2; mt++) {
#pragma unroll
        for (int rr = 0; rr < 2; rr++) {
            int row = warpM + mt * 16 + g + rr * 8;
            int er = es[row];
            if (er < 0) continue;
            __half* hp = g_h2 + (size_t)er * Hd;
#pragma unroll
            for (int nt = 0; nt < 4; nt++) {
                int col = nb + warpN + nt * 8 + t2;
                float v0 = gelu_f(acc[mt][nt][rr * 2 + 0] + b1[(size_t)n * Hd + col]);
                float v1 = gelu_f(acc[mt][nt][rr * 2 + 1] + b1[(size_t)n * Hd + col + 1]);
                __half2 hv = __floats2half2_rn(v0, v1);
                *(__half2*)(hp + col) = hv;
            }
        }
    }
}

// ---------------- FFN pass 2: out = h @ W2 + b2, M=64 tiles, K=2048 ----------------
__global__ __launch_bounds__(256, 2)
void ffn2_mma_k(const float* __restrict__ b2) {
    int n = blockIdx.z, mt0 = blockIdx.y, nb = blockIdx.x * 128;
    int cnt = g_cnt[n];
    int base = mt0 * 64;
    if (base >= cnt) return;

    extern __shared__ __align__(16) __half sm[];
    __shared__ int es[64];
    int tid = threadIdx.x, wid = tid >> 5, lane = tid & 31;
    if (tid < 64) es[tid] = (base + tid < cnt) ? g_list[n * T + base + tid] : -1;
    __syncthreads();

    int arw = tid >> 2, aq = (tid & 3) * 16;
    int e_row = es[arw];
    const __half* arow = (e_row >= 0) ? (g_h2 + (size_t)e_row * Hd) : 0;
    int stoA = arw * FP + aq;
    int brw = tid >> 1, bh = (tid & 1) * 32;
    const __half* brow = g_W22 + ((size_t)n * Dm + nb + brw) * Hd;
    int stoB = 64 * FP + brw * FP + bh;

    float acc[2][4][4];
#pragma unroll
    for (int i = 0; i < 2; i++)
#pragma unroll
        for (int j = 0; j < 4; j++)
#pragma unroll
            for (int k = 0; k < 4; k++) acc[i][j][k] = 0.f;

    int g = lane >> 2, t2 = (lane & 3) * 2;
    int warpM = (wid >> 2) * 32, warpN = (wid & 3) * 32;
    int rA = ((lane >> 3) & 1) * 8 + (lane & 7);
    int kA = (lane >> 4) * 8;
    int rB = (lane & 7) + (lane >> 4) * 8;
    int kB = ((lane >> 3) & 1) * 8;
    uint32_t smb = cvta_smem(sm);

    const int NCH = 32;
    uint4 ra[2], rb[4];
    if (arow) {
        ra[0] = *(const uint4*)(arow + aq);
        ra[1] = *(const uint4*)(arow + aq + 8);
    } else { ra[0] = make_uint4(0, 0, 0, 0); ra[1] = make_uint4(0, 0, 0, 0); }
#pragma unroll
    for (int i = 0; i < 4; i++) rb[i] = *(const uint4*)(brow + bh + i * 8);
    *(uint4*)(sm + stoA) = ra[0]; *(uint4*)(sm + stoA + 8) = ra[1];
#pragma unroll
    for (int i = 0; i < 4; i++) *(uint4*)(sm + stoB + i * 8) = rb[i];
    __syncthreads();

#pragma unroll 1
    for (int c = 0; c < NCH; c++) {
        int buf = c & 1;
        if (c + 1 < NCH) {
            int ko = (c + 1) * 64;
            if (arow) {
                const __half* ap = arow + ko + aq;
                ra[0] = *(const uint4*)(ap); ra[1] = *(const uint4*)(ap + 8);
            }
            const __half* bp = brow + ko + bh;
#pragma unroll
            for (int i = 0; i < 4; i++) rb[i] = *(const uint4*)(bp + i * 8);
        }
        uint32_t baseA = smb + (uint32_t)(buf * FSTAGE * 2);
        hmma_chunk16(baseA, baseA + 64 * FP * 2, warpM, warpN, rA, kA, rB, kB, acc);
        if (c + 1 < NCH) {
            __half* d = sm + ((c + 1) & 1) * FSTAGE;
            *(uint4*)(d + stoA) = ra[0]; *(uint4*)(d + stoA + 8) = ra[1];
#pragma unroll
            for (int i = 0; i < 4; i++) *(uint4*)(d + stoB + i * 8) = rb[i];
        }
        __syncthreads();
    }

#pragma unroll
    for (int mt = 0; mt < 2; mt++) {
#pragma unroll
        for (int rr = 0; rr < 2; rr++) {
            int row = warpM + mt * 16 + g + rr * 8;
            int er = es[row];
            if (er < 0) continue;
            float* op = g_pairs + (size_t)er * Dm;
#pragma unroll
            for (int nt = 0; nt < 4; nt++) {
                int col = nb + warpN + nt * 8 + t2;
                float2 o;
                o.x = acc[mt][nt][rr * 2 + 0] + b2[(size_t)n * Dm + col];
                o.y = acc[mt][nt][rr * 2 + 1] + b2[(size_t)n * Dm + col + 1];
                *(float2*)(op + col) = o;
            }
        }
    }
}

// ---------------- dense HMMA GEMM: C[M,Nc] = A @ W^T + bias (M=128, K=Kd) ----------------
__global__ __launch_bounds__(256)
void gemm_mma_k(const __half* __restrict__ A2, const __half* __restrict__ W2h,
                const float* __restrict__ bias, float* __restrict__ C, int Nc, int Kd) {
    int nb = blockIdx.x * 128, mg = blockIdx.y * 128;
    extern __shared__ __align__(16) __half sm[];
    int tid = threadIdx.x, wid = tid >> 5, lane = tid & 31;

    int hr = tid >> 1, half = tid & 1;
    const __half* arow = A2 + (size_t)(mg + hr) * Kd;
    const __half* brow = W2h + (size_t)(nb + hr) * Kd;
    int sto = hr * FP + half * 32;

    float acc[4][4][4];
#pragma unroll
    for (int i = 0; i < 4; i++)
#pragma unroll
        for (int j = 0; j < 4; j++)
#pragma unroll
            for (int k = 0; k < 4; k++) acc[i][j][k] = 0.f;

    int g = lane >> 2, t2 = (lane & 3) * 2;
    int warpM = (wid >> 2) * 64, warpN = (wid & 3) * 32;
    int rA = ((lane >> 3) & 1) * 8 + (lane & 7);
    int kA = (lane >> 4) * 8;
    int rB = (lane & 7) + (lane >> 4) * 8;
    int kB = ((lane >> 3) & 1) * 8;
    uint32_t smb = cvta_smem(sm);

    int NCH = Kd >> 6;
    uint4 ra[4], rb[4];
#pragma unroll
    for (int i = 0; i < 4; i++) {
        ra[i] = *(const uint4*)(arow + half * 32 + i * 8);
        rb[i] = *(const uint4*)(brow + half * 32 + i * 8);
    }
#pragma unroll
    for (int i = 0; i < 4; i++) {
        *(uint4*)(sm + sto + i * 8) = ra[i];
        *(uint4*)(sm + FTILE + sto + i * 8) = rb[i];
    }
    __syncthreads();

#pragma unroll 1
    for (int c = 0; c < NCH; c++) {
        int buf = c & 1;
        if (c + 1 < NCH) {
            int ko = (c + 1) * 64;
            const __half* ap = arow + ko + half * 32;
            const __half* bp = brow + ko + half * 32;
#pragma unroll
            for (int i = 0; i < 4; i++) {
                ra[i] = *(const uint4*)(ap + i * 8);
                rb[i] = *(const uint4*)(bp + i * 8);
            }
        }
        uint32_t baseA = smb + (uint32_t)(buf * 2 * FTILE * 2);
        hmma_chunk(baseA, baseA + FTILE * 2, warpM, warpN, rA, kA, rB, kB, acc);
        if (c + 1 < NCH) {
            __half* d = sm + ((c + 1) & 1) * 2 * FTILE;
#pragma unroll
            for (int i = 0; i < 4; i++) {
                *(uint4*)(d + sto + i * 8) = ra[i];
                *(uint4*)(d + FTILE + sto + i * 8) = rb[i];
            }
        }
        __syncthreads();
    }

#pragma unroll
    for (int mt = 0; mt < 4; mt++) {
#pragma unroll
        for (int rr = 0; rr < 2; rr++) {
            int row = mg + warpM + mt * 16 + g + rr * 8;
            float* op = C + (size_t)row * Nc;
#pragma unroll
            for (int nt = 0; nt < 4; nt++) {
                int col = nb + warpN + nt * 8 + t2;
                float2 o;
                o.x = acc[mt][nt][rr * 2 + 0] + bias[col];
                o.y = acc[mt][nt][rr * 2 + 1] + bias[col + 1];
                *(float2*)(op + col) = o;
            }
        }
    }
}

// ---------------- mean over k, fused fp16 cast ----------------
__global__ void reduce3_k() {
    int id = blockIdx.x * 256 + threadIdx.x;
    if (id >= T * Dm / 4) return;
    int t = id >> 7, c4 = (id & 127) << 2;
    float4 s = make_float4(0.f, 0.f, 0.f, 0.f);
#pragma unroll
    for (int k2 = 0; k2 < 4; k2++) {
        float4 v = *(const float4*)&g_pairs[(size_t)(t * 4 + k2) * Dm + c4];
        s.x += v.x; s.y += v.y; s.z += v.z; s.w += v.w;
    }
    s.x *= 0.25f; s.y *= 0.25f; s.z *= 0.25f; s.w *= 0.25f;
    *(float4*)&g_nout[(size_t)t * Dm + c4] = s;
    __half2 h0 = __floats2half2_rn(s.x, s.y);
    __half2 h1 = __floats2half2_rn(s.z, s.w);
    *(__half2*)&g_nout2[(size_t)t * Dm + c4] = h0;
    *(__half2*)&g_nout2[(size_t)t * Dm + c4 + 2] = h1;
}

// ---------------- attention (flash, q-tile 64), fp16 epilogue ----------------
__global__ __launch_bounds__(256)
void attn2_k() {
    extern __shared__ float smf[];
    float* Qs  = smf;
    float* KPs = smf + AT_REG;
    float* Vs  = smf + 2 * AT_REG;
    int q0 = blockIdx.x * 64, h = blockIdx.y, b = blockIdx.z;
    int tid = threadIdx.x, lane = tid & 31, w = tid >> 5;
    int qr = w * 8;
    {
        int r = tid >> 2, c0 = (tid & 3) * 16;
        const float* qp = g_qkv + (size_t)(b * Sd + q0 + r) * D3 + h * HDd + c0;
#pragma unroll
        for (int i = 0; i < 4; i++) {
            float4 v = *(const float4*)(qp + i * 4);
            Qs[(c0 + i * 4 + 0) * AT_PAD + r] = v.x * 0.125f;
            Qs[(c0 + i * 4 + 1) * AT_PAD + r] = v.y * 0.125f;
            Qs[(c0 + i * 4 + 2) * AT_PAD + r] = v.z * 0.125f;
            Qs[(c0 + i * 4 + 3) * AT_PAD + r] = v.w * 0.125f;
        }
    }
    float m[8], l[8], o0[8], o1[8];
#pragma unroll
    for (int r = 0; r < 8; r++) { m[r] = -1e30f; l[r] = 0.f; o0[r] = 0.f; o1[r] = 0.f; }
#pragma unroll 1
    for (int j0 = 0; j0 < Sd; j0 += 64) {
        __syncthreads();
        {
            int r = tid >> 2, c0 = (tid & 3) * 16;
            const float* kp = g_qkv + (size_t)(b * Sd + j0 + r) * D3 + Dm + h * HDd + c0;
            const float* vp = kp + Dm;
#pragma unroll
            for (int i = 0; i < 4; i++) {
                float4 kv = *(const float4*)(kp + i * 4);
                KPs[(c0 + i * 4 + 0) * AT_PAD + r] = kv.x;
                KPs[(c0 + i * 4 + 1) * AT_PAD + r] = kv.y;
                KPs[(c0 + i * 4 + 2) * AT_PAD + r] = kv.z;
                KPs[(c0 + i * 4 + 3) * AT_PAD + r] = kv.w;
                float4 vv = *(const float4*)(vp + i * 4);
                Vs[(c0 + i * 4 + 0) * AT_PAD + r] = vv.x;
                Vs[(c0 + i * 4 + 1) * AT_PAD + r] = vv.y;
                Vs[(c0 + i * 4 + 2) * AT_PAD + r] = vv.z;
                Vs[(c0 + i * 4 + 3) * AT_PAD + r] = vv.w;
            }
        }
        __syncthreads();
        float s[8][2];
#pragma unroll
        for (int r = 0; r < 8; r++) { s[r][0] = 0.f; s[r][1] = 0.f; }
#pragma unroll 8
        for (int d = 0; d < 64; d++) {
            float4 qa = *(const float4*)&Qs[d * AT_PAD + qr];
            float4 qb = *(const float4*)&Qs[d * AT_PAD + qr + 4];
            float2 kk = *(const float2*)&KPs[d * AT_PAD + 2 * lane];
            s[0][0] += qa.x * kk.x; s[0][1] += qa.x * kk.y;
            s[1][0] += qa.y * kk.x; s[1][1] += qa.y * kk.y;
            s[2][0] += qa.z * kk.x; s[2][1] += qa.z * kk.y;
            s[3][0] += qa.w * kk.x; s[3][1] += qa.w * kk.y;
            s[4][0] += qb.x * kk.x; s[4][1] += qb.x * kk.y;
            s[5][0] += qb.y * kk.x; s[5][1] += qb.y * kk.y;
            s[6][0] += qb.z * kk.x; s[6][1] += qb.z * kk.y;
            s[7][0] += qb.w * kk.x; s[7][1] += qb.w * kk.y;
        }
#pragma unroll
        for (int r = 0; r < 8; r++) {
            float tmax = fmaxf(s[r][0], s[r][1]);
#pragma unroll
            for (int o = 16; o; o >>= 1) tmax = fmaxf(tmax, __shfl_xor_sync(0xffffffffu, tmax, o));
            float mn = fmaxf(m[r], tmax);
            float corr = __expf(m[r] - mn);
            float p0 = __expf(s[r][0] - mn);
            float p1 = __expf(s[r][1] - mn);
            float rs = p0 + p1;
#pragma unroll
            for (int o = 16; o; o >>= 1) rs += __shfl_xor_sync(0xffffffffu, rs, o);
            l[r] = l[r] * corr + rs;
            m[r] = mn;
            o0[r] *= corr; o1[r] *= corr;
            s[r][0] = p0; s[r][1] = p1;
        }
        __syncthreads();
#pragma unroll
        for (int r = 0; r < 8; r++)
            *(float2*)&KPs[(qr + r) * AT_PAD + 2 * lane] = make_float2(s[r][0], s[r][1]);
        __syncthreads();
        const float* vr0 = &Vs[lane * AT_PAD];
        const float* vr1 = &Vs[(lane + 32) * AT_PAD];
#pragma unroll 4
        for (int k4 = 0; k4 < 16; k4++) {
            float4 v0 = *(const float4*)(vr0 + 4 * k4);
            float4 v1 = *(const float4*)(vr1 + 4 * k4);
#pragma unroll
            for (int r = 0; r < 8; r++) {
                float4 p = *(const float4*)&KPs[(qr + r) * AT_PAD + 4 * k4];
                o0[r] += p.x * v0.x + p.y * v0.y + p.z * v0.z + p.w * v0.w;
                o1[r] += p.x * v1.x + p.y * v1.y + p.z * v1.z + p.w * v1.w;
            }
        }
    }
#pragma unroll
    for (int r = 0; r < 8; r++) {
        float inv = 1.0f / l[r];
        int t = b * Sd + q0 + qr + r;
        __half* dp = g_attno2 + (size_t)t * Dm + h * HDd + lane;
        dp[0]  = __float2half(o0[r] * inv);
        dp[32] = __float2half(o1[r] * inv);
    }
}

// ---------------- fused dual LN ----------------
__global__ void ln_k(const float* __restrict__ x,
                     const float* __restrict__ ln1w, const float* __restrict__ ln1b,
                     const float* __restrict__ ln2w, const float* __restrict__ ln2b,
                     float* __restrict__ out) {
    int t = blockIdx.x, tid = threadIdx.x;
    __shared__ float r1[8], r2[8];
    __shared__ float mu_s, rs_s;
    size_t off = (size_t)t * Dm;
    float a0 = x[off + tid] + g_attnout[off + tid];
    float a1 = x[off + 256 + tid] + g_attnout[off + 256 + tid];
    float s = a0 + a1, ss = a0 * a0 + a1 * a1;
#pragma unroll
    for (int o = 16; o; o >>= 1) {
        s += __shfl_xor_sync(0xffffffffu, s, o);
        ss += __shfl_xor_sync(0xffffffffu, ss, o);
    }
    if ((tid & 31) == 0) { r1[tid >> 5] = s; r2[tid >> 5] = ss; }
    __syncthreads();
    if (tid == 0) {
        float S = 0.f, SS = 0.f;
#pragma unroll
        for (int i = 0; i < 8; i++) { S += r1[i]; SS += r2[i]; }
        float mu = S * (1.0f / 512.0f);
        mu_s = mu;
        rs_s = rsqrtf(SS * (1.0f / 512.0f) - mu * mu + 1e-5f);
    }
    __syncthreads();
    float mu = mu_s, rs = rs_s;
    float z0 = (a0 - mu) * rs * ln1w[tid] + ln1b[tid] + g_nout[off + tid];
    float z1 = (a1 - mu) * rs * ln1w[256 + tid] + ln1b[256 + tid] + g_nout[off + 256 + tid];
    s = z0 + z1; ss = z0 * z0 + z1 * z1;
#pragma unroll
    for (int o = 16; o; o >>= 1) {
        s += __shfl_xor_sync(0xffffffffu, s, o);
        ss += __shfl_xor_sync(0xffffffffu, ss, o);
    }
    __syncthreads();
    if ((tid & 31) == 0) { r1[tid >> 5] = s; r2[tid >> 5] = ss; }
    __syncthreads();
    if (tid == 0) {
        float S = 0.f, SS = 0.f;
#pragma unroll
        for (int i = 0; i < 8; i++) { S += r1[i]; SS += r2[i]; }
        float mu2 = S * (1.0f / 512.0f);
        mu_s = mu2;
        rs_s = rsqrtf(SS * (1.0f / 512.0f) - mu2 * mu2 + 1e-5f);
    }
    __syncthreads();
    mu = mu_s; rs = rs_s;
    out[off + tid] = (z0 - mu) * rs * ln2w[tid] + ln2b[tid];
    out[off + 256 + tid] = (z1 - mu) * rs * ln2w[256 + tid] + ln2b[256 + tid];
}

// ---------------- launcher ----------------
extern "C" void kernel_launch(void* const* d_in, const int* in_sizes, int n_in,
                              void* d_out, int out_size) {
    const float* x    = (const float*)d_in[0];
    const float* Wr   = (const float*)d_in[1];
    const float* br   = (const float*)d_in[2];
    const float* W1   = (const float*)d_in[3];
    const float* b1   = (const float*)d_in[4];
    const float* W2   = (const float*)d_in[5];
    const float* b2   = (const float*)d_in[6];
    const float* Wqkv = (const float*)d_in[7];
    const float* bqkv = (const float*)d_in[8];
    const float* Wo   = (const float*)d_in[9];
    const float* bo   = (const float*)d_in[10];
    const float* ln1w = (const float*)d_in[11];
    const float* ln1b = (const float*)d_in[12];
    const float* ln2w = (const float*)d_in[13];
    const float* ln2b = (const float*)d_in[14];
    float* out = (float*)d_out;

    float *p_qkv, *p_attnout;
    __half *p_x2, *p_w12, *p_w22, *p_wqkv2, *p_wo2, *p_nout2, *p_attno2;
    cudaGetSymbolAddress((void**)&p_qkv, g_qkv);
    cudaGetSymbolAddress((void**)&p_attnout, g_attnout);
    cudaGetSymbolAddress((void**)&p_x2, g_x2);
    cudaGetSymbolAddress((void**)&p_w12, g_W12);
    cudaGetSymbolAddress((void**)&p_w22, g_W22);
    cudaGetSymbolAddress((void**)&p_wqkv2, g_Wqkv2);
    cudaGetSymbolAddress((void**)&p_wo2, g_Wo2);
    cudaGetSymbolAddress((void**)&p_nout2, g_nout2);
    cudaGetSymbolAddress((void**)&p_attno2, g_attno2);

    static int init_done = 0;
    static cudaStream_t sA, sB;
    static cudaEvent_t evRoot, evA, evB, evQ, evO;
    if (!init_done) {
        cudaFuncSetAttribute(attn2_k, cudaFuncAttributeMaxDynamicSharedMemorySize, SMEM_ATTN);
        cudaFuncSetAttribute(ffn1_mma_k, cudaFuncAttributeMaxDynamicSharedMemorySize, SMEM_FFN);
        cudaFuncSetAttribute(ffn2_mma_k, cudaFuncAttributeMaxDynamicSharedMemorySize, SMEM_FFN);
        cudaFuncSetAttribute(gemm_mma_k, cudaFuncAttributeMaxDynamicSharedMemorySize, SMEM_GEMM);
        cudaStreamCreateWithFlags(&sA, cudaStreamNonBlocking);
        cudaStreamCreateWithFlags(&sB, cudaStreamNonBlocking);
        cudaEventCreateWithFlags(&evRoot, cudaEventDisableTiming);
        cudaEventCreateWithFlags(&evA, cudaEventDisableTiming);
        cudaEventCreateWithFlags(&evB, cudaEventDisableTiming);
        cudaEventCreateWithFlags(&evQ, cudaEventDisableTiming);
        cudaEventCreateWithFlags(&evO, cudaEventDisableTiming);
        init_done = 1;
    }

    // fork point
    cudaEventRecord(evRoot, 0);
    cudaStreamWaitEvent(sA, evRoot, 0);
    cudaStreamWaitEvent(sB, evRoot, 0);

    // stream A: inputs needed by ffn1
    conv2_k<<<T * Dm / 256, 256, 0, sA>>>(x, p_x2, T * Dm);
    convw2_k<<<dim3(Hd / 32, Dm / 32, Np), dim3(32, 8), 0, sA>>>(W1, p_w12, Dm, Hd);
    cudaEventRecord(evA, sA);

    // stream B: inputs needed by ffn2 / projections
    convw2_k<<<dim3(Dm / 32, Hd / 32, Np), dim3(32, 8), 0, sB>>>(W2, p_w22, Hd, Dm);
    cudaEventRecord(evB, sB);
    conv2_k<<<D3 * Dm / 256, 256, 0, sB>>>(Wqkv, p_wqkv2, D3 * Dm);
    cudaEventRecord(evQ, sB);
    conv2_k<<<Dm * Dm / 256, 256, 0, sB>>>(Wo, p_wo2, Dm * Dm);
    cudaEventRecord(evO, sB);

    // main stream: router + list build (overlaps conversions)
    router_k<<<T / 8, 256>>>(x, Wr, br);
    zero_k<<<1, 32>>>();
    build_k<<<(T * Kk + 255) / 256, 256>>>();

    // sparse FFN on tensor cores (fp16 single-pass)
    cudaStreamWaitEvent(0, evA, 0);
    ffn1_mma_k<<<dim3(16, 32, 32), 256, SMEM_FFN>>>(b1);
    cudaStreamWaitEvent(0, evB, 0);
    ffn2_mma_k<<<dim3(4, 32, 32), 256, SMEM_FFN>>>(b2);
    reduce3_k<<<(T * Dm / 4 + 255) / 256, 256>>>();

    // attention (fp16 HMMA projections + fp32 flash core)
    cudaStreamWaitEvent(0, evQ, 0);
    gemm_mma_k<<<dim3(D3 / 128, T / 128), 256, SMEM_GEMM>>>(p_nout2, p_wqkv2, bqkv, p_qkv, D3, Dm);
    attn2_k<<<dim3(Sd / 64, NHd, Bd), 256, SMEM_ATTN>>>();
    cudaStreamWaitEvent(0, evO, 0);
    gemm_mma_k<<<dim3(Dm / 128, T / 128), 256, SMEM_GEMM>>>(p_attno2, p_wo2, bo, p_attnout, Dm, Dm);

    // epilogue
    ln_k<<<T, 256>>>(x, ln1w, ln1b, ln2w, ln2b, out);
}

// round 13
// speedup vs baseline: 2.4282x; 2.0150x over previous
#include <cuda_runtime.h>
#include <cuda_fp16.h>
#include <math.h>
#include <stdint.h>

#define T   2048
#define Dm  512
#define Np  32
#define Hd  2048
#define Kk  4
#define NHd 8
#define HDd 64
#define Sd  1024
#define Bd  2
#define D3  1536

// HMMA tile constants: pitch 72 fp16 per row
#define FP 72
#define FTILE (128 * FP)                 // fp16 units per 128-row tile (dense gemm)
#define SMEM_GEMM (4 * FTILE * 2)        // dense gemm: 2 bufs x (A128 + B128)
#define FSTAGE (192 * FP)                // ffn stage: A(64 rows) + B(128 rows)
#define SMEM_FFN (2 * FSTAGE * 2)        // 2 stages

__device__ int   g_idx[T * Kk];
__device__ int   g_cnt[Np];
__device__ int   g_list[Np * T];
__device__ float g_pairs[T * Kk * Dm];
__device__ float g_nout[T * Dm];
__device__ float g_attnout[T * Dm];
__device__ __half g_x2[T * Dm];
__device__ __half g_nout2[T * Dm];
__device__ __half g_attno2[T * Dm];
__device__ __half g_qkv2[(size_t)T * D3];
__device__ __half g_W12[(size_t)Np * Hd * Dm];   // [n][h][k]
__device__ __half g_W22[(size_t)Np * Dm * Hd];   // [n][d][k]
__device__ __half g_Wqkv2[(size_t)D3 * Dm];
__device__ __half g_Wo2[(size_t)Dm * Dm];
__device__ __half g_h2[(size_t)T * Kk * Hd];     // [pair][h]

__device__ __forceinline__ float gelu_f(float v) {
    float u = 0.7978845608028654f * (v + 0.044715f * v * v * v);
    return 0.5f * v * (1.0f + tanhf(u));
}

__device__ __forceinline__ uint32_t cvta_smem(const void* p) {
    uint32_t a;
    asm("{ .reg .u64 t; cvta.to.shared.u64 t, %1; cvt.u32.u64 %0, t; }" : "=r"(a) : "l"(p));
    return a;
}

__device__ __forceinline__ void mma_f16(float c[4], uint32_t a0, uint32_t a1,
                                        uint32_t a2, uint32_t a3,
                                        uint32_t b0, uint32_t b1) {
    asm volatile(
        "mma.sync.aligned.m16n8k16.row.col.f32.f16.f16.f32 "
        "{%0,%1,%2,%3}, {%4,%5,%6,%7}, {%8,%9}, {%0,%1,%2,%3};"
        : "+f"(c[0]), "+f"(c[1]), "+f"(c[2]), "+f"(c[3])
        : "r"(a0), "r"(a1), "r"(a2), "r"(a3), "r"(b0), "r"(b1));
}

__device__ __forceinline__ void ldsm4(uint32_t r[4], uint32_t a) {
    asm volatile("ldmatrix.sync.aligned.m8n8.x4.shared.b16 {%0,%1,%2,%3}, [%4];"
        : "=r"(r[0]), "=r"(r[1]), "=r"(r[2]), "=r"(r[3]) : "r"(a));
}
__device__ __forceinline__ void ldsm4t(uint32_t r[4], uint32_t a) {
    asm volatile("ldmatrix.sync.aligned.m8n8.x4.trans.shared.b16 {%0,%1,%2,%3}, [%4];"
        : "=r"(r[0]), "=r"(r[1]), "=r"(r[2]), "=r"(r[3]) : "r"(a));
}

// ---------------- router / list ----------------
__global__ void router_k(const float* __restrict__ x, const float* __restrict__ Wr,
                         const float* __restrict__ br) {
    int warp = threadIdx.x >> 5, lane = threadIdx.x & 31;
    int t = blockIdx.x * 8 + warp;
    const float* xp = x + (size_t)t * Dm + lane * 16;
    float4 xv[4];
#pragma unroll
    for (int i = 0; i < 4; i++) xv[i] = *(const float4*)(xp + i * 4);
    float lg[32];
#pragma unroll 1
    for (int n = 0; n < 32; n++) {
        const float* wp = Wr + n * Dm + lane * 16;
        float acc = 0.f;
#pragma unroll
        for (int i = 0; i < 4; i++) {
            float4 w = *(const float4*)(wp + i * 4);
            acc += xv[i].x * w.x + xv[i].y * w.y + xv[i].z * w.z + xv[i].w * w.w;
        }
#pragma unroll
        for (int o = 16; o; o >>= 1) acc += __shfl_xor_sync(0xffffffffu, acc, o);
        lg[n] = acc + br[n];
    }
    if (lane == 0) {
        unsigned used = 0;
        for (int k2 = 0; k2 < 4; k2++) {
            float best = -1e30f; int bi = 0;
            for (int n = 0; n < 32; n++)
                if (!((used >> n) & 1u) && lg[n] > best) { best = lg[n]; bi = n; }
            used |= 1u << bi;
            g_idx[t * 4 + k2] = bi;
        }
    }
}
__global__ void zero_k() { if (threadIdx.x < Np) g_cnt[threadIdx.x] = 0; }
__global__ void build_k() {
    int e = blockIdx.x * 256 + threadIdx.x;
    if (e >= T * Kk) return;
    int n = g_idx[e];
    int pos = atomicAdd(&g_cnt[n], 1);
    g_list[n * T + pos] = e;
}

// ---------------- fp16 conversions ----------------
__global__ void conv2_k(const float* __restrict__ src, __half* __restrict__ dst, int total) {
    int i = blockIdx.x * 256 + threadIdx.x;
    if (i < total) dst[i] = __float2half(src[i]);
}
__global__ void convw2_k(const float* __restrict__ W, __half* __restrict__ W2h,
                         int Kd, int Nd) {
    __shared__ float tile[32][33];
    int n = blockIdx.z, k0 = blockIdx.y * 32, c0 = blockIdx.x * 32;
    const float* Wn = W + (size_t)n * Kd * Nd;
#pragma unroll
    for (int i = 0; i < 32; i += 8)
        tile[threadIdx.y + i][threadIdx.x] = Wn[(size_t)(k0 + threadIdx.y + i) * Nd + c0 + threadIdx.x];
    __syncthreads();
    __half* Wo = W2h + (size_t)n * Nd * Kd;
#pragma unroll
    for (int i = 0; i < 32; i += 8)
        Wo[(size_t)(c0 + threadIdx.y + i) * Kd + k0 + threadIdx.x] =
            __float2half(tile[threadIdx.x][threadIdx.y + i]);
}

// ---------------- HMMA chunks ----------------
__device__ __forceinline__ void hmma_chunk(uint32_t smb_A, uint32_t smb_B,
                                           int warpM, int warpN, int rA, int kA,
                                           int rB, int kB, float acc[4][4][4]) {
#pragma unroll
    for (int kk = 0; kk < 4; kk++) {
        uint32_t af[4][4], bf[4][2];
#pragma unroll
        for (int mt = 0; mt < 4; mt++)
            ldsm4(af[mt], smb_A + (uint32_t)(((warpM + mt * 16 + rA) * FP + kk * 16 + kA) * 2));
#pragma unroll
        for (int nt2 = 0; nt2 < 2; nt2++) {
            uint32_t treg[4];
            ldsm4(treg, smb_B + (uint32_t)(((warpN + nt2 * 16 + rB) * FP + kk * 16 + kB) * 2));
            bf[2 * nt2][0] = treg[0]; bf[2 * nt2][1] = treg[1];
            bf[2 * nt2 + 1][0] = treg[2]; bf[2 * nt2 + 1][1] = treg[3];
        }
#pragma unroll
        for (int mt = 0; mt < 4; mt++)
#pragma unroll
            for (int nt = 0; nt < 4; nt++)
                mma_f16(acc[mt][nt], af[mt][0], af[mt][1], af[mt][2], af[mt][3],
                        bf[nt][0], bf[nt][1]);
    }
}
__device__ __forceinline__ void hmma_chunk16(uint32_t smb_A, uint32_t smb_B,
                                             int warpM, int warpN, int rA, int kA,
                                             int rB, int kB, float acc[2][4][4]) {
#pragma unroll
    for (int kk = 0; kk < 4; kk++) {
        uint32_t af[2][4], bf[4][2];
#pragma unroll
        for (int mt = 0; mt < 2; mt++)
            ldsm4(af[mt], smb_A + (uint32_t)(((warpM + mt * 16 + rA) * FP + kk * 16 + kA) * 2));
#pragma unroll
        for (int nt2 = 0; nt2 < 2; nt2++) {
            uint32_t treg[4];
            ldsm4(treg, smb_B + (uint32_t)(((warpN + nt2 * 16 + rB) * FP + kk * 16 + kB) * 2));
            bf[2 * nt2][0] = treg[0]; bf[2 * nt2][1] = treg[1];
            bf[2 * nt2 + 1][0] = treg[2]; bf[2 * nt2 + 1][1] = treg[3];
        }
#pragma unroll
        for (int mt = 0; mt < 2; mt++)
#pragma unroll
            for (int nt = 0; nt < 4; nt++)
                mma_f16(acc[mt][nt], af[mt][0], af[mt][1], af[mt][2], af[mt][3],
                        bf[nt][0], bf[nt][1]);
    }
}

// ---------------- FFN pass 1: h = gelu(x @ W1 + b1), M=64 tiles, K=512 ----------------
__global__ __launch_bounds__(256, 2)
void ffn1_mma_k(const float* __restrict__ b1) {
    int n = blockIdx.z, mt0 = blockIdx.y, nb = blockIdx.x * 128;
    int cnt = g_cnt[n];
    int base = mt0 * 64;
    if (base >= cnt) return;

    extern __shared__ __align__(16) __half sm[];
    __shared__ int es[64];
    int tid = threadIdx.x, wid = tid >> 5, lane = tid & 31;
    if (tid < 64) es[tid] = (base + tid < cnt) ? g_list[n * T + base + tid] : -1;
    __syncthreads();

    int arw = tid >> 2, aq = (tid & 3) * 16;
    int e_row = es[arw];
    const __half* arow = (e_row >= 0) ? (g_x2 + (size_t)(e_row >> 2) * Dm) : 0;
    int stoA = arw * FP + aq;
    int brw = tid >> 1, bh = (tid & 1) * 32;
    const __half* brow = g_W12 + ((size_t)n * Hd + nb + brw) * Dm;
    int stoB = 64 * FP + brw * FP + bh;

    float acc[2][4][4];
#pragma unroll
    for (int i = 0; i < 2; i++)
#pragma unroll
        for (int j = 0; j < 4; j++)
#pragma unroll
            for (int k = 0; k < 4; k++) acc[i][j][k] = 0.f;

    int g = lane >> 2, t2 = (lane & 3) * 2;
    int warpM = (wid >> 2) * 32, warpN = (wid & 3) * 32;
    int rA = ((lane >> 3) & 1) * 8 + (lane & 7);
    int kA = (lane >> 4) * 8;
    int rB = (lane & 7) + (lane >> 4) * 8;
    int kB = ((lane >> 3) & 1) * 8;
    uint32_t smb = cvta_smem(sm);

    const int NCH = 8;
    uint4 ra[2], rb[4];
    if (arow) {
        ra[0] = *(const uint4*)(arow + aq);
        ra[1] = *(const uint4*)(arow + aq + 8);
    } else { ra[0] = make_uint4(0, 0, 0, 0); ra[1] = make_uint4(0, 0, 0, 0); }
#pragma unroll
    for (int i = 0; i < 4; i++) rb[i] = *(const uint4*)(brow + bh + i * 8);
    *(uint4*)(sm + stoA) = ra[0]; *(uint4*)(sm + stoA + 8) = ra[1];
#pragma unroll
    for (int i = 0; i < 4; i++) *(uint4*)(sm + stoB + i * 8) = rb[i];
    __syncthreads();

#pragma unroll 1
    for (int c = 0; c < NCH; c++) {
        int buf = c & 1;
        if (c + 1 < NCH) {
            int ko = (c + 1) * 64;
            if (arow) {
                const __half* ap = arow + ko + aq;
                ra[0] = *(const uint4*)(ap); ra[1] = *(const uint4*)(ap + 8);
            }
            const __half* bp = brow + ko + bh;
#pragma unroll
            for (int i = 0; i < 4; i++) rb[i] = *(const uint4*)(bp + i * 8);
        }
        uint32_t baseA = smb + (uint32_t)(buf * FSTAGE * 2);
        hmma_chunk16(baseA, baseA + 64 * FP * 2, warpM, warpN, rA, kA, rB, kB, acc);
        if (c + 1 < NCH) {
            __half* d = sm + ((c + 1) & 1) * FSTAGE;
            *(uint4*)(d + stoA) = ra[0]; *(uint4*)(d + stoA + 8) = ra[1];
#pragma unroll
            for (int i = 0; i < 4; i++) *(uint4*)(d + stoB + i * 8) = rb[i];
        }
        __syncthreads();
    }

#pragma unroll
    for (int mt = 0; mt < 2; mt++) {
#pragma unroll
        for (int rr = 0; rr < 2; rr++) {
            int row = warpM + mt * 16 + g + rr * 8;
            int er = es[row];
            if (er < 0) continue;
            __half* hp = g_h2 + (size_t)er * Hd;
#pragma unroll
            for (int nt = 0; nt < 4; nt++) {
                int col = nb + warpN + nt * 8 + t2;
                float v0 = gelu_f(acc[mt][nt][rr * 2 + 0] + b1[(size_t)n * Hd + col]);
                float v1 = gelu_f(acc[mt][nt][rr * 2 + 1] + b1[(size_t)n * Hd + col + 1]);
                __half2 hv = __floats2half2_rn(v0, v1);
                *(__half2*)(hp + col) = hv;
            }
        }
    }
}

// ---------------- FFN pass 2: out = h @ W2 + b2, M=64 tiles, K=2048 ----------------
__global__ __launch_bounds__(256, 2)
void ffn2_mma_k(const float* __restrict__ b2) {
    int n = blockIdx.z, mt0 = blockIdx.y, nb = blockIdx.x * 128;
    int cnt = g_cnt[n];
    int base = mt0 * 64;
    if (base >= cnt) return;

    extern __shared__ __align__(16) __half sm[];
    __shared__ int es[64];
    int tid = threadIdx.x, wid = tid >> 5, lane = tid & 31;
    if (tid < 64) es[tid] = (base + tid < cnt) ? g_list[n * T + base + tid] : -1;
    __syncthreads();

    int arw = tid >> 2, aq = (tid & 3) * 16;
    int e_row = es[arw];
    const __half* arow = (e_row >= 0) ? (g_h2 + (size_t)e_row * Hd) : 0;
    int stoA = arw * FP + aq;
    int brw = tid >> 1, bh = (tid & 1) * 32;
    const __half* brow = g_W22 + ((size_t)n * Dm + nb + brw) * Hd;
    int stoB = 64 * FP + brw * FP + bh;

    float acc[2][4][4];
#pragma unroll
    for (int i = 0; i < 2; i++)
#pragma unroll
        for (int j = 0; j < 4; j++)
#pragma unroll
            for (int k = 0; k < 4; k++) acc[i][j][k] = 0.f;

    int g = lane >> 2, t2 = (lane & 3) * 2;
    int warpM = (wid >> 2) * 32, warpN = (wid & 3) * 32;
    int rA = ((lane >> 3) & 1) * 8 + (lane & 7);
    int kA = (lane >> 4) * 8;
    int rB = (lane & 7) + (lane >> 4) * 8;
    int kB = ((lane >> 3) & 1) * 8;
    uint32_t smb = cvta_smem(sm);

    const int NCH = 32;
    uint4 ra[2], rb[4];
    if (arow) {
        ra[0] = *(const uint4*)(arow + aq);
        ra[1] = *(const uint4*)(arow + aq + 8);
    } else { ra[0] = make_uint4(0, 0, 0, 0); ra[1] = make_uint4(0, 0, 0, 0); }
#pragma unroll
    for (int i = 0; i < 4; i++) rb[i] = *(const uint4*)(brow + bh + i * 8);
    *(uint4*)(sm + stoA) = ra[0]; *(uint4*)(sm + stoA + 8) = ra[1];
#pragma unroll
    for (int i = 0; i < 4; i++) *(uint4*)(sm + stoB + i * 8) = rb[i];
    __syncthreads();

#pragma unroll 1
    for (int c = 0; c < NCH; c++) {
        int buf = c & 1;
        if (c + 1 < NCH) {
            int ko = (c + 1) * 64;
            if (arow) {
                const __half* ap = arow + ko + aq;
                ra[0] = *(const uint4*)(ap); ra[1] = *(const uint4*)(ap + 8);
            }
            const __half* bp = brow + ko + bh;
#pragma unroll
            for (int i = 0; i < 4; i++) rb[i] = *(const uint4*)(bp + i * 8);
        }
        uint32_t baseA = smb + (uint32_t)(buf * FSTAGE * 2);
        hmma_chunk16(baseA, baseA + 64 * FP * 2, warpM, warpN, rA, kA, rB, kB, acc);
        if (c + 1 < NCH) {
            __half* d = sm + ((c + 1) & 1) * FSTAGE;
            *(uint4*)(d + stoA) = ra[0]; *(uint4*)(d + stoA + 8) = ra[1];
#pragma unroll
            for (int i = 0; i < 4; i++) *(uint4*)(d + stoB + i * 8) = rb[i];
        }
        __syncthreads();
    }

#pragma unroll
    for (int mt = 0; mt < 2; mt++) {
#pragma unroll
        for (int rr = 0; rr < 2; rr++) {
            int row = warpM + mt * 16 + g + rr * 8;
            int er = es[row];
            if (er < 0) continue;
            float* op = g_pairs + (size_t)er * Dm;
#pragma unroll
            for (int nt = 0; nt < 4; nt++) {
                int col = nb + warpN + nt * 8 + t2;
                float2 o;
                o.x = acc[mt][nt][rr * 2 + 0] + b2[(size_t)n * Dm + col];
                o.y = acc[mt][nt][rr * 2 + 1] + b2[(size_t)n * Dm + col + 1];
                *(float2*)(op + col) = o;
            }
        }
    }
}

// ---------------- dense HMMA GEMM: C = A @ W^T + bias (fp32 or fp16 out) ----------------
__global__ __launch_bounds__(256)
void gemm_mma_k(const __half* __restrict__ A2, const __half* __restrict__ W2h,
                const float* __restrict__ bias, float* __restrict__ C,
                __half* __restrict__ Ch, int Nc, int Kd) {
    int nb = blockIdx.x * 128, mg = blockIdx.y * 128;
    extern __shared__ __align__(16) __half sm[];
    int tid = threadIdx.x, wid = tid >> 5, lane = tid & 31;

    int hr = tid >> 1, half = tid & 1;
    const __half* arow = A2 + (size_t)(mg + hr) * Kd;
    const __half* brow = W2h + (size_t)(nb + hr) * Kd;
    int sto = hr * FP + half * 32;

    float acc[4][4][4];
#pragma unroll
    for (int i = 0; i < 4; i++)
#pragma unroll
        for (int j = 0; j < 4; j++)
#pragma unroll
            for (int k = 0; k < 4; k++) acc[i][j][k] = 0.f;

    int g = lane >> 2, t2 = (lane & 3) * 2;
    int warpM = (wid >> 2) * 64, warpN = (wid & 3) * 32;
    int rA = ((lane >> 3) & 1) * 8 + (lane & 7);
    int kA = (lane >> 4) * 8;
    int rB = (lane & 7) + (lane >> 4) * 8;
    int kB = ((lane >> 3) & 1) * 8;
    uint32_t smb = cvta_smem(sm);

    int NCH = Kd >> 6;
    uint4 ra[4], rb[4];
#pragma unroll
    for (int i = 0; i < 4; i++) {
        ra[i] = *(const uint4*)(arow + half * 32 + i * 8);
        rb[i] = *(const uint4*)(brow + half * 32 + i * 8);
    }
#pragma unroll
    for (int i = 0; i < 4; i++) {
        *(uint4*)(sm + sto + i * 8) = ra[i];
        *(uint4*)(sm + FTILE + sto + i * 8) = rb[i];
    }
    __syncthreads();

#pragma unroll 1
    for (int c = 0; c < NCH; c++) {
        int buf = c & 1;
        if (c + 1 < NCH) {
            int ko = (c + 1) * 64;
            const __half* ap = arow + ko + half * 32;
            const __half* bp = brow + ko + half * 32;
#pragma unroll
            for (int i = 0; i < 4; i++) {
                ra[i] = *(const uint4*)(ap + i * 8);
                rb[i] = *(const uint4*)(bp + i * 8);
            }
        }
        uint32_t baseA = smb + (uint32_t)(buf * 2 * FTILE * 2);
        hmma_chunk(baseA, baseA + FTILE * 2, warpM, warpN, rA, kA, rB, kB, acc);
        if (c + 1 < NCH) {
            __half* d = sm + ((c + 1) & 1) * 2 * FTILE;
#pragma unroll
            for (int i = 0; i < 4; i++) {
                *(uint4*)(d + sto + i * 8) = ra[i];
                *(uint4*)(d + FTILE + sto + i * 8) = rb[i];
            }
        }
        __syncthreads();
    }

#pragma unroll
    for (int mt = 0; mt < 4; mt++) {
#pragma unroll
        for (int rr = 0; rr < 2; rr++) {
            int row = mg + warpM + mt * 16 + g + rr * 8;
#pragma unroll
            for (int nt = 0; nt < 4; nt++) {
                int col = nb + warpN + nt * 8 + t2;
                float ox = acc[mt][nt][rr * 2 + 0] + bias[col];
                float oy = acc[mt][nt][rr * 2 + 1] + bias[col + 1];
                if (Ch) {
                    *(__half2*)(Ch + (size_t)row * Nc + col) = __floats2half2_rn(ox, oy);
                } else {
                    *(float2*)(C + (size_t)row * Nc + col) = make_float2(ox, oy);
                }
            }
        }
    }
}

// ---------------- mean over k, fused fp16 cast ----------------
__global__ void reduce3_k() {
    int id = blockIdx.x * 256 + threadIdx.x;
    if (id >= T * Dm / 4) return;
    int t = id >> 7, c4 = (id & 127) << 2;
    float4 s = make_float4(0.f, 0.f, 0.f, 0.f);
#pragma unroll
    for (int k2 = 0; k2 < 4; k2++) {
        float4 v = *(const float4*)&g_pairs[(size_t)(t * 4 + k2) * Dm + c4];
        s.x += v.x; s.y += v.y; s.z += v.z; s.w += v.w;
    }
    s.x *= 0.25f; s.y *= 0.25f; s.z *= 0.25f; s.w *= 0.25f;
    *(float4*)&g_nout[(size_t)t * Dm + c4] = s;
    __half2 h0 = __floats2half2_rn(s.x, s.y);
    __half2 h1 = __floats2half2_rn(s.z, s.w);
    *(__half2*)&g_nout2[(size_t)t * Dm + c4] = h0;
    *(__half2*)&g_nout2[(size_t)t * Dm + c4 + 2] = h1;
}

// ---------------- attention: fp16 HMMA flash, q-tile 64, 4 warps ----------------
__global__ __launch_bounds__(128)
void attn3_k() {
    __shared__ __align__(16) __half Qs[64 * FP];
    __shared__ __align__(16) __half Ks[64 * FP];
    __shared__ __align__(16) __half Vs[64 * FP];
    int q0 = blockIdx.x * 64, h = blockIdx.y, b = blockIdx.z;
    int tid = threadIdx.x, lane = tid & 31, w = tid >> 5;
    int warpQ = w * 16;
    int g = lane >> 2, t2 = (lane & 3) * 2;

    // load Q tile (scaled by 1/8, exact in fp16)
    {
        int r = tid >> 1, c = (tid & 1) * 32;
        const __half* qp = g_qkv2 + (size_t)(b * Sd + q0 + r) * D3 + h * HDd + c;
        __half2 sc = __half2half2(__float2half(0.125f));
#pragma unroll
        for (int i = 0; i < 4; i++) {
            uint4 v = *(const uint4*)(qp + i * 8);
            __half2* hv = (__half2*)&v;
#pragma unroll
            for (int j = 0; j < 4; j++) hv[j] = __hmul2(hv[j], sc);
            *(uint4*)(Qs + r * FP + c + i * 8) = v;
        }
    }

    float m[2] = {-1e30f, -1e30f}, l[2] = {0.f, 0.f};
    float o[8][4];
#pragma unroll
    for (int i = 0; i < 8; i++)
#pragma unroll
        for (int j = 0; j < 4; j++) o[i][j] = 0.f;

    int rA = ((lane >> 3) & 1) * 8 + (lane & 7);
    int kA = (lane >> 4) * 8;
    int rB = (lane & 7) + (lane >> 4) * 8;
    int kB = ((lane >> 3) & 1) * 8;
    int vKey = (lane & 7) + ((lane >> 3) & 1) * 8;
    int vD = (lane >> 4) * 8;
    uint32_t qb = cvta_smem(Qs), kb = cvta_smem(Ks), vb = cvta_smem(Vs);

#pragma unroll 1
    for (int j0 = 0; j0 < Sd; j0 += 64) {
        __syncthreads();
        {
            int r = tid >> 1, c = (tid & 1) * 32;
            const __half* kp = g_qkv2 + (size_t)(b * Sd + j0 + r) * D3 + Dm + h * HDd + c;
            const __half* vp = kp + Dm;
#pragma unroll
            for (int i = 0; i < 4; i++) {
                *(uint4*)(Ks + r * FP + c + i * 8) = *(const uint4*)(kp + i * 8);
                *(uint4*)(Vs + r * FP + c + i * 8) = *(const uint4*)(vp + i * 8);
            }
        }
        __syncthreads();

        // S = Q K^T  (8 n-tiles of 8 keys)
        float s[8][4];
#pragma unroll
        for (int i = 0; i < 8; i++)
#pragma unroll
            for (int j = 0; j < 4; j++) s[i][j] = 0.f;
#pragma unroll
        for (int kc = 0; kc < 4; kc++) {
            uint32_t af[4];
            ldsm4(af, qb + (uint32_t)(((warpQ + rA) * FP + kc * 16 + kA) * 2));
#pragma unroll
            for (int np = 0; np < 4; np++) {
                uint32_t treg[4];
                ldsm4(treg, kb + (uint32_t)(((np * 16 + rB) * FP + kc * 16 + kB) * 2));
                mma_f16(s[2 * np],     af[0], af[1], af[2], af[3], treg[0], treg[1]);
                mma_f16(s[2 * np + 1], af[0], af[1], af[2], af[3], treg[2], treg[3]);
            }
        }

        // streaming softmax (rows g and g+8; quad lanes share a row)
        float corr[2];
#pragma unroll
        for (int rr = 0; rr < 2; rr++) {
            float tmax = -1e30f;
#pragma unroll
            for (int nt = 0; nt < 8; nt++)
                tmax = fmaxf(tmax, fmaxf(s[nt][rr * 2], s[nt][rr * 2 + 1]));
            tmax = fmaxf(tmax, __shfl_xor_sync(0xffffffffu, tmax, 1));
            tmax = fmaxf(tmax, __shfl_xor_sync(0xffffffffu, tmax, 2));
            float mn = fmaxf(m[rr], tmax);
            corr[rr] = __expf(m[rr] - mn);
            m[rr] = mn;
            float rs = 0.f;
#pragma unroll
            for (int nt = 0; nt < 8; nt++) {
                float p0 = __expf(s[nt][rr * 2] - mn);
                float p1 = __expf(s[nt][rr * 2 + 1] - mn);
                s[nt][rr * 2] = p0; s[nt][rr * 2 + 1] = p1;
                rs += p0 + p1;
            }
            rs += __shfl_xor_sync(0xffffffffu, rs, 1);
            rs += __shfl_xor_sync(0xffffffffu, rs, 2);
            l[rr] = l[rr] * corr[rr] + rs;
        }
#pragma unroll
        for (int nt = 0; nt < 8; nt++) {
            o[nt][0] *= corr[0]; o[nt][1] *= corr[0];
            o[nt][2] *= corr[1]; o[nt][3] *= corr[1];
        }

        // O += P V  (P fragments straight from S accumulators; V^T via ldmatrix.trans)
#pragma unroll
        for (int kc = 0; kc < 4; kc++) {
            __half2 h0 = __floats2half2_rn(s[2 * kc][0], s[2 * kc][1]);
            __half2 h1 = __floats2half2_rn(s[2 * kc][2], s[2 * kc][3]);
            __half2 h2 = __floats2half2_rn(s[2 * kc + 1][0], s[2 * kc + 1][1]);
            __half2 h3 = __floats2half2_rn(s[2 * kc + 1][2], s[2 * kc + 1][3]);
            uint32_t pa0 = *(uint32_t*)&h0, pa1 = *(uint32_t*)&h1;
            uint32_t pa2 = *(uint32_t*)&h2, pa3 = *(uint32_t*)&h3;
#pragma unroll
            for (int np = 0; np < 4; np++) {
                uint32_t treg[4];
                ldsm4t(treg, vb + (uint32_t)(((kc * 16 + vKey) * FP + np * 16 + vD) * 2));
                mma_f16(o[2 * np],     pa0, pa1, pa2, pa3, treg[0], treg[1]);
                mma_f16(o[2 * np + 1], pa0, pa1, pa2, pa3, treg[2], treg[3]);
            }
        }
    }

    // epilogue: normalize + fp16 store
#pragma unroll
    for (int rr = 0; rr < 2; rr++) {
        float inv = 1.0f / l[rr];
        int t = b * Sd + q0 + warpQ + g + rr * 8;
        __half* dp = g_attno2 + (size_t)t * Dm + h * HDd;
#pragma unroll
        for (int nt = 0; nt < 8; nt++) {
            __half2 hv = __floats2half2_rn(o[nt][rr * 2] * inv, o[nt][rr * 2 + 1] * inv);
            *(__half2*)(dp + nt * 8 + t2) = hv;
        }
    }
}

// ---------------- fused dual LN ----------------
__global__ void ln_k(const float* __restrict__ x,
                     const float* __restrict__ ln1w, const float* __restrict__ ln1b,
                     const float* __restrict__ ln2w, const float* __restrict__ ln2b,
                     float* __restrict__ out) {
    int t = blockIdx.x, tid = threadIdx.x;
    __shared__ float r1[8], r2[8];
    __shared__ float mu_s, rs_s;
    size_t off = (size_t)t * Dm;
    float a0 = x[off + tid] + g_attnout[off + tid];
    float a1 = x[off + 256 + tid] + g_attnout[off + 256 + tid];
    float s = a0 + a1, ss = a0 * a0 + a1 * a1;
#pragma unroll
    for (int o = 16; o; o >>= 1) {
        s += __shfl_xor_sync(0xffffffffu, s, o);
        ss += __shfl_xor_sync(0xffffffffu, ss, o);
    }
    if ((tid & 31) == 0) { r1[tid >> 5] = s; r2[tid >> 5] = ss; }
    __syncthreads();
    if (tid == 0) {
        float S = 0.f, SS = 0.f;
#pragma unroll
        for (int i = 0; i < 8; i++) { S += r1[i]; SS += r2[i]; }
        float mu = S * (1.0f / 512.0f);
        mu_s = mu;
        rs_s = rsqrtf(SS * (1.0f / 512.0f) - mu * mu + 1e-5f);
    }
    __syncthreads();
    float mu = mu_s, rs = rs_s;
    float z0 = (a0 - mu) * rs * ln1w[tid] + ln1b[tid] + g_nout[off + tid];
    float z1 = (a1 - mu) * rs * ln1w[256 + tid] + ln1b[256 + tid] + g_nout[off + 256 + tid];
    s = z0 + z1; ss = z0 * z0 + z1 * z1;
#pragma unroll
    for (int o = 16; o; o >>= 1) {
        s += __shfl_xor_sync(0xffffffffu, s, o);
        ss += __shfl_xor_sync(0xffffffffu, ss, o);
    }
    __syncthreads();
    if ((tid & 31) == 0) { r1[tid >> 5] = s; r2[tid >> 5] = ss; }
    __syncthreads();
    if (tid == 0) {
        float S = 0.f, SS = 0.f;
#pragma unroll
        for (int i = 0; i < 8; i++) { S += r1[i]; SS += r2[i]; }
        float mu2 = S * (1.0f / 512.0f);
        mu_s = mu2;
        rs_s = rsqrtf(SS * (1.0f / 512.0f) - mu2 * mu2 + 1e-5f);
    }
    __syncthreads();
    mu = mu_s; rs = rs_s;
    out[off + tid] = (z0 - mu) * rs * ln2w[tid] + ln2b[tid];
    out[off + 256 + tid] = (z1 - mu) * rs * ln2w[256 + tid] + ln2b[256 + tid];
}

// ---------------- launcher ----------------
extern "C" void kernel_launch(void* const* d_in, const int* in_sizes, int n_in,
                              void* d_out, int out_size) {
    const float* x    = (const float*)d_in[0];
    const float* Wr   = (const float*)d_in[1];
    const float* br   = (const float*)d_in[2];
    const float* W1   = (const float*)d_in[3];
    const float* b1   = (const float*)d_in[4];
    const float* W2   = (const float*)d_in[5];
    const float* b2   = (const float*)d_in[6];
    const float* Wqkv = (const float*)d_in[7];
    const float* bqkv = (const float*)d_in[8];
    const float* Wo   = (const float*)d_in[9];
    const float* bo   = (const float*)d_in[10];
    const float* ln1w = (const float*)d_in[11];
    const float* ln1b = (const float*)d_in[12];
    const float* ln2w = (const float*)d_in[13];
    const float* ln2b = (const float*)d_in[14];
    float* out = (float*)d_out;

    float *p_attnout;
    __half *p_x2, *p_w12, *p_w22, *p_wqkv2, *p_wo2, *p_nout2, *p_attno2, *p_qkv2;
    cudaGetSymbolAddress((void**)&p_attnout, g_attnout);
    cudaGetSymbolAddress((void**)&p_x2, g_x2);
    cudaGetSymbolAddress((void**)&p_w12, g_W12);
    cudaGetSymbolAddress((void**)&p_w22, g_W22);
    cudaGetSymbolAddress((void**)&p_wqkv2, g_Wqkv2);
    cudaGetSymbolAddress((void**)&p_wo2, g_Wo2);
    cudaGetSymbolAddress((void**)&p_nout2, g_nout2);
    cudaGetSymbolAddress((void**)&p_attno2, g_attno2);
    cudaGetSymbolAddress((void**)&p_qkv2, g_qkv2);

    static int init_done = 0;
    static cudaStream_t sA, sB;
    static cudaEvent_t evRoot, evA, evB, evQ, evO;
    if (!init_done) {
        cudaFuncSetAttribute(ffn1_mma_k, cudaFuncAttributeMaxDynamicSharedMemorySize, SMEM_FFN);
        cudaFuncSetAttribute(ffn2_mma_k, cudaFuncAttributeMaxDynamicSharedMemorySize, SMEM_FFN);
        cudaFuncSetAttribute(gemm_mma_k, cudaFuncAttributeMaxDynamicSharedMemorySize, SMEM_GEMM);
        cudaStreamCreateWithFlags(&sA, cudaStreamNonBlocking);
        cudaStreamCreateWithFlags(&sB, cudaStreamNonBlocking);
        cudaEventCreateWithFlags(&evRoot, cudaEventDisableTiming);
        cudaEventCreateWithFlags(&evA, cudaEventDisableTiming);
        cudaEventCreateWithFlags(&evB, cudaEventDisableTiming);
        cudaEventCreateWithFlags(&evQ, cudaEventDisableTiming);
        cudaEventCreateWithFlags(&evO, cudaEventDisableTiming);
        init_done = 1;
    }

    // fork point
    cudaEventRecord(evRoot, 0);
    cudaStreamWaitEvent(sA, evRoot, 0);
    cudaStreamWaitEvent(sB, evRoot, 0);

    // stream A: inputs needed by ffn1
    conv2_k<<<T * Dm / 256, 256, 0, sA>>>(x, p_x2, T * Dm);
    convw2_k<<<dim3(Hd / 32, Dm / 32, Np), dim3(32, 8), 0, sA>>>(W1, p_w12, Dm, Hd);
    cudaEventRecord(evA, sA);

    // stream B: inputs needed by ffn2 / projections
    convw2_k<<<dim3(Dm / 32, Hd / 32, Np), dim3(32, 8), 0, sB>>>(W2, p_w22, Hd, Dm);
    cudaEventRecord(evB, sB);
    conv2_k<<<D3 * Dm / 256, 256, 0, sB>>>(Wqkv, p_wqkv2, D3 * Dm);
    cudaEventRecord(evQ, sB);
    conv2_k<<<Dm * Dm / 256, 256, 0, sB>>>(Wo, p_wo2, Dm * Dm);
    cudaEventRecord(evO, sB);

    // main stream: router + list build (overlaps conversions)
    router_k<<<T / 8, 256>>>(x, Wr, br);
    zero_k<<<1, 32>>>();
    build_k<<<(T * Kk + 255) / 256, 256>>>();

    // sparse FFN on tensor cores (fp16 single-pass)
    cudaStreamWaitEvent(0, evA, 0);
    ffn1_mma_k<<<dim3(16, 32, 32), 256, SMEM_FFN>>>(b1);
    cudaStreamWaitEvent(0, evB, 0);
    ffn2_mma_k<<<dim3(4, 32, 32), 256, SMEM_FFN>>>(b2);
    reduce3_k<<<(T * Dm / 4 + 255) / 256, 256>>>();

    // attention: fp16 QKV projection + fp16 HMMA flash core
    cudaStreamWaitEvent(0, evQ, 0);
    gemm_mma_k<<<dim3(D3 / 128, T / 128), 256, SMEM_GEMM>>>(p_nout2, p_wqkv2, bqkv, 0, p_qkv2, D3, Dm);
    attn3_k<<<dim3(Sd / 64, NHd, Bd), 128>>>();
    cudaStreamWaitEvent(0, evO, 0);
    gemm_mma_k<<<dim3(Dm / 128, T / 128), 256, SMEM_GEMM>>>(p_attno2, p_wo2, bo, p_attnout, 0, Dm, Dm);

    // epilogue
    ln_k<<<T, 256>>>(x, ln1w, ln1b, ln2w, ln2b, out);
}

// round 14
// speedup vs baseline: 2.4976x; 1.0286x over previous
#include <cuda_runtime.h>
#include <cuda_fp16.h>
#include <math.h>
#include <stdint.h>

#define T   2048
#define Dm  512
#define Np  32
#define Hd  2048
#define Kk  4
#define NHd 8
#define HDd 64
#define Sd  1024
#define Bd  2
#define D3  1536

// HMMA tile constants: pitch 72 fp16 per row
#define FP 72
#define FTILE (128 * FP)                 // fp16 units per 128-row tile (dense gemm)
#define SMEM_GEMM (4 * FTILE * 2)        // dense gemm: 2 bufs x (A128 + B128)
#define FSTAGE (192 * FP)                // ffn stage: A(64 rows) + B(128 rows)
#define SMEM_FFN (2 * FSTAGE * 2)        // 2 stages

#define MAXTILES 8                        // covers cnt <= 512 (~16 sigma)

__device__ int   g_cnt[Np];
__device__ int   g_list[Np * T];
__device__ float g_pairs[T * Kk * Dm];
__device__ float g_nout[T * Dm];
__device__ float g_attnout[T * Dm];
__device__ __half g_x2[T * Dm];
__device__ __half g_nout2[T * Dm];
__device__ __half g_attno2[T * Dm];
__device__ __half g_qkv2[(size_t)T * D3];
__device__ __half g_W12[(size_t)Np * Hd * Dm];   // [n][h][k]
__device__ __half g_W22[(size_t)Np * Dm * Hd];   // [n][d][k]
__device__ __half g_Wqkv2[(size_t)D3 * Dm];
__device__ __half g_Wo2[(size_t)Dm * Dm];
__device__ __half g_h2[(size_t)T * Kk * Hd];     // [pair][h]

__device__ __forceinline__ float gelu_f(float v) {
    float u = 0.7978845608028654f * (v + 0.044715f * v * v * v);
    return 0.5f * v * (1.0f + tanhf(u));
}

__device__ __forceinline__ uint32_t cvta_smem(const void* p) {
    uint32_t a;
    asm("{ .reg .u64 t; cvta.to.shared.u64 t, %1; cvt.u32.u64 %0, t; }" : "=r"(a) : "l"(p));
    return a;
}

__device__ __forceinline__ void mma_f16(float c[4], uint32_t a0, uint32_t a1,
                                        uint32_t a2, uint32_t a3,
                                        uint32_t b0, uint32_t b1) {
    asm volatile(
        "mma.sync.aligned.m16n8k16.row.col.f32.f16.f16.f32 "
        "{%0,%1,%2,%3}, {%4,%5,%6,%7}, {%8,%9}, {%0,%1,%2,%3};"
        : "+f"(c[0]), "+f"(c[1]), "+f"(c[2]), "+f"(c[3])
        : "r"(a0), "r"(a1), "r"(a2), "r"(a3), "r"(b0), "r"(b1));
}

__device__ __forceinline__ void ldsm4(uint32_t r[4], uint32_t a) {
    asm volatile("ldmatrix.sync.aligned.m8n8.x4.shared.b16 {%0,%1,%2,%3}, [%4];"
        : "=r"(r[0]), "=r"(r[1]), "=r"(r[2]), "=r"(r[3]) : "r"(a));
}
__device__ __forceinline__ void ldsm4t(uint32_t r[4], uint32_t a) {
    asm volatile("ldmatrix.sync.aligned.m8n8.x4.trans.shared.b16 {%0,%1,%2,%3}, [%4];"
        : "=r"(r[0]), "=r"(r[1]), "=r"(r[2]), "=r"(r[3]) : "r"(a));
}

// ---------------- zero counters ----------------
__global__ void zero_k() { if (threadIdx.x < Np) g_cnt[threadIdx.x] = 0; }

// ---------------- router: top-4 + direct atomic list build ----------------
__global__ void router_k(const float* __restrict__ x, const float* __restrict__ Wr,
                         const float* __restrict__ br) {
    int warp = threadIdx.x >> 5, lane = threadIdx.x & 31;
    int t = blockIdx.x * 8 + warp;
    const float* xp = x + (size_t)t * Dm + lane * 16;
    float4 xv[4];
#pragma unroll
    for (int i = 0; i < 4; i++) xv[i] = *(const float4*)(xp + i * 4);
    float lg[32];
#pragma unroll 1
    for (int n = 0; n < 32; n++) {
        const float* wp = Wr + n * Dm + lane * 16;
        float acc = 0.f;
#pragma unroll
        for (int i = 0; i < 4; i++) {
            float4 w = *(const float4*)(wp + i * 4);
            acc += xv[i].x * w.x + xv[i].y * w.y + xv[i].z * w.z + xv[i].w * w.w;
        }
#pragma unroll
        for (int o = 16; o; o >>= 1) acc += __shfl_xor_sync(0xffffffffu, acc, o);
        lg[n] = acc + br[n];
    }
    if (lane == 0) {
        unsigned used = 0;
        for (int k2 = 0; k2 < 4; k2++) {
            float best = -1e30f; int bi = 0;
            for (int n = 0; n < 32; n++)
                if (!((used >> n) & 1u) && lg[n] > best) { best = lg[n]; bi = n; }
            used |= 1u << bi;
            int pos = atomicAdd(&g_cnt[bi], 1);   // order-free: each pair owns its slot
            g_list[bi * T + pos] = t * 4 + k2;
        }
    }
}

// ---------------- fp16 conversions ----------------
__global__ void conv2_k(const float* __restrict__ src, __half* __restrict__ dst, int total) {
    int i = blockIdx.x * 256 + threadIdx.x;
    if (i < total) dst[i] = __float2half(src[i]);
}
__global__ void convw2_k(const float* __restrict__ W, __half* __restrict__ W2h,
                         int Kd, int Nd) {
    __shared__ float tile[32][33];
    int n = blockIdx.z, k0 = blockIdx.y * 32, c0 = blockIdx.x * 32;
    const float* Wn = W + (size_t)n * Kd * Nd;
#pragma unroll
    for (int i = 0; i < 32; i += 8)
        tile[threadIdx.y + i][threadIdx.x] = Wn[(size_t)(k0 + threadIdx.y + i) * Nd + c0 + threadIdx.x];
    __syncthreads();
    __half* Wo = W2h + (size_t)n * Nd * Kd;
#pragma unroll
    for (int i = 0; i < 32; i += 8)
        Wo[(size_t)(c0 + threadIdx.y + i) * Kd + k0 + threadIdx.x] =
            __float2half(tile[threadIdx.x][threadIdx.y + i]);
}

// ---------------- HMMA chunks ----------------
__device__ __forceinline__ void hmma_chunk(uint32_t smb_A, uint32_t smb_B,
                                           int warpM, int warpN, int rA, int kA,
                                           int rB, int kB, float acc[4][4][4]) {
#pragma unroll
    for (int kk = 0; kk < 4; kk++) {
        uint32_t af[4][4], bf[4][2];
#pragma unroll
        for (int mt = 0; mt < 4; mt++)
            ldsm4(af[mt], smb_A + (uint32_t)(((warpM + mt * 16 + rA) * FP + kk * 16 + kA) * 2));
#pragma unroll
        for (int nt2 = 0; nt2 < 2; nt2++) {
            uint32_t treg[4];
            ldsm4(treg, smb_B + (uint32_t)(((warpN + nt2 * 16 + rB) * FP + kk * 16 + kB) * 2));
            bf[2 * nt2][0] = treg[0]; bf[2 * nt2][1] = treg[1];
            bf[2 * nt2 + 1][0] = treg[2]; bf[2 * nt2 + 1][1] = treg[3];
        }
#pragma unroll
        for (int mt = 0; mt < 4; mt++)
#pragma unroll
            for (int nt = 0; nt < 4; nt++)
                mma_f16(acc[mt][nt], af[mt][0], af[mt][1], af[mt][2], af[mt][3],
                        bf[nt][0], bf[nt][1]);
    }
}
__device__ __forceinline__ void hmma_chunk16(uint32_t smb_A, uint32_t smb_B,
                                             int warpM, int warpN, int rA, int kA,
                                             int rB, int kB, float acc[2][4][4]) {
#pragma unroll
    for (int kk = 0; kk < 4; kk++) {
        uint32_t af[2][4], bf[4][2];
#pragma unroll
        for (int mt = 0; mt < 2; mt++)
            ldsm4(af[mt], smb_A + (uint32_t)(((warpM + mt * 16 + rA) * FP + kk * 16 + kA) * 2));
#pragma unroll
        for (int nt2 = 0; nt2 < 2; nt2++) {
            uint32_t treg[4];
            ldsm4(treg, smb_B + (uint32_t)(((warpN + nt2 * 16 + rB) * FP + kk * 16 + kB) * 2));
            bf[2 * nt2][0] = treg[0]; bf[2 * nt2][1] = treg[1];
            bf[2 * nt2 + 1][0] = treg[2]; bf[2 * nt2 + 1][1] = treg[3];
        }
#pragma unroll
        for (int mt = 0; mt < 2; mt++)
#pragma unroll
            for (int nt = 0; nt < 4; nt++)
                mma_f16(acc[mt][nt], af[mt][0], af[mt][1], af[mt][2], af[mt][3],
                        bf[nt][0], bf[nt][1]);
    }
}

// ---------------- FFN pass 1: h = gelu(x @ W1 + b1), M=64 tiles, K=512 ----------------
__global__ __launch_bounds__(256, 2)
void ffn1_mma_k(const float* __restrict__ b1) {
    int n = blockIdx.z, mt0 = blockIdx.y, nb = blockIdx.x * 128;
    int cnt = g_cnt[n];
    int base = mt0 * 64;
    if (base >= cnt) return;

    extern __shared__ __align__(16) __half sm[];
    __shared__ int es[64];
    int tid = threadIdx.x, wid = tid >> 5, lane = tid & 31;
    if (tid < 64) es[tid] = (base + tid < cnt) ? g_list[n * T + base + tid] : -1;
    __syncthreads();

    int arw = tid >> 2, aq = (tid & 3) * 16;
    int e_row = es[arw];
    const __half* arow = (e_row >= 0) ? (g_x2 + (size_t)(e_row >> 2) * Dm) : 0;
    int stoA = arw * FP + aq;
    int brw = tid >> 1, bh = (tid & 1) * 32;
    const __half* brow = g_W12 + ((size_t)n * Hd + nb + brw) * Dm;
    int stoB = 64 * FP + brw * FP + bh;

    float acc[2][4][4];
#pragma unroll
    for (int i = 0; i < 2; i++)
#pragma unroll
        for (int j = 0; j < 4; j++)
#pragma unroll
            for (int k = 0; k < 4; k++) acc[i][j][k] = 0.f;

    int g = lane >> 2, t2 = (lane & 3) * 2;
    int warpM = (wid >> 2) * 32, warpN = (wid & 3) * 32;
    int rA = ((lane >> 3) & 1) * 8 + (lane & 7);
    int kA = (lane >> 4) * 8;
    int rB = (lane & 7) + (lane >> 4) * 8;
    int kB = ((lane >> 3) & 1) * 8;
    uint32_t smb = cvta_smem(sm);

    const int NCH = 8;
    uint4 ra[2], rb[4];
    if (arow) {
        ra[0] = *(const uint4*)(arow + aq);
        ra[1] = *(const uint4*)(arow + aq + 8);
    } else { ra[0] = make_uint4(0, 0, 0, 0); ra[1] = make_uint4(0, 0, 0, 0); }
#pragma unroll
    for (int i = 0; i < 4; i++) rb[i] = *(const uint4*)(brow + bh + i * 8);
    *(uint4*)(sm + stoA) = ra[0]; *(uint4*)(sm + stoA + 8) = ra[1];
#pragma unroll
    for (int i = 0; i < 4; i++) *(uint4*)(sm + stoB + i * 8) = rb[i];
    __syncthreads();

#pragma unroll 1
    for (int c = 0; c < NCH; c++) {
        int buf = c & 1;
        if (c + 1 < NCH) {
            int ko = (c + 1) * 64;
            if (arow) {
                const __half* ap = arow + ko + aq;
                ra[0] = *(const uint4*)(ap); ra[1] = *(const uint4*)(ap + 8);
            }
            const __half* bp = brow + ko + bh;
#pragma unroll
            for (int i = 0; i < 4; i++) rb[i] = *(const uint4*)(bp + i * 8);
        }
        uint32_t baseA = smb + (uint32_t)(buf * FSTAGE * 2);
        hmma_chunk16(baseA, baseA + 64 * FP * 2, warpM, warpN, rA, kA, rB, kB, acc);
        if (c + 1 < NCH) {
            __half* d = sm + ((c + 1) & 1) * FSTAGE;
            *(uint4*)(d + stoA) = ra[0]; *(uint4*)(d + stoA + 8) = ra[1];
#pragma unroll
            for (int i = 0; i < 4; i++) *(uint4*)(d + stoB + i * 8) = rb[i];
        }
        __syncthreads();
    }

#pragma unroll
    for (int mt = 0; mt < 2; mt++) {
#pragma unroll
        for (int rr = 0; rr < 2; rr++) {
            int row = warpM + mt * 16 + g + rr * 8;
            int er = es[row];
            if (er < 0) continue;
            __half* hp = g_h2 + (size_t)er * Hd;
#pragma unroll
            for (int nt = 0; nt < 4; nt++) {
                int col = nb + warpN + nt * 8 + t2;
                float v0 = gelu_f(acc[mt][nt][rr * 2 + 0] + b1[(size_t)n * Hd + col]);
                float v1 = gelu_f(acc[mt][nt][rr * 2 + 1] + b1[(size_t)n * Hd + col + 1]);
                __half2 hv = __floats2half2_rn(v0, v1);
                *(__half2*)(hp + col) = hv;
            }
        }
    }
}

// ---------------- FFN pass 2: out = h @ W2 + b2, M=64 tiles, K=2048 ----------------
__global__ __launch_bounds__(256, 2)
void ffn2_mma_k(const float* __restrict__ b2) {
    int n = blockIdx.z, mt0 = blockIdx.y, nb = blockIdx.x * 128;
    int cnt = g_cnt[n];
    int base = mt0 * 64;
    if (base >= cnt) return;

    extern __shared__ __align__(16) __half sm[];
    __shared__ int es[64];
    int tid = threadIdx.x, wid = tid >> 5, lane = tid & 31;
    if (tid < 64) es[tid] = (base + tid < cnt) ? g_list[n * T + base + tid] : -1;
    __syncthreads();

    int arw = tid >> 2, aq = (tid & 3) * 16;
    int e_row = es[arw];
    const __half* arow = (e_row >= 0) ? (g_h2 + (size_t)e_row * Hd) : 0;
    int stoA = arw * FP + aq;
    int brw = tid >> 1, bh = (tid & 1) * 32;
    const __half* brow = g_W22 + ((size_t)n * Dm + nb + brw) * Hd;
    int stoB = 64 * FP + brw * FP + bh;

    float acc[2][4][4];
#pragma unroll
    for (int i = 0; i < 2; i++)
#pragma unroll
        for (int j = 0; j < 4; j++)
#pragma unroll
            for (int k = 0; k < 4; k++) acc[i][j][k] = 0.f;

    int g = lane >> 2, t2 = (lane & 3) * 2;
    int warpM = (wid >> 2) * 32, warpN = (wid & 3) * 32;
    int rA = ((lane >> 3) & 1) * 8 + (lane & 7);
    int kA = (lane >> 4) * 8;
    int rB = (lane & 7) + (lane >> 4) * 8;
    int kB = ((lane >> 3) & 1) * 8;
    uint32_t smb = cvta_smem(sm);

    const int NCH = 32;
    uint4 ra[2], rb[4];
    if (arow) {
        ra[0] = *(const uint4*)(arow + aq);
        ra[1] = *(const uint4*)(arow + aq + 8);
    } else { ra[0] = make_uint4(0, 0, 0, 0); ra[1] = make_uint4(0, 0, 0, 0); }
#pragma unroll
    for (int i = 0; i < 4; i++) rb[i] = *(const uint4*)(brow + bh + i * 8);
    *(uint4*)(sm + stoA) = ra[0]; *(uint4*)(sm + stoA + 8) = ra[1];
#pragma unroll
    for (int i = 0; i < 4; i++) *(uint4*)(sm + stoB + i * 8) = rb[i];
    __syncthreads();

#pragma unroll 1
    for (int c = 0; c < NCH; c++) {
        int buf = c & 1;
        if (c + 1 < NCH) {
            int ko = (c + 1) * 64;
            if (arow) {
                const __half* ap = arow + ko + aq;
                ra[0] = *(const uint4*)(ap); ra[1] = *(const uint4*)(ap + 8);
            }
            const __half* bp = brow + ko + bh;
#pragma unroll
            for (int i = 0; i < 4; i++) rb[i] = *(const uint4*)(bp + i * 8);
        }
        uint32_t baseA = smb + (uint32_t)(buf * FSTAGE * 2);
        hmma_chunk16(baseA, baseA + 64 * FP * 2, warpM, warpN, rA, kA, rB, kB, acc);
        if (c + 1 < NCH) {
            __half* d = sm + ((c + 1) & 1) * FSTAGE;
            *(uint4*)(d + stoA) = ra[0]; *(uint4*)(d + stoA + 8) = ra[1];
#pragma unroll
            for (int i = 0; i < 4; i++) *(uint4*)(d + stoB + i * 8) = rb[i];
        }
        __syncthreads();
    }

#pragma unroll
    for (int mt = 0; mt < 2; mt++) {
#pragma unroll
        for (int rr = 0; rr < 2; rr++) {
            int row = warpM + mt * 16 + g + rr * 8;
            int er = es[row];
            if (er < 0) continue;
            float* op = g_pairs + (size_t)er * Dm;
#pragma unroll
            for (int nt = 0; nt < 4; nt++) {
                int col = nb + warpN + nt * 8 + t2;
                float2 o;
                o.x = acc[mt][nt][rr * 2 + 0] + b2[(size_t)n * Dm + col];
                o.y = acc[mt][nt][rr * 2 + 1] + b2[(size_t)n * Dm + col + 1];
                *(float2*)(op + col) = o;
            }
        }
    }
}

// ---------------- dense HMMA GEMM: C = A @ W^T + bias (fp32 or fp16 out) ----------------
__global__ __launch_bounds__(256)
void gemm_mma_k(const __half* __restrict__ A2, const __half* __restrict__ W2h,
                const float* __restrict__ bias, float* __restrict__ C,
                __half* __restrict__ Ch, int Nc, int Kd) {
    int nb = blockIdx.x * 128, mg = blockIdx.y * 128;
    extern __shared__ __align__(16) __half sm[];
    int tid = threadIdx.x, wid = tid >> 5, lane = tid & 31;

    int hr = tid >> 1, half = tid & 1;
    const __half* arow = A2 + (size_t)(mg + hr) * Kd;
    const __half* brow = W2h + (size_t)(nb + hr) * Kd;
    int sto = hr * FP + half * 32;

    float acc[4][4][4];
#pragma unroll
    for (int i = 0; i < 4; i++)
#pragma unroll
        for (int j = 0; j < 4; j++)
#pragma unroll
            for (int k = 0; k < 4; k++) acc[i][j][k] = 0.f;

    int g = lane >> 2, t2 = (lane & 3) * 2;
    int warpM = (wid >> 2) * 64, warpN = (wid & 3) * 32;
    int rA = ((lane >> 3) & 1) * 8 + (lane & 7);
    int kA = (lane >> 4) * 8;
    int rB = (lane & 7) + (lane >> 4) * 8;
    int kB = ((lane >> 3) & 1) * 8;
    uint32_t smb = cvta_smem(sm);

    int NCH = Kd >> 6;
    uint4 ra[4], rb[4];
#pragma unroll
    for (int i = 0; i < 4; i++) {
        ra[i] = *(const uint4*)(arow + half * 32 + i * 8);
        rb[i] = *(const uint4*)(brow + half * 32 + i * 8);
    }
#pragma unroll
    for (int i = 0; i < 4; i++) {
        *(uint4*)(sm + sto + i * 8) = ra[i];
        *(uint4*)(sm + FTILE + sto + i * 8) = rb[i];
    }
    __syncthreads();

#pragma unroll 1
    for (int c = 0; c < NCH; c++) {
        int buf = c & 1;
        if (c + 1 < NCH) {
            int ko = (c + 1) * 64;
            const __half* ap = arow + ko + half * 32;
            const __half* bp = brow + ko + half * 32;
#pragma unroll
            for (int i = 0; i < 4; i++) {
                ra[i] = *(const uint4*)(ap + i * 8);
                rb[i] = *(const uint4*)(bp + i * 8);
            }
        }
        uint32_t baseA = smb + (uint32_t)(buf * 2 * FTILE * 2);
        hmma_chunk(baseA, baseA + FTILE * 2, warpM, warpN, rA, kA, rB, kB, acc);
        if (c + 1 < NCH) {
            __half* d = sm + ((c + 1) & 1) * 2 * FTILE;
#pragma unroll
            for (int i = 0; i < 4; i++) {
                *(uint4*)(d + sto + i * 8) = ra[i];
                *(uint4*)(d + FTILE + sto + i * 8) = rb[i];
            }
        }
        __syncthreads();
    }

#pragma unroll
    for (int mt = 0; mt < 4; mt++) {
#pragma unroll
        for (int rr = 0; rr < 2; rr++) {
            int row = mg + warpM + mt * 16 + g + rr * 8;
#pragma unroll
            for (int nt = 0; nt < 4; nt++) {
                int col = nb + warpN + nt * 8 + t2;
                float ox = acc[mt][nt][rr * 2 + 0] + bias[col];
                float oy = acc[mt][nt][rr * 2 + 1] + bias[col + 1];
                if (Ch) {
                    *(__half2*)(Ch + (size_t)row * Nc + col) = __floats2half2_rn(ox, oy);
                } else {
                    *(float2*)(C + (size_t)row * Nc + col) = make_float2(ox, oy);
                }
            }
        }
    }
}

// ---------------- mean over k, fused fp16 cast ----------------
__global__ void reduce3_k() {
    int id = blockIdx.x * 256 + threadIdx.x;
    if (id >= T * Dm / 4) return;
    int t = id >> 7, c4 = (id & 127) << 2;
    float4 s = make_float4(0.f, 0.f, 0.f, 0.f);
#pragma unroll
    for (int k2 = 0; k2 < 4; k2++) {
        float4 v = *(const float4*)&g_pairs[(size_t)(t * 4 + k2) * Dm + c4];
        s.x += v.x; s.y += v.y; s.z += v.z; s.w += v.w;
    }
    s.x *= 0.25f; s.y *= 0.25f; s.z *= 0.25f; s.w *= 0.25f;
    *(float4*)&g_nout[(size_t)t * Dm + c4] = s;
    __half2 h0 = __floats2half2_rn(s.x, s.y);
    __half2 h1 = __floats2half2_rn(s.z, s.w);
    *(__half2*)&g_nout2[(size_t)t * Dm + c4] = h0;
    *(__half2*)&g_nout2[(size_t)t * Dm + c4 + 2] = h1;
}

// ---------------- attention: fp16 HMMA flash, q-tile 64, 4 warps ----------------
__global__ __launch_bounds__(128)
void attn3_k() {
    __shared__ __align__(16) __half Qs[64 * FP];
    __shared__ __align__(16) __half Ks[64 * FP];
    __shared__ __align__(16) __half Vs[64 * FP];
    int q0 = blockIdx.x * 64, h = blockIdx.y, b = blockIdx.z;
    int tid = threadIdx.x, lane = tid & 31, w = tid >> 5;
    int warpQ = w * 16;
    int g = lane >> 2, t2 = (lane & 3) * 2;

    {
        int r = tid >> 1, c = (tid & 1) * 32;
        const __half* qp = g_qkv2 + (size_t)(b * Sd + q0 + r) * D3 + h * HDd + c;
        __half2 sc = __half2half2(__float2half(0.125f));
#pragma unroll
        for (int i = 0; i < 4; i++) {
            uint4 v = *(const uint4*)(qp + i * 8);
            __half2* hv = (__half2*)&v;
#pragma unroll
            for (int j = 0; j < 4; j++) hv[j] = __hmul2(hv[j], sc);
            *(uint4*)(Qs + r * FP + c + i * 8) = v;
        }
    }

    float m[2] = {-1e30f, -1e30f}, l[2] = {0.f, 0.f};
    float o[8][4];
#pragma unroll
    for (int i = 0; i < 8; i++)
#pragma unroll
        for (int j = 0; j < 4; j++) o[i][j] = 0.f;

    int rA = ((lane >> 3) & 1) * 8 + (lane & 7);
    int kA = (lane >> 4) * 8;
    int rB = (lane & 7) + (lane >> 4) * 8;
    int kB = ((lane >> 3) & 1) * 8;
    int vKey = (lane & 7) + ((lane >> 3) & 1) * 8;
    int vD = (lane >> 4) * 8;
    uint32_t qb = cvta_smem(Qs), kb = cvta_smem(Ks), vb = cvta_smem(Vs);

#pragma unroll 1
    for (int j0 = 0; j0 < Sd; j0 += 64) {
        __syncthreads();
        {
            int r = tid >> 1, c = (tid & 1) * 32;
            const __half* kp = g_qkv2 + (size_t)(b * Sd + j0 + r) * D3 + Dm + h * HDd + c;
            const __half* vp = kp + Dm;
#pragma unroll
            for (int i = 0; i < 4; i++) {
                *(uint4*)(Ks + r * FP + c + i * 8) = *(const uint4*)(kp + i * 8);
                *(uint4*)(Vs + r * FP + c + i * 8) = *(const uint4*)(vp + i * 8);
            }
        }
        __syncthreads();

        float s[8][4];
#pragma unroll
        for (int i = 0; i < 8; i++)
#pragma unroll
            for (int j = 0; j < 4; j++) s[i][j] = 0.f;
#pragma unroll
        for (int kc = 0; kc < 4; kc++) {
            uint32_t af[4];
            ldsm4(af, qb + (uint32_t)(((warpQ + rA) * FP + kc * 16 + kA) * 2));
#pragma unroll
            for (int np = 0; np < 4; np++) {
                uint32_t treg[4];
                ldsm4(treg, kb + (uint32_t)(((np * 16 + rB) * FP + kc * 16 + kB) * 2));
                mma_f16(s[2 * np],     af[0], af[1], af[2], af[3], treg[0], treg[1]);
                mma_f16(s[2 * np + 1], af[0], af[1], af[2], af[3], treg[2], treg[3]);
            }
        }

        float corr[2];
#pragma unroll
        for (int rr = 0; rr < 2; rr++) {
            float tmax = -1e30f;
#pragma unroll
            for (int nt = 0; nt < 8; nt++)
                tmax = fmaxf(tmax, fmaxf(s[nt][rr * 2], s[nt][rr * 2 + 1]));
            tmax = fmaxf(tmax, __shfl_xor_sync(0xffffffffu, tmax, 1));
            tmax = fmaxf(tmax, __shfl_xor_sync(0xffffffffu, tmax, 2));
            float mn = fmaxf(m[rr], tmax);
            corr[rr] = __expf(m[rr] - mn);
            m[rr] = mn;
            float rs = 0.f;
#pragma unroll
            for (int nt = 0; nt < 8; nt++) {
                float p0 = __expf(s[nt][rr * 2] - mn);
                float p1 = __expf(s[nt][rr * 2 + 1] - mn);
                s[nt][rr * 2] = p0; s[nt][rr * 2 + 1] = p1;
                rs += p0 + p1;
            }
            rs += __shfl_xor_sync(0xffffffffu, rs, 1);
            rs += __shfl_xor_sync(0xffffffffu, rs, 2);
            l[rr] = l[rr] * corr[rr] + rs;
        }
#pragma unroll
        for (int nt = 0; nt < 8; nt++) {
            o[nt][0] *= corr[0]; o[nt][1] *= corr[0];
            o[nt][2] *= corr[1]; o[nt][3] *= corr[1];
        }

#pragma unroll
        for (int kc = 0; kc < 4; kc++) {
            __half2 h0 = __floats2half2_rn(s[2 * kc][0], s[2 * kc][1]);
            __half2 h1 = __floats2half2_rn(s[2 * kc][2], s[2 * kc][3]);
            __half2 h2 = __floats2half2_rn(s[2 * kc + 1][0], s[2 * kc + 1][1]);
            __half2 h3 = __floats2half2_rn(s[2 * kc + 1][2], s[2 * kc + 1][3]);
            uint32_t pa0 = *(uint32_t*)&h0, pa1 = *(uint32_t*)&h1;
            uint32_t pa2 = *(uint32_t*)&h2, pa3 = *(uint32_t*)&h3;
#pragma unroll
            for (int np = 0; np < 4; np++) {
                uint32_t treg[4];
                ldsm4t(treg, vb + (uint32_t)(((kc * 16 + vKey) * FP + np * 16 + vD) * 2));
                mma_f16(o[2 * np],     pa0, pa1, pa2, pa3, treg[0], treg[1]);
                mma_f16(o[2 * np + 1], pa0, pa1, pa2, pa3, treg[2], treg[3]);
            }
        }
    }

#pragma unroll
    for (int rr = 0; rr < 2; rr++) {
        float inv = 1.0f / l[rr];
        int t = b * Sd + q0 + warpQ + g + rr * 8;
        __half* dp = g_attno2 + (size_t)t * Dm + h * HDd;
#pragma unroll
        for (int nt = 0; nt < 8; nt++) {
            __half2 hv = __floats2half2_rn(o[nt][rr * 2] * inv, o[nt][rr * 2 + 1] * inv);
            *(__half2*)(dp + nt * 8 + t2) = hv;
        }
    }
}

// ---------------- fused dual LN ----------------
__global__ void ln_k(const float* __restrict__ x,
                     const float* __restrict__ ln1w, const float* __restrict__ ln1b,
                     const float* __restrict__ ln2w, const float* __restrict__ ln2b,
                     float* __restrict__ out) {
    int t = blockIdx.x, tid = threadIdx.x;
    __shared__ float r1[8], r2[8];
    __shared__ float mu_s, rs_s;
    size_t off = (size_t)t * Dm;
    float a0 = x[off + tid] + g_attnout[off + tid];
    float a1 = x[off + 256 + tid] + g_attnout[off + 256 + tid];
    float s = a0 + a1, ss = a0 * a0 + a1 * a1;
#pragma unroll
    for (int o = 16; o; o >>= 1) {
        s += __shfl_xor_sync(0xffffffffu, s, o);
        ss += __shfl_xor_sync(0xffffffffu, ss, o);
    }
    if ((tid & 31) == 0) { r1[tid >> 5] = s; r2[tid >> 5] = ss; }
    __syncthreads();
    if (tid == 0) {
        float S = 0.f, SS = 0.f;
#pragma unroll
        for (int i = 0; i < 8; i++) { S += r1[i]; SS += r2[i]; }
        float mu = S * (1.0f / 512.0f);
        mu_s = mu;
        rs_s = rsqrtf(SS * (1.0f / 512.0f) - mu * mu + 1e-5f);
    }
    __syncthreads();
    float mu = mu_s, rs = rs_s;
    float z0 = (a0 - mu) * rs * ln1w[tid] + ln1b[tid] + g_nout[off + tid];
    float z1 = (a1 - mu) * rs * ln1w[256 + tid] + ln1b[256 + tid] + g_nout[off + 256 + tid];
    s = z0 + z1; ss = z0 * z0 + z1 * z1;
#pragma unroll
    for (int o = 16; o; o >>= 1) {
        s += __shfl_xor_sync(0xffffffffu, s, o);
        ss += __shfl_xor_sync(0xffffffffu, ss, o);
    }
    __syncthreads();
    if ((tid & 31) == 0) { r1[tid >> 5] = s; r2[tid >> 5] = ss; }
    __syncthreads();
    if (tid == 0) {
        float S = 0.f, SS = 0.f;
#pragma unroll
        for (int i = 0; i < 8; i++) { S += r1[i]; SS += r2[i]; }
        float mu2 = S * (1.0f / 512.0f);
        mu_s = mu2;
        rs_s = rsqrtf(SS * (1.0f / 512.0f) - mu2 * mu2 + 1e-5f);
    }
    __syncthreads();
    mu = mu_s; rs = rs_s;
    out[off + tid] = (z0 - mu) * rs * ln2w[tid] + ln2b[tid];
    out[off + 256 + tid] = (z1 - mu) * rs * ln2w[256 + tid] + ln2b[256 + tid];
}

// ---------------- launcher ----------------
extern "C" void kernel_launch(void* const* d_in, const int* in_sizes, int n_in,
                              void* d_out, int out_size) {
    const float* x    = (const float*)d_in[0];
    const float* Wr   = (const float*)d_in[1];
    const float* br   = (const float*)d_in[2];
    const float* W1   = (const float*)d_in[3];
    const float* b1   = (const float*)d_in[4];
    const float* W2   = (const float*)d_in[5];
    const float* b2   = (const float*)d_in[6];
    const float* Wqkv = (const float*)d_in[7];
    const float* bqkv = (const float*)d_in[8];
    const float* Wo   = (const float*)d_in[9];
    const float* bo   = (const float*)d_in[10];
    const float* ln1w = (const float*)d_in[11];
    const float* ln1b = (const float*)d_in[12];
    const float* ln2w = (const float*)d_in[13];
    const float* ln2b = (const float*)d_in[14];
    float* out = (float*)d_out;

    float *p_attnout;
    __half *p_x2, *p_w12, *p_w22, *p_wqkv2, *p_wo2, *p_nout2, *p_attno2, *p_qkv2;
    cudaGetSymbolAddress((void**)&p_attnout, g_attnout);
    cudaGetSymbolAddress((void**)&p_x2, g_x2);
    cudaGetSymbolAddress((void**)&p_w12, g_W12);
    cudaGetSymbolAddress((void**)&p_w22, g_W22);
    cudaGetSymbolAddress((void**)&p_wqkv2, g_Wqkv2);
    cudaGetSymbolAddress((void**)&p_wo2, g_Wo2);
    cudaGetSymbolAddress((void**)&p_nout2, g_nout2);
    cudaGetSymbolAddress((void**)&p_attno2, g_attno2);
    cudaGetSymbolAddress((void**)&p_qkv2, g_qkv2);

    static int init_done = 0;
    static cudaStream_t sA, sB;
    static cudaEvent_t evRoot, evA, evB, evQ, evO, evZ;
    if (!init_done) {
        cudaFuncSetAttribute(ffn1_mma_k, cudaFuncAttributeMaxDynamicSharedMemorySize, SMEM_FFN);
        cudaFuncSetAttribute(ffn2_mma_k, cudaFuncAttributeMaxDynamicSharedMemorySize, SMEM_FFN);
        cudaFuncSetAttribute(gemm_mma_k, cudaFuncAttributeMaxDynamicSharedMemorySize, SMEM_GEMM);
        cudaStreamCreateWithFlags(&sA, cudaStreamNonBlocking);
        cudaStreamCreateWithFlags(&sB, cudaStreamNonBlocking);
        cudaEventCreateWithFlags(&evRoot, cudaEventDisableTiming);
        cudaEventCreateWithFlags(&evA, cudaEventDisableTiming);
        cudaEventCreateWithFlags(&evB, cudaEventDisableTiming);
        cudaEventCreateWithFlags(&evQ, cudaEventDisableTiming);
        cudaEventCreateWithFlags(&evO, cudaEventDisableTiming);
        cudaEventCreateWithFlags(&evZ, cudaEventDisableTiming);
        init_done = 1;
    }

    // fork point
    cudaEventRecord(evRoot, 0);
    cudaStreamWaitEvent(sA, evRoot, 0);
    cudaStreamWaitEvent(sB, evRoot, 0);

    // stream A: inputs needed by ffn1
    conv2_k<<<T * Dm / 256, 256, 0, sA>>>(x, p_x2, T * Dm);
    convw2_k<<<dim3(Hd / 32, Dm / 32, Np), dim3(32, 8), 0, sA>>>(W1, p_w12, Dm, Hd);
    cudaEventRecord(evA, sA);

    // stream B: zero counters first, then ffn2 / projection weights
    zero_k<<<1, 32, 0, sB>>>();
    cudaEventRecord(evZ, sB);
    convw2_k<<<dim3(Dm / 32, Hd / 32, Np), dim3(32, 8), 0, sB>>>(W2, p_w22, Hd, Dm);
    cudaEventRecord(evB, sB);
    conv2_k<<<D3 * Dm / 256, 256, 0, sB>>>(Wqkv, p_wqkv2, D3 * Dm);
    cudaEventRecord(evQ, sB);
    conv2_k<<<Dm * Dm / 256, 256, 0, sB>>>(Wo, p_wo2, Dm * Dm);
    cudaEventRecord(evO, sB);

    // main stream: router (top-4 + direct list build)
    cudaStreamWaitEvent(0, evZ, 0);
    router_k<<<T / 8, 256>>>(x, Wr, br);

    // sparse FFN on tensor cores (fp16 single-pass)
    cudaStreamWaitEvent(0, evA, 0);
    ffn1_mma_k<<<dim3(16, MAXTILES, 32), 256, SMEM_FFN>>>(b1);
    cudaStreamWaitEvent(0, evB, 0);
    ffn2_mma_k<<<dim3(4, MAXTILES, 32), 256, SMEM_FFN>>>(b2);
    reduce3_k<<<(T * Dm / 4 + 255) / 256, 256>>>();

    // attention: fp16 QKV projection + fp16 HMMA flash core
    cudaStreamWaitEvent(0, evQ, 0);
    gemm_mma_k<<<dim3(D3 / 128, T / 128), 256, SMEM_GEMM>>>(p_nout2, p_wqkv2, bqkv, 0, p_qkv2, D3, Dm);
    attn3_k<<<dim3(Sd / 64, NHd, Bd), 128>>>();
    cudaStreamWaitEvent(0, evO, 0);
    gemm_mma_k<<<dim3(Dm / 128, T / 128), 256, SMEM_GEMM>>>(p_attno2, p_wo2, bo, p_attnout, 0, Dm, Dm);

    // epilogue
    ln_k<<<T, 256>>>(x, ln1w, ln1b, ln2w, ln2b, out);
}

// round 15
// speedup vs baseline: 2.5897x; 1.0369x over previous
#include <cuda_runtime.h>
#include <cuda_fp16.h>
#include <math.h>
#include <stdint.h>

#define T   2048
#define Dm  512
#define Np  32
#define Hd  2048
#define Kk  4
#define NHd 8
#define HDd 64
#define Sd  1024
#define Bd  2
#define D3  1536

// HMMA tile constants
#define FP 72                             // A-tile pitch (fp16): 64 data rows x 72
#define BP 136                            // FFN B-tile pitch (fp16): [k][n] tiles, 128 data + 8 pad
#define FTILE (128 * FP)                  // dense gemm tile (both operands [rows][k])
#define SMEM_GEMM (4 * FTILE * 2)         // dense gemm: 2 bufs x (A128 + B128)
#define FSTAGE (64 * FP + 64 * BP)        // ffn stage: A(64xFP) + B(64xBP) fp16 units
#define SMEM_FFN (2 * FSTAGE * 2)         // 2 stages (53 KB)

#define MAXTILES 8                        // covers cnt <= 512 (~16 sigma)

__device__ int   g_cnt[Np];
__device__ int   g_list[Np * T];
__device__ float g_pairs[T * Kk * Dm];
__device__ float g_nout[T * Dm];
__device__ float g_attnout[T * Dm];
__device__ __half g_x2[T * Dm];
__device__ __half g_nout2[T * Dm];
__device__ __half g_attno2[T * Dm];
__device__ __half g_qkv2[(size_t)T * D3];
__device__ __half g_W12[(size_t)Np * Dm * Hd];   // original layout [n][k=512][h=2048]
__device__ __half g_W22[(size_t)Np * Hd * Dm];   // original layout [n][k=2048][d=512]
__device__ __half g_Wqkv2[(size_t)D3 * Dm];      // [N][K]
__device__ __half g_Wo2[(size_t)Dm * Dm];        // [N][K]
__device__ __half g_h2[(size_t)T * Kk * Hd];     // [pair][h]

__device__ __forceinline__ float gelu_f(float v) {
    float u = 0.7978845608028654f * (v + 0.044715f * v * v * v);
    return 0.5f * v * (1.0f + tanhf(u));
}

__device__ __forceinline__ uint32_t cvta_smem(const void* p) {
    uint32_t a;
    asm("{ .reg .u64 t; cvta.to.shared.u64 t, %1; cvt.u32.u64 %0, t; }" : "=r"(a) : "l"(p));
    return a;
}

__device__ __forceinline__ void mma_f16(float c[4], uint32_t a0, uint32_t a1,
                                        uint32_t a2, uint32_t a3,
                                        uint32_t b0, uint32_t b1) {
    asm volatile(
        "mma.sync.aligned.m16n8k16.row.col.f32.f16.f16.f32 "
        "{%0,%1,%2,%3}, {%4,%5,%6,%7}, {%8,%9}, {%0,%1,%2,%3};"
        : "+f"(c[0]), "+f"(c[1]), "+f"(c[2]), "+f"(c[3])
        : "r"(a0), "r"(a1), "r"(a2), "r"(a3), "r"(b0), "r"(b1));
}

__device__ __forceinline__ void ldsm4(uint32_t r[4], uint32_t a) {
    asm volatile("ldmatrix.sync.aligned.m8n8.x4.shared.b16 {%0,%1,%2,%3}, [%4];"
        : "=r"(r[0]), "=r"(r[1]), "=r"(r[2]), "=r"(r[3]) : "r"(a));
}
__device__ __forceinline__ void ldsm4t(uint32_t r[4], uint32_t a) {
    asm volatile("ldmatrix.sync.aligned.m8n8.x4.trans.shared.b16 {%0,%1,%2,%3}, [%4];"
        : "=r"(r[0]), "=r"(r[1]), "=r"(r[2]), "=r"(r[3]) : "r"(a));
}

// ---------------- zero counters ----------------
__global__ void zero_k() { if (threadIdx.x < Np) g_cnt[threadIdx.x] = 0; }

// ---------------- router: top-4 + direct atomic list build ----------------
__global__ void router_k(const float* __restrict__ x, const float* __restrict__ Wr,
                         const float* __restrict__ br) {
    int warp = threadIdx.x >> 5, lane = threadIdx.x & 31;
    int t = blockIdx.x * 8 + warp;
    const float* xp = x + (size_t)t * Dm + lane * 16;
    float4 xv[4];
#pragma unroll
    for (int i = 0; i < 4; i++) xv[i] = *(const float4*)(xp + i * 4);
    float lg[32];
#pragma unroll 1
    for (int n = 0; n < 32; n++) {
        const float* wp = Wr + n * Dm + lane * 16;
        float acc = 0.f;
#pragma unroll
        for (int i = 0; i < 4; i++) {
            float4 w = *(const float4*)(wp + i * 4);
            acc += xv[i].x * w.x + xv[i].y * w.y + xv[i].z * w.z + xv[i].w * w.w;
        }
#pragma unroll
        for (int o = 16; o; o >>= 1) acc += __shfl_xor_sync(0xffffffffu, acc, o);
        lg[n] = acc + br[n];
    }
    if (lane == 0) {
        unsigned used = 0;
        for (int k2 = 0; k2 < 4; k2++) {
            float best = -1e30f; int bi = 0;
            for (int n = 0; n < 32; n++)
                if (!((used >> n) & 1u) && lg[n] > best) { best = lg[n]; bi = n; }
            used |= 1u << bi;
            int pos = atomicAdd(&g_cnt[bi], 1);
            g_list[bi * T + pos] = t * 4 + k2;
        }
    }
}

// ---------------- vectorized fp32 -> fp16 (8 elems/thread) ----------------
__global__ void convv_k(const float4* __restrict__ src, uint4* __restrict__ dst, int total8) {
    int i = blockIdx.x * 256 + threadIdx.x;
    if (i >= total8) return;
    float4 a = src[2 * i], b = src[2 * i + 1];
    __half2 h[4];
    h[0] = __floats2half2_rn(a.x, a.y);
    h[1] = __floats2half2_rn(a.z, a.w);
    h[2] = __floats2half2_rn(b.x, b.y);
    h[3] = __floats2half2_rn(b.z, b.w);
    dst[i] = *(uint4*)h;
}

// ---------------- dense HMMA chunk (A,B both [rows][k], ldsm4) ----------------
__device__ __forceinline__ void hmma_chunk(uint32_t smb_A, uint32_t smb_B,
                                           int warpM, int warpN, int rA, int kA,
                                           int rB, int kB, float acc[4][4][4]) {
#pragma unroll
    for (int kk = 0; kk < 4; kk++) {
        uint32_t af[4][4], bf[4][2];
#pragma unroll
        for (int mt = 0; mt < 4; mt++)
            ldsm4(af[mt], smb_A + (uint32_t)(((warpM + mt * 16 + rA) * FP + kk * 16 + kA) * 2));
#pragma unroll
        for (int nt2 = 0; nt2 < 2; nt2++) {
            uint32_t treg[4];
            ldsm4(treg, smb_B + (uint32_t)(((warpN + nt2 * 16 + rB) * FP + kk * 16 + kB) * 2));
            bf[2 * nt2][0] = treg[0]; bf[2 * nt2][1] = treg[1];
            bf[2 * nt2 + 1][0] = treg[2]; bf[2 * nt2 + 1][1] = treg[3];
        }
#pragma unroll
        for (int mt = 0; mt < 4; mt++)
#pragma unroll
            for (int nt = 0; nt < 4; nt++)
                mma_f16(acc[mt][nt], af[mt][0], af[mt][1], af[mt][2], af[mt][3],
                        bf[nt][0], bf[nt][1]);
    }
}

// ---------------- FFN HMMA chunk: A [m][k] ldsm4, B [k][n] ldsm4t ----------------
__device__ __forceinline__ void hmma_chunk16t(uint32_t smb_A, uint32_t smb_B,
                                              int warpM, int warpN, int rA, int kA,
                                              int vKey, int vD, float acc[2][4][4]) {
#pragma unroll
    for (int kk = 0; kk < 4; kk++) {
        uint32_t af[2][4], bf[4][2];
#pragma unroll
        for (int mt = 0; mt < 2; mt++)
            ldsm4(af[mt], smb_A + (uint32_t)(((warpM + mt * 16 + rA) * FP + kk * 16 + kA) * 2));
#pragma unroll
        for (int nt2 = 0; nt2 < 2; nt2++) {
            uint32_t treg[4];
            ldsm4t(treg, smb_B + (uint32_t)(((kk * 16 + vKey) * BP + warpN + nt2 * 16 + vD) * 2));
            bf[2 * nt2][0] = treg[0]; bf[2 * nt2][1] = treg[1];
            bf[2 * nt2 + 1][0] = treg[2]; bf[2 * nt2 + 1][1] = treg[3];
        }
#pragma unroll
        for (int mt = 0; mt < 2; mt++)
#pragma unroll
            for (int nt = 0; nt < 4; nt++)
                mma_f16(acc[mt][nt], af[mt][0], af[mt][1], af[mt][2], af[mt][3],
                        bf[nt][0], bf[nt][1]);
    }
}

// ---------------- FFN pass 1: h = gelu(x @ W1 + b1), M=64 tiles, K=512 ----------------
__global__ __launch_bounds__(256, 2)
void ffn1_mma_k(const float* __restrict__ b1) {
    int n = blockIdx.z, mt0 = blockIdx.y, nb = blockIdx.x * 128;
    int cnt = g_cnt[n];
    int base = mt0 * 64;
    if (base >= cnt) return;

    extern __shared__ __align__(16) __half sm[];
    __shared__ int es[64];
    int tid = threadIdx.x, wid = tid >> 5, lane = tid & 31;
    if (tid < 64) es[tid] = (base + tid < cnt) ? g_list[n * T + base + tid] : -1;
    __syncthreads();

    int arw = tid >> 2, aq = (tid & 3) * 16;
    int e_row = es[arw];
    const __half* arow = (e_row >= 0) ? (g_x2 + (size_t)(e_row >> 2) * Dm) : 0;
    int stoA = arw * FP + aq;
    // B loader: [k=64][n=128] tiles from original W1 layout [n_neuron][k][h]
    int brw = tid >> 2, bh = (tid & 2) * 32 + (tid & 1) * 16;   // 4 threads/row: cols 0,16,64,80? -> use contiguous: (tid&3)*32
    brw = tid >> 2; bh = (tid & 3) * 32;
    const __half* brow = g_W12 + (size_t)n * Dm * Hd + (size_t)brw * Hd + nb + bh;
    int stoB = 64 * FP + brw * BP + bh;

    float acc[2][4][4];
#pragma unroll
    for (int i = 0; i < 2; i++)
#pragma unroll
        for (int j = 0; j < 4; j++)
#pragma unroll
            for (int k = 0; k < 4; k++) acc[i][j][k] = 0.f;

    int g = lane >> 2, t2 = (lane & 3) * 2;
    int warpM = (wid >> 2) * 32, warpN = (wid & 3) * 32;
    int rA = ((lane >> 3) & 1) * 8 + (lane & 7);
    int kA = (lane >> 4) * 8;
    int vKey = (lane & 7) + ((lane >> 3) & 1) * 8;
    int vD = (lane >> 4) * 8;
    uint32_t smb = cvta_smem(sm);

    const int NCH = 8;
    uint4 ra[2], rb[4];
    if (arow) {
        ra[0] = *(const uint4*)(arow + aq);
        ra[1] = *(const uint4*)(arow + aq + 8);
    } else { ra[0] = make_uint4(0, 0, 0, 0); ra[1] = make_uint4(0, 0, 0, 0); }
#pragma unroll
    for (int i = 0; i < 4; i++) rb[i] = *(const uint4*)(brow + i * 8);
    *(uint4*)(sm + stoA) = ra[0]; *(uint4*)(sm + stoA + 8) = ra[1];
#pragma unroll
    for (int i = 0; i < 4; i++) *(uint4*)(sm + stoB + i * 8) = rb[i];
    __syncthreads();

#pragma unroll 1
    for (int c = 0; c < NCH; c++) {
        int buf = c & 1;
        if (c + 1 < NCH) {
            int ko = (c + 1) * 64;
            if (arow) {
                const __half* ap = arow + ko + aq;
                ra[0] = *(const uint4*)(ap); ra[1] = *(const uint4*)(ap + 8);
            }
            const __half* bp = brow + (size_t)ko * Hd;
#pragma unroll
            for (int i = 0; i < 4; i++) rb[i] = *(const uint4*)(bp + i * 8);
        }
        uint32_t baseA = smb + (uint32_t)(buf * FSTAGE * 2);
        hmma_chunk16t(baseA, baseA + 64 * FP * 2, warpM, warpN, rA, kA, vKey, vD, acc);
        if (c + 1 < NCH) {
            __half* d = sm + ((c + 1) & 1) * FSTAGE;
            *(uint4*)(d + stoA) = ra[0]; *(uint4*)(d + stoA + 8) = ra[1];
#pragma unroll
            for (int i = 0; i < 4; i++) *(uint4*)(d + stoB + i * 8) = rb[i];
        }
        __syncthreads();
    }

#pragma unroll
    for (int mt = 0; mt < 2; mt++) {
#pragma unroll
        for (int rr = 0; rr < 2; rr++) {
            int row = warpM + mt * 16 + g + rr * 8;
            int er = es[row];
            if (er < 0) continue;
            __half* hp = g_h2 + (size_t)er * Hd;
#pragma unroll
            for (int nt = 0; nt < 4; nt++) {
                int col = nb + warpN + nt * 8 + t2;
                float v0 = gelu_f(acc[mt][nt][rr * 2 + 0] + b1[(size_t)n * Hd + col]);
                float v1 = gelu_f(acc[mt][nt][rr * 2 + 1] + b1[(size_t)n * Hd + col + 1]);
                __half2 hv = __floats2half2_rn(v0, v1);
                *(__half2*)(hp + col) = hv;
            }
        }
    }
}

// ---------------- FFN pass 2: out = h @ W2 + b2, M=64 tiles, K=2048 ----------------
__global__ __launch_bounds__(256, 2)
void ffn2_mma_k(const float* __restrict__ b2) {
    int n = blockIdx.z, mt0 = blockIdx.y, nb = blockIdx.x * 128;
    int cnt = g_cnt[n];
    int base = mt0 * 64;
    if (base >= cnt) return;

    extern __shared__ __align__(16) __half sm[];
    __shared__ int es[64];
    int tid = threadIdx.x, wid = tid >> 5, lane = tid & 31;
    if (tid < 64) es[tid] = (base + tid < cnt) ? g_list[n * T + base + tid] : -1;
    __syncthreads();

    int arw = tid >> 2, aq = (tid & 3) * 16;
    int e_row = es[arw];
    const __half* arow = (e_row >= 0) ? (g_h2 + (size_t)e_row * Hd) : 0;
    int stoA = arw * FP + aq;
    int brw = tid >> 2, bh = (tid & 3) * 32;
    const __half* brow = g_W22 + (size_t)n * Hd * Dm + (size_t)brw * Dm + nb + bh;
    int stoB = 64 * FP + brw * BP + bh;

    float acc[2][4][4];
#pragma unroll
    for (int i = 0; i < 2; i++)
#pragma unroll
        for (int j = 0; j < 4; j++)
#pragma unroll
            for (int k = 0; k < 4; k++) acc[i][j][k] = 0.f;

    int g = lane >> 2, t2 = (lane & 3) * 2;
    int warpM = (wid >> 2) * 32, warpN = (wid & 3) * 32;
    int rA = ((lane >> 3) & 1) * 8 + (lane & 7);
    int kA = (lane >> 4) * 8;
    int vKey = (lane & 7) + ((lane >> 3) & 1) * 8;
    int vD = (lane >> 4) * 8;
    uint32_t smb = cvta_smem(sm);

    const int NCH = 32;
    uint4 ra[2], rb[4];
    if (arow) {
        ra[0] = *(const uint4*)(arow + aq);
        ra[1] = *(const uint4*)(arow + aq + 8);
    } else { ra[0] = make_uint4(0, 0, 0, 0); ra[1] = make_uint4(0, 0, 0, 0); }
#pragma unroll
    for (int i = 0; i < 4; i++) rb[i] = *(const uint4*)(brow + i * 8);
    *(uint4*)(sm + stoA) = ra[0]; *(uint4*)(sm + stoA + 8) = ra[1];
#pragma unroll
    for (int i = 0; i < 4; i++) *(uint4*)(sm + stoB + i * 8) = rb[i];
    __syncthreads();

#pragma unroll 1
    for (int c = 0; c < NCH; c++) {
        int buf = c & 1;
        if (c + 1 < NCH) {
            int ko = (c + 1) * 64;
            if (arow) {
                const __half* ap = arow + ko + aq;
                ra[0] = *(const uint4*)(ap); ra[1] = *(const uint4*)(ap + 8);
            }
            const __half* bp = brow + (size_t)ko * Dm;
#pragma unroll
            for (int i = 0; i < 4; i++) rb[i] = *(const uint4*)(bp + i * 8);
        }
        uint32_t baseA = smb + (uint32_t)(buf * FSTAGE * 2);
        hmma_chunk16t(baseA, baseA + 64 * FP * 2, warpM, warpN, rA, kA, vKey, vD, acc);
        if (c + 1 < NCH) {
            __half* d = sm + ((c + 1) & 1) * FSTAGE;
            *(uint4*)(d + stoA) = ra[0]; *(uint4*)(d + stoA + 8) = ra[1];
#pragma unroll
            for (int i = 0; i < 4; i++) *(uint4*)(d + stoB + i * 8) = rb[i];
        }
        __syncthreads();
    }

#pragma unroll
    for (int mt = 0; mt < 2; mt++) {
#pragma unroll
        for (int rr = 0; rr < 2; rr++) {
            int row = warpM + mt * 16 + g + rr * 8;
            int er = es[row];
            if (er < 0) continue;
            float* op = g_pairs + (size_t)er * Dm;
#pragma unroll
            for (int nt = 0; nt < 4; nt++) {
                int col = nb + warpN + nt * 8 + t2;
                float2 o;
                o.x = acc[mt][nt][rr * 2 + 0] + b2[(size_t)n * Dm + col];
                o.y = acc[mt][nt][rr * 2 + 1] + b2[(size_t)n * Dm + col + 1];
                *(float2*)(op + col) = o;
            }
        }
    }
}

// ---------------- dense HMMA GEMM: C = A @ W^T + bias (fp32 or fp16 out) ----------------
__global__ __launch_bounds__(256)
void gemm_mma_k(const __half* __restrict__ A2, const __half* __restrict__ W2h,
                const float* __restrict__ bias, float* __restrict__ C,
                __half* __restrict__ Ch, int Nc, int Kd) {
    int nb = blockIdx.x * 128, mg = blockIdx.y * 128;
    extern __shared__ __align__(16) __half sm[];
    int tid = threadIdx.x, wid = tid >> 5, lane = tid & 31;

    int hr = tid >> 1, half = tid & 1;
    const __half* arow = A2 + (size_t)(mg + hr) * Kd;
    const __half* brow = W2h + (size_t)(nb + hr) * Kd;
    int sto = hr * FP + half * 32;

    float acc[4][4][4];
#pragma unroll
    for (int i = 0; i < 4; i++)
#pragma unroll
        for (int j = 0; j < 4; j++)
#pragma unroll
            for (int k = 0; k < 4; k++) acc[i][j][k] = 0.f;

    int g = lane >> 2, t2 = (lane & 3) * 2;
    int warpM = (wid >> 2) * 64, warpN = (wid & 3) * 32;
    int rA = ((lane >> 3) & 1) * 8 + (lane & 7);
    int kA = (lane >> 4) * 8;
    int rB = (lane & 7) + (lane >> 4) * 8;
    int kB = ((lane >> 3) & 1) * 8;
    uint32_t smb = cvta_smem(sm);

    int NCH = Kd >> 6;
    uint4 ra[4], rb[4];
#pragma unroll
    for (int i = 0; i < 4; i++) {
        ra[i] = *(const uint4*)(arow + half * 32 + i * 8);
        rb[i] = *(const uint4*)(brow + half * 32 + i * 8);
    }
#pragma unroll
    for (int i = 0; i < 4; i++) {
        *(uint4*)(sm + sto + i * 8) = ra[i];
        *(uint4*)(sm + FTILE + sto + i * 8) = rb[i];
    }
    __syncthreads();

#pragma unroll 1
    for (int c = 0; c < NCH; c++) {
        int buf = c & 1;
        if (c + 1 < NCH) {
            int ko = (c + 1) * 64;
            const __half* ap = arow + ko + half * 32;
            const __half* bp = brow + ko + half * 32;
#pragma unroll
            for (int i = 0; i < 4; i++) {
                ra[i] = *(const uint4*)(ap + i * 8);
                rb[i] = *(const uint4*)(bp + i * 8);
            }
        }
        uint32_t baseA = smb + (uint32_t)(buf * 2 * FTILE * 2);
        hmma_chunk(baseA, baseA + FTILE * 2, warpM, warpN, rA, kA, rB, kB, acc);
        if (c + 1 < NCH) {
            __half* d = sm + ((c + 1) & 1) * 2 * FTILE;
#pragma unroll
            for (int i = 0; i < 4; i++) {
                *(uint4*)(d + sto + i * 8) = ra[i];
                *(uint4*)(d + FTILE + sto + i * 8) = rb[i];
            }
        }
        __syncthreads();
    }

#pragma unroll
    for (int mt = 0; mt < 4; mt++) {
#pragma unroll
        for (int rr = 0; rr < 2; rr++) {
            int row = mg + warpM + mt * 16 + g + rr * 8;
#pragma unroll
            for (int nt = 0; nt < 4; nt++) {
                int col = nb + warpN + nt * 8 + t2;
                float ox = acc[mt][nt][rr * 2 + 0] + bias[col];
                float oy = acc[mt][nt][rr * 2 + 1] + bias[col + 1];
                if (Ch) {
                    *(__half2*)(Ch + (size_t)row * Nc + col) = __floats2half2_rn(ox, oy);
                } else {
                    *(float2*)(C + (size_t)row * Nc + col) = make_float2(ox, oy);
                }
            }
        }
    }
}

// ---------------- mean over k, fused fp16 cast ----------------
__global__ void reduce3_k() {
    int id = blockIdx.x * 256 + threadIdx.x;
    if (id >= T * Dm / 4) return;
    int t = id >> 7, c4 = (id & 127) << 2;
    float4 s = make_float4(0.f, 0.f, 0.f, 0.f);
#pragma unroll
    for (int k2 = 0; k2 < 4; k2++) {
        float4 v = *(const float4*)&g_pairs[(size_t)(t * 4 + k2) * Dm + c4];
        s.x += v.x; s.y += v.y; s.z += v.z; s.w += v.w;
    }
    s.x *= 0.25f; s.y *= 0.25f; s.z *= 0.25f; s.w *= 0.25f;
    *(float4*)&g_nout[(size_t)t * Dm + c4] = s;
    __half2 h0 = __floats2half2_rn(s.x, s.y);
    __half2 h1 = __floats2half2_rn(s.z, s.w);
    *(__half2*)&g_nout2[(size_t)t * Dm + c4] = h0;
    *(__half2*)&g_nout2[(size_t)t * Dm + c4 + 2] = h1;
}

// ---------------- attention: fp16 HMMA flash, q-tile 64, 4 warps ----------------
__global__ __launch_bounds__(128)
void attn3_k() {
    __shared__ __align__(16) __half Qs[64 * FP];
    __shared__ __align__(16) __half Ks[64 * FP];
    __shared__ __align__(16) __half Vs[64 * FP];
    int q0 = blockIdx.x * 64, h = blockIdx.y, b = blockIdx.z;
    int tid = threadIdx.x, lane = tid & 31, w = tid >> 5;
    int warpQ = w * 16;
    int g = lane >> 2, t2 = (lane & 3) * 2;

    {
        int r = tid >> 1, c = (tid & 1) * 32;
        const __half* qp = g_qkv2 + (size_t)(b * Sd + q0 + r) * D3 + h * HDd + c;
        __half2 sc = __half2half2(__float2half(0.125f));
#pragma unroll
        for (int i = 0; i < 4; i++) {
            uint4 v = *(const uint4*)(qp + i * 8);
            __half2* hv = (__half2*)&v;
#pragma unroll
            for (int j = 0; j < 4; j++) hv[j] = __hmul2(hv[j], sc);
            *(uint4*)(Qs + r * FP + c + i * 8) = v;
        }
    }

    float m[2] = {-1e30f, -1e30f}, l[2] = {0.f, 0.f};
    float o[8][4];
#pragma unroll
    for (int i = 0; i < 8; i++)
#pragma unroll
        for (int j = 0; j < 4; j++) o[i][j] = 0.f;

    int rA = ((lane >> 3) & 1) * 8 + (lane & 7);
    int kA = (lane >> 4) * 8;
    int rB = (lane & 7) + (lane >> 4) * 8;
    int kB = ((lane >> 3) & 1) * 8;
    int vKey = (lane & 7) + ((lane >> 3) & 1) * 8;
    int vD = (lane >> 4) * 8;
    uint32_t qb = cvta_smem(Qs), kb = cvta_smem(Ks), vb = cvta_smem(Vs);

#pragma unroll 1
    for (int j0 = 0; j0 < Sd; j0 += 64) {
        __syncthreads();
        {
            int r = tid >> 1, c = (tid & 1) * 32;
            const __half* kp = g_qkv2 + (size_t)(b * Sd + j0 + r) * D3 + Dm + h * HDd + c;
            const __half* vp = kp + Dm;
#pragma unroll
            for (int i = 0; i < 4; i++) {
                *(uint4*)(Ks + r * FP + c + i * 8) = *(const uint4*)(kp + i * 8);
                *(uint4*)(Vs + r * FP + c + i * 8) = *(const uint4*)(vp + i * 8);
            }
        }
        __syncthreads();

        float s[8][4];
#pragma unroll
        for (int i = 0; i < 8; i++)
#pragma unroll
            for (int j = 0; j < 4; j++) s[i][j] = 0.f;
#pragma unroll
        for (int kc = 0; kc < 4; kc++) {
            uint32_t af[4];
            ldsm4(af, qb + (uint32_t)(((warpQ + rA) * FP + kc * 16 + kA) * 2));
#pragma unroll
            for (int np = 0; np < 4; np++) {
                uint32_t treg[4];
                ldsm4(treg, kb + (uint32_t)(((np * 16 + rB) * FP + kc * 16 + kB) * 2));
                mma_f16(s[2 * np],     af[0], af[1], af[2], af[3], treg[0], treg[1]);
                mma_f16(s[2 * np + 1], af[0], af[1], af[2], af[3], treg[2], treg[3]);
            }
        }

        float corr[2];
#pragma unroll
        for (int rr = 0; rr < 2; rr++) {
            float tmax = -1e30f;
#pragma unroll
            for (int nt = 0; nt < 8; nt++)
                tmax = fmaxf(tmax, fmaxf(s[nt][rr * 2], s[nt][rr * 2 + 1]));
            tmax = fmaxf(tmax, __shfl_xor_sync(0xffffffffu, tmax, 1));
            tmax = fmaxf(tmax, __shfl_xor_sync(0xffffffffu, tmax, 2));
            float mn = fmaxf(m[rr], tmax);
            corr[rr] = __expf(m[rr] - mn);
            m[rr] = mn;
            float rs = 0.f;
#pragma unroll
            for (int nt = 0; nt < 8; nt++) {
                float p0 = __expf(s[nt][rr * 2] - mn);
                float p1 = __expf(s[nt][rr * 2 + 1] - mn);
                s[nt][rr * 2] = p0; s[nt][rr * 2 + 1] = p1;
                rs += p0 + p1;
            }
            rs += __shfl_xor_sync(0xffffffffu, rs, 1);
            rs += __shfl_xor_sync(0xffffffffu, rs, 2);
            l[rr] = l[rr] * corr[rr] + rs;
        }
#pragma unroll
        for (int nt = 0; nt < 8; nt++) {
            o[nt][0] *= corr[0]; o[nt][1] *= corr[0];
            o[nt][2] *= corr[1]; o[nt][3] *= corr[1];
        }

#pragma unroll
        for (int kc = 0; kc < 4; kc++) {
            __half2 h0 = __floats2half2_rn(s[2 * kc][0], s[2 * kc][1]);
            __half2 h1 = __floats2half2_rn(s[2 * kc][2], s[2 * kc][3]);
            __half2 h2 = __floats2half2_rn(s[2 * kc + 1][0], s[2 * kc + 1][1]);
            __half2 h3 = __floats2half2_rn(s[2 * kc + 1][2], s[2 * kc + 1][3]);
            uint32_t pa0 = *(uint32_t*)&h0, pa1 = *(uint32_t*)&h1;
            uint32_t pa2 = *(uint32_t*)&h2, pa3 = *(uint32_t*)&h3;
#pragma unroll
            for (int np = 0; np < 4; np++) {
                uint32_t treg[4];
                ldsm4t(treg, vb + (uint32_t)(((kc * 16 + vKey) * FP + np * 16 + vD) * 2));
                mma_f16(o[2 * np],     pa0, pa1, pa2, pa3, treg[0], treg[1]);
                mma_f16(o[2 * np + 1], pa0, pa1, pa2, pa3, treg[2], treg[3]);
            }
        }
    }

#pragma unroll
    for (int rr = 0; rr < 2; rr++) {
        float inv = 1.0f / l[rr];
        int t = b * Sd + q0 + warpQ + g + rr * 8;
        __half* dp = g_attno2 + (size_t)t * Dm + h * HDd;
#pragma unroll
        for (int nt = 0; nt < 8; nt++) {
            __half2 hv = __floats2half2_rn(o[nt][rr * 2] * inv, o[nt][rr * 2 + 1] * inv);
            *(__half2*)(dp + nt * 8 + t2) = hv;
        }
    }
}

// ---------------- fused dual LN ----------------
__global__ void ln_k(const float* __restrict__ x,
                     const float* __restrict__ ln1w, const float* __restrict__ ln1b,
                     const float* __restrict__ ln2w, const float* __restrict__ ln2b,
                     float* __restrict__ out) {
    int t = blockIdx.x, tid = threadIdx.x;
    __shared__ float r1[8], r2[8];
    __shared__ float mu_s, rs_s;
    size_t off = (size_t)t * Dm;
    float a0 = x[off + tid] + g_attnout[off + tid];
    float a1 = x[off + 256 + tid] + g_attnout[off + 256 + tid];
    float s = a0 + a1, ss = a0 * a0 + a1 * a1;
#pragma unroll
    for (int o = 16; o; o >>= 1) {
        s += __shfl_xor_sync(0xffffffffu, s, o);
        ss += __shfl_xor_sync(0xffffffffu, ss, o);
    }
    if ((tid & 31) == 0) { r1[tid >> 5] = s; r2[tid >> 5] = ss; }
    __syncthreads();
    if (tid == 0) {
        float S = 0.f, SS = 0.f;
#pragma unroll
        for (int i = 0; i < 8; i++) { S += r1[i]; SS += r2[i]; }
        float mu = S * (1.0f / 512.0f);
        mu_s = mu;
        rs_s = rsqrtf(SS * (1.0f / 512.0f) - mu * mu + 1e-5f);
    }
    __syncthreads();
    float mu = mu_s, rs = rs_s;
    float z0 = (a0 - mu) * rs * ln1w[tid] + ln1b[tid] + g_nout[off + tid];
    float z1 = (a1 - mu) * rs * ln1w[256 + tid] + ln1b[256 + tid] + g_nout[off + 256 + tid];
    s = z0 + z1; ss = z0 * z0 + z1 * z1;
#pragma unroll
    for (int o = 16; o; o >>= 1) {
        s += __shfl_xor_sync(0xffffffffu, s, o);
        ss += __shfl_xor_sync(0xffffffffu, ss, o);
    }
    __syncthreads();
    if ((tid & 31) == 0) { r1[tid >> 5] = s; r2[tid >> 5] = ss; }
    __syncthreads();
    if (tid == 0) {
        float S = 0.f, SS = 0.f;
#pragma unroll
        for (int i = 0; i < 8; i++) { S += r1[i]; SS += r2[i]; }
        float mu2 = S * (1.0f / 512.0f);
        mu_s = mu2;
        rs_s = rsqrtf(SS * (1.0f / 512.0f) - mu2 * mu2 + 1e-5f);
    }
    __syncthreads();
    mu = mu_s; rs = rs_s;
    out[off + tid] = (z0 - mu) * rs * ln2w[tid] + ln2b[tid];
    out[off + 256 + tid] = (z1 - mu) * rs * ln2w[256 + tid] + ln2b[256 + tid];
}

// ---------------- launcher ----------------
extern "C" void kernel_launch(void* const* d_in, const int* in_sizes, int n_in,
                              void* d_out, int out_size) {
    const float* x    = (const float*)d_in[0];
    const float* Wr   = (const float*)d_in[1];
    const float* br   = (const float*)d_in[2];
    const float* W1   = (const float*)d_in[3];
    const float* b1   = (const float*)d_in[4];
    const float* W2   = (const float*)d_in[5];
    const float* b2   = (const float*)d_in[6];
    const float* Wqkv = (const float*)d_in[7];
    const float* bqkv = (const float*)d_in[8];
    const float* Wo   = (const float*)d_in[9];
    const float* bo   = (const float*)d_in[10];
    const float* ln1w = (const float*)d_in[11];
    const float* ln1b = (const float*)d_in[12];
    const float* ln2w = (const float*)d_in[13];
    const float* ln2b = (const float*)d_in[14];
    float* out = (float*)d_out;

    float *p_attnout;
    __half *p_x2, *p_w12, *p_w22, *p_wqkv2, *p_wo2, *p_nout2, *p_attno2, *p_qkv2;
    cudaGetSymbolAddress((void**)&p_attnout, g_attnout);
    cudaGetSymbolAddress((void**)&p_x2, g_x2);
    cudaGetSymbolAddress((void**)&p_w12, g_W12);
    cudaGetSymbolAddress((void**)&p_w22, g_W22);
    cudaGetSymbolAddress((void**)&p_wqkv2, g_Wqkv2);
    cudaGetSymbolAddress((void**)&p_wo2, g_Wo2);
    cudaGetSymbolAddress((void**)&p_nout2, g_nout2);
    cudaGetSymbolAddress((void**)&p_attno2, g_attno2);
    cudaGetSymbolAddress((void**)&p_qkv2, g_qkv2);

    static int init_done = 0;
    static cudaStream_t sA, sB;
    static cudaEvent_t evRoot, evA, evB, evQ, evO, evZ;
    if (!init_done) {
        cudaFuncSetAttribute(ffn1_mma_k, cudaFuncAttributeMaxDynamicSharedMemorySize, SMEM_FFN);
        cudaFuncSetAttribute(ffn2_mma_k, cudaFuncAttributeMaxDynamicSharedMemorySize, SMEM_FFN);
        cudaFuncSetAttribute(gemm_mma_k, cudaFuncAttributeMaxDynamicSharedMemorySize, SMEM_GEMM);
        cudaStreamCreateWithFlags(&sA, cudaStreamNonBlocking);
        cudaStreamCreateWithFlags(&sB, cudaStreamNonBlocking);
        cudaEventCreateWithFlags(&evRoot, cudaEventDisableTiming);
        cudaEventCreateWithFlags(&evA, cudaEventDisableTiming);
        cudaEventCreateWithFlags(&evB, cudaEventDisableTiming);
        cudaEventCreateWithFlags(&evQ, cudaEventDisableTiming);
        cudaEventCreateWithFlags(&evO, cudaEventDisableTiming);
        cudaEventCreateWithFlags(&evZ, cudaEventDisableTiming);
        init_done = 1;
    }

    // fork point
    cudaEventRecord(evRoot, 0);
    cudaStreamWaitEvent(sA, evRoot, 0);
    cudaStreamWaitEvent(sB, evRoot, 0);

    // stream A: inputs needed by ffn1 (pure streaming converts, no transpose)
    convv_k<<<T * Dm / 8 / 256, 256, 0, sA>>>((const float4*)x, (uint4*)p_x2, T * Dm / 8);
    convv_k<<<(int)((size_t)Np * Dm * Hd / 8 / 256), 256, 0, sA>>>((const float4*)W1, (uint4*)p_w12, (int)((size_t)Np * Dm * Hd / 8));
    cudaEventRecord(evA, sA);

    // stream B: zero counters first, then ffn2 / projection weights
    zero_k<<<1, 32, 0, sB>>>();
    cudaEventRecord(evZ, sB);
    convv_k<<<(int)((size_t)Np * Hd * Dm / 8 / 256), 256, 0, sB>>>((const float4*)W2, (uint4*)p_w22, (int)((size_t)Np * Hd * Dm / 8));
    cudaEventRecord(evB, sB);
    convv_k<<<D3 * Dm / 8 / 256, 256, 0, sB>>>((const float4*)Wqkv, (uint4*)p_wqkv2, D3 * Dm / 8);
    cudaEventRecord(evQ, sB);
    convv_k<<<Dm * Dm / 8 / 256, 256, 0, sB>>>((const float4*)Wo, (uint4*)p_wo2, Dm * Dm / 8);
    cudaEventRecord(evO, sB);

    // main stream: router (top-4 + direct list build)
    cudaStreamWaitEvent(0, evZ, 0);
    router_k<<<T / 8, 256>>>(x, Wr, br);

    // sparse FFN on tensor cores (fp16 single-pass, no-transpose B)
    cudaStreamWaitEvent(0, evA, 0);
    ffn1_mma_k<<<dim3(16, MAXTILES, 32), 256, SMEM_FFN>>>(b1);
    cudaStreamWaitEvent(0, evB, 0);
    ffn2_mma_k<<<dim3(4, MAXTILES, 32), 256, SMEM_FFN>>>(b2);
    reduce3_k<<<(T * Dm / 4 + 255) / 256, 256>>>();

    // attention: fp16 QKV projection + fp16 HMMA flash core
    cudaStreamWaitEvent(0, evQ, 0);
    gemm_mma_k<<<dim3(D3 / 128, T / 128), 256, SMEM_GEMM>>>(p_nout2, p_wqkv2, bqkv, 0, p_qkv2, D3, Dm);
    attn3_k<<<dim3(Sd / 64, NHd, Bd), 128>>>();
    cudaStreamWaitEvent(0, evO, 0);
    gemm_mma_k<<<dim3(Dm / 128, T / 128), 256, SMEM_GEMM>>>(p_attno2, p_wo2, bo, p_attnout, 0, Dm, Dm);

    // epilogue
    ln_k<<<T, 256>>>(x, ln1w, ln1b, ln2w, ln2b, out);
}